// round 4
// baseline (speedup 1.0000x reference)
#include <cuda_runtime.h>

// Problem constants: B=8, N=2048, D=256, HEAD=8, ATT=32
#define NROWS 16384   // B*N
#define DMODEL 256

// Scratch (allocation-free rule: device globals)
__device__ __align__(16) float g_Q[NROWS * DMODEL];
__device__ __align__(16) float g_K[NROWS * DMODEL];
__device__ __align__(16) float g_V[NROWS * DMODEL];
__device__ __align__(16) float g_AO[NROWS * DMODEL];

// ---------------------------------------------------------------------------
// C[M,256] = A[M,256] @ W[256,256]^T + bias
// 128x128 tile, K-step 16, 256 threads, 8x8 micro-tile (2x2 blocks of 4x4).
// Smem k-major; global loads register-double-buffered across K steps.
// ---------------------------------------------------------------------------
__global__ __launch_bounds__(256)
void gemm_bias_kernel(const float* __restrict__ A,
                      const float* __restrict__ W,
                      const float* __restrict__ bias,
                      float* __restrict__ C)
{
    __shared__ __align__(16) float As[16][128];
    __shared__ __align__(16) float Ws[16][128];

    const int tx = threadIdx.x, ty = threadIdx.y;
    const int tid = ty * 16 + tx;
    const int m0 = blockIdx.y * 128;
    const int n0 = blockIdx.x * 128;

    float acc[8][8] = {};

    // prefetch first K-slab (kk = 0)
    float4 pa[2], pw[2];
    #pragma unroll
    for (int it = 0; it < 2; it++) {
        int idx = tid * 2 + it;          // 0..511
        int r   = idx >> 2;              // 0..127
        int c4  = (idx & 3) * 4;         // 0,4,8,12
        pa[it] = *(const float4*)(A + (size_t)(m0 + r) * 256 + c4);
        pw[it] = *(const float4*)(W + (size_t)(n0 + r) * 256 + c4);
    }

    for (int kk = 0; kk < 256; kk += 16) {
        // stage current slab (transposed to k-major)
        #pragma unroll
        for (int it = 0; it < 2; it++) {
            int idx = tid * 2 + it;
            int r   = idx >> 2;
            int c4  = (idx & 3) * 4;
            As[c4 + 0][r] = pa[it].x; As[c4 + 1][r] = pa[it].y;
            As[c4 + 2][r] = pa[it].z; As[c4 + 3][r] = pa[it].w;
            Ws[c4 + 0][r] = pw[it].x; Ws[c4 + 1][r] = pw[it].y;
            Ws[c4 + 2][r] = pw[it].z; Ws[c4 + 3][r] = pw[it].w;
        }
        __syncthreads();

        // prefetch next slab (overlaps with FMA below)
        if (kk < 240) {
            #pragma unroll
            for (int it = 0; it < 2; it++) {
                int idx = tid * 2 + it;
                int r   = idx >> 2;
                int c4  = (idx & 3) * 4;
                pa[it] = *(const float4*)(A + (size_t)(m0 + r) * 256 + kk + 16 + c4);
                pw[it] = *(const float4*)(W + (size_t)(n0 + r) * 256 + kk + 16 + c4);
            }
        }

        #pragma unroll
        for (int k = 0; k < 16; k++) {
            float4 a0 = *(const float4*)&As[k][ty * 4];
            float4 a1 = *(const float4*)&As[k][64 + ty * 4];
            float4 b0 = *(const float4*)&Ws[k][tx * 4];
            float4 b1 = *(const float4*)&Ws[k][64 + tx * 4];
            float ar[8] = {a0.x, a0.y, a0.z, a0.w, a1.x, a1.y, a1.z, a1.w};
            float br[8] = {b0.x, b0.y, b0.z, b0.w, b1.x, b1.y, b1.z, b1.w};
            #pragma unroll
            for (int i = 0; i < 8; i++)
                #pragma unroll
                for (int j = 0; j < 8; j++)
                    acc[i][j] += ar[i] * br[j];
        }
        __syncthreads();
    }

    float4 bv0 = *(const float4*)(bias + n0 + tx * 4);
    float4 bv1 = *(const float4*)(bias + n0 + 64 + tx * 4);
    float bb[8] = {bv0.x, bv0.y, bv0.z, bv0.w, bv1.x, bv1.y, bv1.z, bv1.w};

    #pragma unroll
    for (int rh = 0; rh < 2; rh++)
        #pragma unroll
        for (int i = 0; i < 4; i++) {
            int row = m0 + rh * 64 + ty * 4 + i;
            int ai = rh * 4 + i;
            float4 r4;
            r4.x = acc[ai][0] + bb[0]; r4.y = acc[ai][1] + bb[1];
            r4.z = acc[ai][2] + bb[2]; r4.w = acc[ai][3] + bb[3];
            *(float4*)(C + (size_t)row * 256 + n0 + tx * 4) = r4;
            r4.x = acc[ai][4] + bb[4]; r4.y = acc[ai][5] + bb[5];
            r4.z = acc[ai][6] + bb[6]; r4.w = acc[ai][7] + bb[7];
            *(float4*)(C + (size_t)row * 256 + n0 + 64 + tx * 4) = r4;
        }
}

// ---------------------------------------------------------------------------
// Causal flash attention, fp32. 128 threads (16x8). Q tile 64, KV tile 64.
// S phase: 8 rows x 4 cols per thread (rows {ty*4+i, 32+ty*4+i}).
// PV phase: remapped 4 rows x 4 d-cols per thread (rg = tid&15, dg = tid>>4).
// Softmax stats (m,l) live in registers of the owning 16-lane groups;
// alpha/l communicated through tiny smem arrays.
// K/V global loads prefetched one KV tile ahead in registers.
// ---------------------------------------------------------------------------
__global__ __launch_bounds__(128)
void attn_kernel(const float* __restrict__ Qg, const float* __restrict__ Kg,
                 const float* __restrict__ Vg, float* __restrict__ Og)
{
    __shared__ __align__(16) float Qs[32][64];   // [k][row]
    __shared__ __align__(16) float Ks[32][64];   // [k][col]
    __shared__ __align__(16) float Vs[64][32];   // [n][d]
    __shared__ __align__(16) float Ps[64][68];   // [row][n], padded vs 16-way conflicts
    __shared__ float alpha_s[64];
    __shared__ float l_s[64];

    const int tx = threadIdx.x, ty = threadIdx.y;
    const int tid = ty * 16 + tx;
    const int tq = (int)gridDim.x - 1 - (int)blockIdx.x;  // long blocks first
    const int hb = blockIdx.y;
    const int h  = hb & 7;
    const int bb = hb >> 3;
    const size_t base = (size_t)bb * 2048 * 256 + (size_t)h * 32;
    const float* Qb = Qg + base;
    const float* Kb = Kg + base;
    const float* Vb = Vg + base;
    float*       Ob = Og + base;

    const float scale = 0.17677669529663687f;   // 1/sqrt(32), folded into Q

    // stage Q (scaled) into k-major smem
    #pragma unroll
    for (int it = 0; it < 4; it++) {
        int idx = tid * 4 + it;          // 0..511
        int r   = idx >> 3;              // 0..63
        int c4  = (idx & 7) * 4;         // 0..28
        float4 v = *(const float4*)(Qb + (size_t)(tq * 64 + r) * 256 + c4);
        Qs[c4 + 0][r] = v.x * scale; Qs[c4 + 1][r] = v.y * scale;
        Qs[c4 + 2][r] = v.z * scale; Qs[c4 + 3][r] = v.w * scale;
    }

    const int r0 = ty * 4;           // S rows: {r0+i, 32+r0+i}
    const int c0 = tx * 4;           // S cols
    const int rg = (tid & 15) * 4;   // PV rows
    const int dg = (tid >> 4) * 4;   // PV d-cols

    float m[2][4], l[2][4], o[4][4];
    #pragma unroll
    for (int hh = 0; hh < 2; hh++)
        #pragma unroll
        for (int i = 0; i < 4; i++) { m[hh][i] = -1e30f; l[hh][i] = 0.0f; }
    #pragma unroll
    for (int i = 0; i < 4; i++)
        #pragma unroll
        for (int d = 0; d < 4; d++) o[i][d] = 0.0f;

    // prefetch KV tile j=0 into registers
    float4 kreg[4], vreg[4];
    #pragma unroll
    for (int it = 0; it < 4; it++) {
        int idx = tid * 4 + it;
        int r   = idx >> 3;
        int c4  = (idx & 7) * 4;
        kreg[it] = *(const float4*)(Kb + (size_t)r * 256 + c4);
        vreg[it] = *(const float4*)(Vb + (size_t)r * 256 + c4);
    }

    for (int j = 0; j <= tq; j++) {
        // stage current KV tile (K transposed to k-major)
        #pragma unroll
        for (int it = 0; it < 4; it++) {
            int idx = tid * 4 + it;
            int r   = idx >> 3;
            int c4  = (idx & 7) * 4;
            Ks[c4 + 0][r] = kreg[it].x; Ks[c4 + 1][r] = kreg[it].y;
            Ks[c4 + 2][r] = kreg[it].z; Ks[c4 + 3][r] = kreg[it].w;
            *(float4*)&Vs[r][c4] = vreg[it];
        }
        __syncthreads();   // tiles (and Qs on first iter) visible

        // prefetch next KV tile — overlaps all compute below
        if (j < tq) {
            #pragma unroll
            for (int it = 0; it < 4; it++) {
                int idx = tid * 4 + it;
                int r   = idx >> 3;
                int c4  = (idx & 7) * 4;
                kreg[it] = *(const float4*)(Kb + (size_t)((j + 1) * 64 + r) * 256 + c4);
                vreg[it] = *(const float4*)(Vb + (size_t)((j + 1) * 64 + r) * 256 + c4);
            }
        }

        // S = Q @ K^T  (8 rows x 4 cols per thread)
        float s[2][4][4] = {};
        #pragma unroll
        for (int k = 0; k < 32; k++) {
            float4 a0 = *(const float4*)&Qs[k][r0];
            float4 a1 = *(const float4*)&Qs[k][32 + r0];
            float4 b  = *(const float4*)&Ks[k][c0];
            float ar[2][4] = {{a0.x, a0.y, a0.z, a0.w}, {a1.x, a1.y, a1.z, a1.w}};
            float br[4] = {b.x, b.y, b.z, b.w};
            #pragma unroll
            for (int hh = 0; hh < 2; hh++)
                #pragma unroll
                for (int i = 0; i < 4; i++)
                    #pragma unroll
                    for (int jj = 0; jj < 4; jj++)
                        s[hh][i][jj] += ar[hh][i] * br[jj];
        }

        if (j == tq) {   // causal mask, diagonal tile only
            #pragma unroll
            for (int hh = 0; hh < 2; hh++)
                #pragma unroll
                for (int i = 0; i < 4; i++)
                    #pragma unroll
                    for (int jj = 0; jj < 4; jj++)
                        if (c0 + jj > hh * 32 + r0 + i) s[hh][i][jj] = -1e30f;
        }

        // online softmax; m,l register-resident (identical across 16 owner lanes)
        #pragma unroll
        for (int hh = 0; hh < 2; hh++)
            #pragma unroll
            for (int i = 0; i < 4; i++) {
                int row = hh * 32 + r0 + i;
                float mt = fmaxf(fmaxf(s[hh][i][0], s[hh][i][1]),
                                 fmaxf(s[hh][i][2], s[hh][i][3]));
                mt = fmaxf(mt, __shfl_xor_sync(0xffffffffu, mt, 1));
                mt = fmaxf(mt, __shfl_xor_sync(0xffffffffu, mt, 2));
                mt = fmaxf(mt, __shfl_xor_sync(0xffffffffu, mt, 4));
                mt = fmaxf(mt, __shfl_xor_sync(0xffffffffu, mt, 8));
                float mnew  = fmaxf(m[hh][i], mt);
                float alpha = __expf(m[hh][i] - mnew);
                float e0 = __expf(s[hh][i][0] - mnew);
                float e1 = __expf(s[hh][i][1] - mnew);
                float e2 = __expf(s[hh][i][2] - mnew);
                float e3 = __expf(s[hh][i][3] - mnew);
                float ls = e0 + e1 + e2 + e3;
                ls += __shfl_xor_sync(0xffffffffu, ls, 1);
                ls += __shfl_xor_sync(0xffffffffu, ls, 2);
                ls += __shfl_xor_sync(0xffffffffu, ls, 4);
                ls += __shfl_xor_sync(0xffffffffu, ls, 8);
                m[hh][i] = mnew;
                l[hh][i] = l[hh][i] * alpha + ls;
                alpha_s[row] = alpha;                 // identical value, all owners
                *(float4*)&Ps[row][c0] = make_float4(e0, e1, e2, e3);
            }
        __syncthreads();   // Ps + alpha ready

        // PV: o = o*alpha + P @ V  (4 rows x 4 d per thread)
        float al[4];
        #pragma unroll
        for (int i = 0; i < 4; i++) al[i] = alpha_s[rg + i];
        #pragma unroll
        for (int i = 0; i < 4; i++)
            #pragma unroll
            for (int d = 0; d < 4; d++) o[i][d] *= al[i];

        #pragma unroll
        for (int n4 = 0; n4 < 64; n4 += 4) {
            float p[4][4], vv[4][4];
            #pragma unroll
            for (int i = 0; i < 4; i++) {
                float4 t = *(const float4*)&Ps[rg + i][n4];
                p[i][0] = t.x; p[i][1] = t.y; p[i][2] = t.z; p[i][3] = t.w;
            }
            #pragma unroll
            for (int nn = 0; nn < 4; nn++) {
                float4 t = *(const float4*)&Vs[n4 + nn][dg];
                vv[nn][0] = t.x; vv[nn][1] = t.y; vv[nn][2] = t.z; vv[nn][3] = t.w;
            }
            #pragma unroll
            for (int i = 0; i < 4; i++)
                #pragma unroll
                for (int nn = 0; nn < 4; nn++)
                    #pragma unroll
                    for (int d = 0; d < 4; d++)
                        o[i][d] += p[i][nn] * vv[nn][d];
        }
        __syncthreads();   // Vs/Ps consumed before next staging
    }

    // publish row sums, normalize, store
    #pragma unroll
    for (int hh = 0; hh < 2; hh++)
        #pragma unroll
        for (int i = 0; i < 4; i++)
            l_s[hh * 32 + r0 + i] = l[hh][i];
    __syncthreads();

    #pragma unroll
    for (int i = 0; i < 4; i++) {
        float inv = 1.0f / l_s[rg + i];
        float4 res = make_float4(o[i][0] * inv, o[i][1] * inv,
                                 o[i][2] * inv, o[i][3] * inv);
        *(float4*)(Ob + (size_t)(tq * 64 + rg + i) * 256 + dg) = res;
    }
}

// ---------------------------------------------------------------------------
extern "C" void kernel_launch(void* const* d_in, const int* in_sizes, int n_in,
                              void* d_out, int out_size)
{
    const float* query = (const float*)d_in[0];
    const float* key   = (const float*)d_in[1];
    const float* value = (const float*)d_in[2];
    const float* Wq    = (const float*)d_in[3];
    const float* bq    = (const float*)d_in[4];
    const float* Wk    = (const float*)d_in[5];
    const float* bk    = (const float*)d_in[6];
    const float* Wv    = (const float*)d_in[7];
    const float* bv    = (const float*)d_in[8];
    const float* Wo    = (const float*)d_in[9];
    const float* bo    = (const float*)d_in[10];
    float* out = (float*)d_out;

    float *Q, *K, *V, *AO;
    cudaGetSymbolAddress((void**)&Q,  g_Q);
    cudaGetSymbolAddress((void**)&K,  g_K);
    cudaGetSymbolAddress((void**)&V,  g_V);
    cudaGetSymbolAddress((void**)&AO, g_AO);

    dim3 gblk(16, 16);
    dim3 gproj(DMODEL / 128, NROWS / 128);   // (2, 128)

    gemm_bias_kernel<<<gproj, gblk>>>(query, Wq, bq, Q);
    gemm_bias_kernel<<<gproj, gblk>>>(key,   Wk, bk, K);
    gemm_bias_kernel<<<gproj, gblk>>>(value, Wv, bv, V);

    attn_kernel<<<dim3(2048 / 64, 64), dim3(16, 8)>>>(Q, K, V, AO);

    gemm_bias_kernel<<<gproj, gblk>>>(AO, Wo, bo, out);
}

// round 6
// speedup vs baseline: 1.5099x; 1.5099x over previous
#include <cuda_runtime.h>
#include <cuda_bf16.h>
#include <cstdint>

// Problem constants: B=8, N=2048, D=256, HEAD=8, ATT=32
#define NROWS 16384   // B*N
#define DMODEL 256

// Scratch (allocation-free rule: device globals)
__device__ __align__(16) float g_Q[NROWS * DMODEL];
__device__ __align__(16) float g_K[NROWS * DMODEL];
__device__ __align__(16) float g_V[NROWS * DMODEL];
__device__ __align__(16) float g_AO[NROWS * DMODEL];
__device__ __align__(16) __nv_bfloat16 g_Wh[4 * DMODEL * DMODEL];
__device__ __align__(16) __nv_bfloat16 g_Wl[4 * DMODEL * DMODEL];

// ========================= PTX helpers (compute_100-safe) ==================
__device__ __forceinline__ uint32_t smem_u32(const void* p) {
    uint32_t a;
    asm("{ .reg .u64 t; cvta.to.shared.u64 t, %1; cvt.u32.u64 %0, t; }"
        : "=r"(a) : "l"(p));
    return a;
}

#define LDSM_X4(r, addr) \
    asm volatile("ldmatrix.sync.aligned.m8n8.x4.shared.b16 {%0,%1,%2,%3}, [%4];" \
        : "=r"((r)[0]), "=r"((r)[1]), "=r"((r)[2]), "=r"((r)[3]) : "r"(addr))

#define LDSM_X2(r, addr) \
    asm volatile("ldmatrix.sync.aligned.m8n8.x2.shared.b16 {%0,%1}, [%2];" \
        : "=r"((r)[0]), "=r"((r)[1]) : "r"(addr))

#define MMA16816(d, a, b) \
    asm volatile("mma.sync.aligned.m16n8k16.row.col.f32.bf16.bf16.f32 " \
        "{%0,%1,%2,%3}, {%4,%5,%6,%7}, {%8,%9}, {%0,%1,%2,%3};" \
        : "+f"((d)[0]), "+f"((d)[1]), "+f"((d)[2]), "+f"((d)[3]) \
        : "r"((a)[0]), "r"((a)[1]), "r"((a)[2]), "r"((a)[3]), \
          "r"((b)[0]), "r"((b)[1]))

// ============================ weight split =================================
__global__ void convert_w_kernel(const float* __restrict__ W0, const float* __restrict__ W1,
                                 const float* __restrict__ W2, const float* __restrict__ W3,
                                 __nv_bfloat16* __restrict__ hi, __nv_bfloat16* __restrict__ lo)
{
    int i = blockIdx.x * 256 + threadIdx.x;   // 0..65535
    int m = blockIdx.y;                        // 0..3
    const float* src = (m == 0) ? W0 : (m == 1) ? W1 : (m == 2) ? W2 : W3;
    float x = src[i];
    __nv_bfloat16 h = __float2bfloat16(x);
    float r = x - __bfloat162float(h);
    hi[m * 65536 + i] = h;
    lo[m * 65536 + i] = __float2bfloat16(r);
}

// ======================= mma.sync bf16-split GEMM ==========================
// C[16384,256] = A @ W^T + bias   (3-pass split: Ah*Wh + Ah*Wl + Al*Wh)
// Block: 256 thr (8 warps, 2x4), tile 128x128, K-chunk 32.
// Smem rows padded to 40 bf16 (80B) -> ldmatrix conflict-free.
__global__ __launch_bounds__(256)
void gemm_mma_kernel(const float* __restrict__ A,
                     const __nv_bfloat16* __restrict__ Whi,
                     const __nv_bfloat16* __restrict__ Wlo,
                     const float* __restrict__ bias,
                     float* __restrict__ C)
{
    __shared__ __align__(16) __nv_bfloat16 sAh[128][40];
    __shared__ __align__(16) __nv_bfloat16 sAl[128][40];
    __shared__ __align__(16) __nv_bfloat16 sWh[128][40];
    __shared__ __align__(16) __nv_bfloat16 sWl[128][40];

    const int tid  = threadIdx.x;
    const int wid  = tid >> 5;
    const int lane = tid & 31;
    const int m0 = blockIdx.y * 128;
    const int n0 = blockIdx.x * 128;
    const int wm = (wid >> 2) * 64;   // warp M offset (0/64)
    const int wn = (wid & 3) * 32;    // warp N offset (0/32/64/96)

    float acc[4][4][4] = {};          // [m16 tile][n8 tile][reg]

    for (int kk = 0; kk < 256; kk += 32) {
        __syncthreads();   // previous chunk's ldmatrix reads done
        // stage A (fp32 -> bf16 hi/lo)
        #pragma unroll
        for (int it = 0; it < 8; it++) {
            int idx = tid + it * 256;          // 0..2047
            int r = idx >> 4, c2 = (idx & 15) * 2;
            float2 a = *(const float2*)(A + (size_t)(m0 + r) * 256 + kk + c2);
            __nv_bfloat16 hx = __float2bfloat16(a.x);
            __nv_bfloat16 hy = __float2bfloat16(a.y);
            __nv_bfloat16 lx = __float2bfloat16(a.x - __bfloat162float(hx));
            __nv_bfloat16 ly = __float2bfloat16(a.y - __bfloat162float(hy));
            *(uint32_t*)&sAh[r][c2] =
                ((uint32_t)__bfloat16_as_ushort(hy) << 16) | __bfloat16_as_ushort(hx);
            *(uint32_t*)&sAl[r][c2] =
                ((uint32_t)__bfloat16_as_ushort(ly) << 16) | __bfloat16_as_ushort(lx);
        }
        // stage W hi/lo (already bf16)
        #pragma unroll
        for (int it = 0; it < 8; it++) {
            int idx = tid + it * 256;
            int r = idx >> 4, c2 = (idx & 15) * 2;
            *(uint32_t*)&sWh[r][c2] = *(const uint32_t*)(Whi + (size_t)(n0 + r) * 256 + kk + c2);
            *(uint32_t*)&sWl[r][c2] = *(const uint32_t*)(Wlo + (size_t)(n0 + r) * 256 + kk + c2);
        }
        __syncthreads();

        #pragma unroll
        for (int ks = 0; ks < 32; ks += 16) {
            uint32_t ah[4][4], al[4][4], wh[4][2], wl[4][2];
            // A fragments: ldmatrix x4; lane -> (row = lane&15, k-col = (lane>>4)*8)
            const int arow = lane & 15;
            const int acol = ks + ((lane >> 4) << 3);
            #pragma unroll
            for (int i = 0; i < 4; i++) {
                LDSM_X4(ah[i], smem_u32(&sAh[wm + i * 16 + arow][acol]));
                LDSM_X4(al[i], smem_u32(&sAl[wm + i * 16 + arow][acol]));
            }
            // B fragments: ldmatrix x2 on [n][k] rows (col-major B)
            const int brow = lane & 7;
            const int bcol = ks + (((lane >> 3) & 1) << 3);
            #pragma unroll
            for (int j = 0; j < 4; j++) {
                LDSM_X2(wh[j], smem_u32(&sWh[wn + j * 8 + brow][bcol]));
                LDSM_X2(wl[j], smem_u32(&sWl[wn + j * 8 + brow][bcol]));
            }
            #pragma unroll
            for (int i = 0; i < 4; i++)
                #pragma unroll
                for (int j = 0; j < 4; j++) {
                    MMA16816(acc[i][j], ah[i], wh[j]);
                    MMA16816(acc[i][j], ah[i], wl[j]);
                    MMA16816(acc[i][j], al[i], wh[j]);
                }
        }
    }

    // epilogue: c0,c1 -> (row, col..col+1); c2,c3 -> (row+8, ...)
    const int r0 = lane >> 2;
    const int cp = (lane & 3) * 2;
    #pragma unroll
    for (int i = 0; i < 4; i++)
        #pragma unroll
        for (int j = 0; j < 4; j++) {
            int col = n0 + wn + j * 8 + cp;
            float2 bb = *(const float2*)(bias + col);
            int row = m0 + wm + i * 16 + r0;
            float2 o0 = make_float2(acc[i][j][0] + bb.x, acc[i][j][1] + bb.y);
            *(float2*)(C + (size_t)row * 256 + col) = o0;
            float2 o1 = make_float2(acc[i][j][2] + bb.x, acc[i][j][3] + bb.y);
            *(float2*)(C + (size_t)(row + 8) * 256 + col) = o1;
        }
}

// ---------------------------------------------------------------------------
// Causal flash attention, fp32 (R2 kernel — measured 713us, rel_err 5e-7).
// ---------------------------------------------------------------------------
__global__ __launch_bounds__(256)
void attn_kernel(const float* __restrict__ Qg, const float* __restrict__ Kg,
                 const float* __restrict__ Vg, float* __restrict__ Og)
{
    __shared__ __align__(16) float Qs[32][64];
    __shared__ __align__(16) float Ks[32][64];
    __shared__ __align__(16) float Vs[64][32];
    __shared__ __align__(16) float Ps[64][64];
    __shared__ float m_s[64];
    __shared__ float l_s[64];

    const int tx = threadIdx.x, ty = threadIdx.y;
    const int tid = ty * 16 + tx;
    const int tq = (int)gridDim.x - 1 - (int)blockIdx.x;
    const int hb = blockIdx.y;
    const int h  = hb & 7;
    const int bb = hb >> 3;
    const size_t base = (size_t)bb * 2048 * 256 + (size_t)h * 32;
    const float* Qb = Qg + base;
    const float* Kb = Kg + base;
    const float* Vb = Vg + base;
    float*       Ob = Og + base;

    const float scale = 0.17677669529663687f;

    #pragma unroll
    for (int it = 0; it < 2; it++) {
        int idx = tid * 2 + it;
        int r   = idx >> 3;
        int c4  = (idx & 7) * 4;
        float4 v = *(const float4*)(Qb + (size_t)(tq * 64 + r) * 256 + c4);
        Qs[c4 + 0][r] = v.x * scale; Qs[c4 + 1][r] = v.y * scale;
        Qs[c4 + 2][r] = v.z * scale; Qs[c4 + 3][r] = v.w * scale;
    }
    if (tid < 64) { m_s[tid] = -1e30f; l_s[tid] = 0.0f; }

    const int r0 = ty * 4;
    const int c0 = tx * 4;
    const int cc = tx * 2;
    float o[4][2] = {};

    for (int j = 0; j <= tq; j++) {
        __syncthreads();
        #pragma unroll
        for (int it = 0; it < 2; it++) {
            int idx = tid * 2 + it;
            int r   = idx >> 3;
            int c4  = (idx & 7) * 4;
            float4 kv = *(const float4*)(Kb + (size_t)(j * 64 + r) * 256 + c4);
            Ks[c4 + 0][r] = kv.x; Ks[c4 + 1][r] = kv.y;
            Ks[c4 + 2][r] = kv.z; Ks[c4 + 3][r] = kv.w;
            float4 vv = *(const float4*)(Vb + (size_t)(j * 64 + r) * 256 + c4);
            *(float4*)&Vs[r][c4] = vv;
        }
        __syncthreads();

        float s[4][4] = {};
        #pragma unroll
        for (int k = 0; k < 32; k++) {
            float4 a = *(const float4*)&Qs[k][r0];
            float4 b = *(const float4*)&Ks[k][c0];
            s[0][0] += a.x*b.x; s[0][1] += a.x*b.y; s[0][2] += a.x*b.z; s[0][3] += a.x*b.w;
            s[1][0] += a.y*b.x; s[1][1] += a.y*b.y; s[1][2] += a.y*b.z; s[1][3] += a.y*b.w;
            s[2][0] += a.z*b.x; s[2][1] += a.z*b.y; s[2][2] += a.z*b.z; s[2][3] += a.z*b.w;
            s[3][0] += a.w*b.x; s[3][1] += a.w*b.y; s[3][2] += a.w*b.z; s[3][3] += a.w*b.w;
        }

        if (j == tq) {
            #pragma unroll
            for (int i = 0; i < 4; i++)
                #pragma unroll
                for (int jj = 0; jj < 4; jj++)
                    if (c0 + jj > r0 + i) s[i][jj] = -1e30f;
        }

        float mold[4], lold[4];
        #pragma unroll
        for (int i = 0; i < 4; i++) { mold[i] = m_s[r0 + i]; lold[i] = l_s[r0 + i]; }
        __syncwarp();

        float alpha[4];
        #pragma unroll
        for (int i = 0; i < 4; i++) {
            float mt = fmaxf(fmaxf(s[i][0], s[i][1]), fmaxf(s[i][2], s[i][3]));
            mt = fmaxf(mt, __shfl_xor_sync(0xffffffffu, mt, 1));
            mt = fmaxf(mt, __shfl_xor_sync(0xffffffffu, mt, 2));
            mt = fmaxf(mt, __shfl_xor_sync(0xffffffffu, mt, 4));
            mt = fmaxf(mt, __shfl_xor_sync(0xffffffffu, mt, 8));
            float mnew = fmaxf(mold[i], mt);
            alpha[i] = __expf(mold[i] - mnew);
            s[i][0] = __expf(s[i][0] - mnew);
            s[i][1] = __expf(s[i][1] - mnew);
            s[i][2] = __expf(s[i][2] - mnew);
            s[i][3] = __expf(s[i][3] - mnew);
            float ls = s[i][0] + s[i][1] + s[i][2] + s[i][3];
            ls += __shfl_xor_sync(0xffffffffu, ls, 1);
            ls += __shfl_xor_sync(0xffffffffu, ls, 2);
            ls += __shfl_xor_sync(0xffffffffu, ls, 4);
            ls += __shfl_xor_sync(0xffffffffu, ls, 8);
            m_s[r0 + i] = mnew;
            l_s[r0 + i] = lold[i] * alpha[i] + ls;
            o[i][0] *= alpha[i];
            o[i][1] *= alpha[i];
            float4 pv = make_float4(s[i][0], s[i][1], s[i][2], s[i][3]);
            *(float4*)&Ps[r0 + i][c0] = pv;
        }
        __syncthreads();

        #pragma unroll
        for (int n4 = 0; n4 < 64; n4 += 4) {
            float4 p0 = *(const float4*)&Ps[r0 + 0][n4];
            float4 p1 = *(const float4*)&Ps[r0 + 1][n4];
            float4 p2 = *(const float4*)&Ps[r0 + 2][n4];
            float4 p3 = *(const float4*)&Ps[r0 + 3][n4];
            float2 v0 = *(const float2*)&Vs[n4 + 0][cc];
            float2 v1 = *(const float2*)&Vs[n4 + 1][cc];
            float2 v2 = *(const float2*)&Vs[n4 + 2][cc];
            float2 v3 = *(const float2*)&Vs[n4 + 3][cc];
            o[0][0] += p0.x*v0.x + p0.y*v1.x + p0.z*v2.x + p0.w*v3.x;
            o[0][1] += p0.x*v0.y + p0.y*v1.y + p0.z*v2.y + p0.w*v3.y;
            o[1][0] += p1.x*v0.x + p1.y*v1.x + p1.z*v2.x + p1.w*v3.x;
            o[1][1] += p1.x*v0.y + p1.y*v1.y + p1.z*v2.y + p1.w*v3.y;
            o[2][0] += p2.x*v0.x + p2.y*v1.x + p2.z*v2.x + p2.w*v3.x;
            o[2][1] += p2.x*v0.y + p2.y*v1.y + p2.z*v2.y + p2.w*v3.y;
            o[3][0] += p3.x*v0.x + p3.y*v1.x + p3.z*v2.x + p3.w*v3.x;
            o[3][1] += p3.x*v0.y + p3.y*v1.y + p3.z*v2.y + p3.w*v3.y;
        }
    }

    #pragma unroll
    for (int i = 0; i < 4; i++) {
        float inv = 1.0f / l_s[r0 + i];
        float2 res = make_float2(o[i][0] * inv, o[i][1] * inv);
        *(float2*)(Ob + (size_t)(tq * 64 + r0 + i) * 256 + cc) = res;
    }
}

// ---------------------------------------------------------------------------
extern "C" void kernel_launch(void* const* d_in, const int* in_sizes, int n_in,
                              void* d_out, int out_size)
{
    const float* query = (const float*)d_in[0];
    const float* key   = (const float*)d_in[1];
    const float* value = (const float*)d_in[2];
    const float* Wq    = (const float*)d_in[3];
    const float* bq    = (const float*)d_in[4];
    const float* Wk    = (const float*)d_in[5];
    const float* bk    = (const float*)d_in[6];
    const float* Wv    = (const float*)d_in[7];
    const float* bv    = (const float*)d_in[8];
    const float* Wo    = (const float*)d_in[9];
    const float* bo    = (const float*)d_in[10];
    float* out = (float*)d_out;

    float *Q, *K, *V, *AO;
    __nv_bfloat16 *Wh, *Wl;
    cudaGetSymbolAddress((void**)&Q,  g_Q);
    cudaGetSymbolAddress((void**)&K,  g_K);
    cudaGetSymbolAddress((void**)&V,  g_V);
    cudaGetSymbolAddress((void**)&AO, g_AO);
    cudaGetSymbolAddress((void**)&Wh, g_Wh);
    cudaGetSymbolAddress((void**)&Wl, g_Wl);

    // split all 4 weight matrices into bf16 hi/lo
    convert_w_kernel<<<dim3(256, 4), 256>>>(Wq, Wk, Wv, Wo, Wh, Wl);

    dim3 ggrid(2, 128);   // 128x128 tiles over [16384 x 256]
    gemm_mma_kernel<<<ggrid, 256>>>(query, Wh,          Wl,          bq, Q);
    gemm_mma_kernel<<<ggrid, 256>>>(key,   Wh + 65536,  Wl + 65536,  bk, K);
    gemm_mma_kernel<<<ggrid, 256>>>(value, Wh + 131072, Wl + 131072, bv, V);

    attn_kernel<<<dim3(2048 / 64, 64), dim3(16, 16)>>>(Q, K, V, AO);

    gemm_mma_kernel<<<ggrid, 256>>>(AO, Wh + 196608, Wl + 196608, bo, out);
}

// round 7
// speedup vs baseline: 2.8429x; 1.8829x over previous
#include <cuda_runtime.h>
#include <cuda_bf16.h>
#include <cstdint>

// Problem constants: B=8, N=2048, D=256, HEAD=8, ATT=32
#define NROWS 16384   // B*N
#define DMODEL 256

// Scratch (allocation-free rule: device globals)
__device__ __align__(16) float g_Q[NROWS * DMODEL];
__device__ __align__(16) float g_K[NROWS * DMODEL];
__device__ __align__(16) float g_V[NROWS * DMODEL];
__device__ __align__(16) float g_AO[NROWS * DMODEL];
__device__ __align__(16) __nv_bfloat16 g_Wh[4 * DMODEL * DMODEL];
__device__ __align__(16) __nv_bfloat16 g_Wl[4 * DMODEL * DMODEL];

// ========================= PTX helpers (compute_100-safe) ==================
__device__ __forceinline__ uint32_t smem_u32(const void* p) {
    uint32_t a;
    asm("{ .reg .u64 t; cvta.to.shared.u64 t, %1; cvt.u32.u64 %0, t; }"
        : "=r"(a) : "l"(p));
    return a;
}

#define LDSM_X4(r, addr) \
    asm volatile("ldmatrix.sync.aligned.m8n8.x4.shared.b16 {%0,%1,%2,%3}, [%4];" \
        : "=r"((r)[0]), "=r"((r)[1]), "=r"((r)[2]), "=r"((r)[3]) : "r"(addr))

#define LDSM_X2(r, addr) \
    asm volatile("ldmatrix.sync.aligned.m8n8.x2.shared.b16 {%0,%1}, [%2];" \
        : "=r"((r)[0]), "=r"((r)[1]) : "r"(addr))

#define LDSM_X2_T(r, addr) \
    asm volatile("ldmatrix.sync.aligned.m8n8.x2.trans.shared.b16 {%0,%1}, [%2];" \
        : "=r"((r)[0]), "=r"((r)[1]) : "r"(addr))

#define MMA16816(d, a, b) \
    asm volatile("mma.sync.aligned.m16n8k16.row.col.f32.bf16.bf16.f32 " \
        "{%0,%1,%2,%3}, {%4,%5,%6,%7}, {%8,%9}, {%0,%1,%2,%3};" \
        : "+f"((d)[0]), "+f"((d)[1]), "+f"((d)[2]), "+f"((d)[3]) \
        : "r"((a)[0]), "r"((a)[1]), "r"((a)[2]), "r"((a)[3]), \
          "r"((b)[0]), "r"((b)[1]))

__device__ __forceinline__ void split_pack(float x, float y, uint32_t& hp, uint32_t& lp) {
    __nv_bfloat16 hx = __float2bfloat16(x);
    __nv_bfloat16 hy = __float2bfloat16(y);
    __nv_bfloat16 lx = __float2bfloat16(x - __bfloat162float(hx));
    __nv_bfloat16 ly = __float2bfloat16(y - __bfloat162float(hy));
    hp = ((uint32_t)__bfloat16_as_ushort(hy) << 16) | __bfloat16_as_ushort(hx);
    lp = ((uint32_t)__bfloat16_as_ushort(ly) << 16) | __bfloat16_as_ushort(lx);
}

// ============================ weight split =================================
__global__ void convert_w_kernel(const float* __restrict__ W0, const float* __restrict__ W1,
                                 const float* __restrict__ W2, const float* __restrict__ W3,
                                 __nv_bfloat16* __restrict__ hi, __nv_bfloat16* __restrict__ lo)
{
    int i = blockIdx.x * 256 + threadIdx.x;
    int m = blockIdx.y;
    const float* src = (m == 0) ? W0 : (m == 1) ? W1 : (m == 2) ? W2 : W3;
    float x = src[i];
    __nv_bfloat16 h = __float2bfloat16(x);
    float r = x - __bfloat162float(h);
    hi[m * 65536 + i] = h;
    lo[m * 65536 + i] = __float2bfloat16(r);
}

// ======================= mma.sync bf16-split GEMM ==========================
// (unchanged from R5 — measured 41us/GEMM, rel_err 7e-6)
__global__ __launch_bounds__(256)
void gemm_mma_kernel(const float* __restrict__ A,
                     const __nv_bfloat16* __restrict__ Whi,
                     const __nv_bfloat16* __restrict__ Wlo,
                     const float* __restrict__ bias,
                     float* __restrict__ C)
{
    __shared__ __align__(16) __nv_bfloat16 sAh[128][40];
    __shared__ __align__(16) __nv_bfloat16 sAl[128][40];
    __shared__ __align__(16) __nv_bfloat16 sWh[128][40];
    __shared__ __align__(16) __nv_bfloat16 sWl[128][40];

    const int tid  = threadIdx.x;
    const int wid  = tid >> 5;
    const int lane = tid & 31;
    const int m0 = blockIdx.y * 128;
    const int n0 = blockIdx.x * 128;
    const int wm = (wid >> 2) * 64;
    const int wn = (wid & 3) * 32;

    float acc[4][4][4] = {};

    for (int kk = 0; kk < 256; kk += 32) {
        __syncthreads();
        #pragma unroll
        for (int it = 0; it < 8; it++) {
            int idx = tid + it * 256;
            int r = idx >> 4, c2 = (idx & 15) * 2;
            float2 a = *(const float2*)(A + (size_t)(m0 + r) * 256 + kk + c2);
            uint32_t hp, lp;
            split_pack(a.x, a.y, hp, lp);
            *(uint32_t*)&sAh[r][c2] = hp;
            *(uint32_t*)&sAl[r][c2] = lp;
        }
        #pragma unroll
        for (int it = 0; it < 8; it++) {
            int idx = tid + it * 256;
            int r = idx >> 4, c2 = (idx & 15) * 2;
            *(uint32_t*)&sWh[r][c2] = *(const uint32_t*)(Whi + (size_t)(n0 + r) * 256 + kk + c2);
            *(uint32_t*)&sWl[r][c2] = *(const uint32_t*)(Wlo + (size_t)(n0 + r) * 256 + kk + c2);
        }
        __syncthreads();

        #pragma unroll
        for (int ks = 0; ks < 32; ks += 16) {
            uint32_t ah[4][4], al[4][4], wh[4][2], wl[4][2];
            const int arow = lane & 15;
            const int acol = ks + ((lane >> 4) << 3);
            #pragma unroll
            for (int i = 0; i < 4; i++) {
                LDSM_X4(ah[i], smem_u32(&sAh[wm + i * 16 + arow][acol]));
                LDSM_X4(al[i], smem_u32(&sAl[wm + i * 16 + arow][acol]));
            }
            const int brow = lane & 7;
            const int bcol = ks + (((lane >> 3) & 1) << 3);
            #pragma unroll
            for (int j = 0; j < 4; j++) {
                LDSM_X2(wh[j], smem_u32(&sWh[wn + j * 8 + brow][bcol]));
                LDSM_X2(wl[j], smem_u32(&sWl[wn + j * 8 + brow][bcol]));
            }
            #pragma unroll
            for (int i = 0; i < 4; i++)
                #pragma unroll
                for (int j = 0; j < 4; j++) {
                    MMA16816(acc[i][j], ah[i], wh[j]);
                    MMA16816(acc[i][j], ah[i], wl[j]);
                    MMA16816(acc[i][j], al[i], wh[j]);
                }
        }
    }

    const int r0 = lane >> 2;
    const int cp = (lane & 3) * 2;
    #pragma unroll
    for (int i = 0; i < 4; i++)
        #pragma unroll
        for (int j = 0; j < 4; j++) {
            int col = n0 + wn + j * 8 + cp;
            float2 bb = *(const float2*)(bias + col);
            int row = m0 + wm + i * 16 + r0;
            float2 o0 = make_float2(acc[i][j][0] + bb.x, acc[i][j][1] + bb.y);
            *(float2*)(C + (size_t)row * 256 + col) = o0;
            float2 o1 = make_float2(acc[i][j][2] + bb.x, acc[i][j][3] + bb.y);
            *(float2*)(C + (size_t)(row + 8) * 256 + col) = o1;
        }
}

// ====================== mma.sync flash attention ===========================
// 128 q-rows per block, 8 warps (16 rows each), KV tiles of 64, head dim 32.
// S = Q@K^T via 3-pass bf16 split; P stays in registers (acc layout == A-frag
// layout for PV); PV via 3-pass split. Per-warp softmax: shfl over 4 lanes.
__global__ __launch_bounds__(256)
void attn_mma_kernel(const float* __restrict__ Qg, const float* __restrict__ Kg,
                     const float* __restrict__ Vg, float* __restrict__ Og)
{
    __shared__ __align__(16) __nv_bfloat16 sQh[128][40];
    __shared__ __align__(16) __nv_bfloat16 sQl[128][40];
    __shared__ __align__(16) __nv_bfloat16 sKh[64][40];
    __shared__ __align__(16) __nv_bfloat16 sKl[64][40];
    __shared__ __align__(16) __nv_bfloat16 sVh[64][40];
    __shared__ __align__(16) __nv_bfloat16 sVl[64][40];

    const int tid  = threadIdx.x;
    const int wid  = tid >> 5;
    const int lane = tid & 31;
    const int tq = (int)gridDim.x - 1 - (int)blockIdx.x;   // long blocks first
    const int hb = blockIdx.y;
    const int h  = hb & 7;
    const int bb = hb >> 3;
    const size_t base = (size_t)bb * 2048 * 256 + (size_t)h * 32;
    const float* Qb = Qg + base;
    const float* Kb = Kg + base;
    const float* Vb = Vg + base;
    float*       Ob = Og + base;
    const int qbase = tq * 128;
    const float scale = 0.17677669529663687f;   // 1/sqrt(32)

    // stage Q (scaled, bf16 hi/lo)
    #pragma unroll
    for (int it = 0; it < 8; it++) {
        int idx = tid + it * 256;            // 0..2047
        int r = idx >> 4, c2 = (idx & 15) * 2;
        float2 v = *(const float2*)(Qb + (size_t)(qbase + r) * 256 + c2);
        uint32_t hp, lp;
        split_pack(v.x * scale, v.y * scale, hp, lp);
        *(uint32_t*)&sQh[r][c2] = hp;
        *(uint32_t*)&sQl[r][c2] = lp;
    }
    __syncthreads();

    // per-warp Q fragments (resident for whole kernel)
    uint32_t qh[2][4], ql[2][4];
    {
        const int arow = lane & 15;
        const int aco  = ((lane >> 4) << 3);
        #pragma unroll
        for (int ks = 0; ks < 2; ks++) {
            LDSM_X4(qh[ks], smem_u32(&sQh[wid * 16 + arow][ks * 16 + aco]));
            LDSM_X4(ql[ks], smem_u32(&sQl[wid * 16 + arow][ks * 16 + aco]));
        }
    }

    float o[4][4] = {};
    float mrow[2] = {-1e30f, -1e30f};
    float lrow[2] = {0.0f, 0.0f};

    const int ntiles = 2 * tq + 2;

    // prefetch KV tile 0 (4 K float2 + 4 V float2 per thread)
    float2 pk[4], pv[4];
    #pragma unroll
    for (int it = 0; it < 4; it++) {
        int idx = tid + it * 256;            // 0..1023
        int r = idx >> 4, c2 = (idx & 15) * 2;
        pk[it] = *(const float2*)(Kb + (size_t)r * 256 + c2);
        pv[it] = *(const float2*)(Vb + (size_t)r * 256 + c2);
    }

    for (int jt = 0; jt < ntiles; jt++) {
        __syncthreads();   // previous tile's smem reads done
        // stage K/V (split hi/lo)
        #pragma unroll
        for (int it = 0; it < 4; it++) {
            int idx = tid + it * 256;
            int r = idx >> 4, c2 = (idx & 15) * 2;
            uint32_t hp, lp;
            split_pack(pk[it].x, pk[it].y, hp, lp);
            *(uint32_t*)&sKh[r][c2] = hp;
            *(uint32_t*)&sKl[r][c2] = lp;
            split_pack(pv[it].x, pv[it].y, hp, lp);
            *(uint32_t*)&sVh[r][c2] = hp;
            *(uint32_t*)&sVl[r][c2] = lp;
        }
        __syncthreads();

        // prefetch next tile (overlaps compute)
        if (jt + 1 < ntiles) {
            #pragma unroll
            for (int it = 0; it < 4; it++) {
                int idx = tid + it * 256;
                int r = (jt + 1) * 64 + (idx >> 4);
                int c2 = (idx & 15) * 2;
                pk[it] = *(const float2*)(Kb + (size_t)r * 256 + c2);
                pv[it] = *(const float2*)(Vb + (size_t)r * 256 + c2);
            }
        }

        // skip warps whose entire 16-row strip is masked by causality
        if (jt * 64 > qbase + wid * 16 + 15) continue;

        // ---- S = Q @ K^T (3-pass split) ----
        float s[8][4] = {};
        #pragma unroll
        for (int ks = 0; ks < 2; ks++) {
            uint32_t kh[8][2], kl[8][2];
            const int brow = lane & 7;
            const int bcol = ks * 16 + (((lane >> 3) & 1) << 3);
            #pragma unroll
            for (int j = 0; j < 8; j++) {
                LDSM_X2(kh[j], smem_u32(&sKh[j * 8 + brow][bcol]));
                LDSM_X2(kl[j], smem_u32(&sKl[j * 8 + brow][bcol]));
            }
            #pragma unroll
            for (int j = 0; j < 8; j++) {
                MMA16816(s[j], qh[ks], kh[j]);
                MMA16816(s[j], qh[ks], kl[j]);
                MMA16816(s[j], ql[ks], kh[j]);
            }
        }

        // ---- causal mask (diagonal region only) ----
        if (jt >= 2 * tq) {
            const int row0 = qbase + wid * 16 + (lane >> 2);
            #pragma unroll
            for (int j = 0; j < 8; j++) {
                int col = jt * 64 + j * 8 + (lane & 3) * 2;
                if (col     > row0)     s[j][0] = -1e30f;
                if (col + 1 > row0)     s[j][1] = -1e30f;
                if (col     > row0 + 8) s[j][2] = -1e30f;
                if (col + 1 > row0 + 8) s[j][3] = -1e30f;
            }
        }

        // ---- online softmax (per half: regs {0,1} row g, {2,3} row g+8) ----
        #pragma unroll
        for (int hf = 0; hf < 2; hf++) {
            float mt = -1e30f;
            #pragma unroll
            for (int j = 0; j < 8; j++)
                mt = fmaxf(mt, fmaxf(s[j][2 * hf], s[j][2 * hf + 1]));
            mt = fmaxf(mt, __shfl_xor_sync(0xffffffffu, mt, 1));
            mt = fmaxf(mt, __shfl_xor_sync(0xffffffffu, mt, 2));
            float mnew  = fmaxf(mrow[hf], mt);
            float alpha = __expf(mrow[hf] - mnew);
            float ls = 0.0f;
            #pragma unroll
            for (int j = 0; j < 8; j++) {
                s[j][2 * hf]     = __expf(s[j][2 * hf]     - mnew);
                s[j][2 * hf + 1] = __expf(s[j][2 * hf + 1] - mnew);
                ls += s[j][2 * hf] + s[j][2 * hf + 1];
            }
            ls += __shfl_xor_sync(0xffffffffu, ls, 1);
            ls += __shfl_xor_sync(0xffffffffu, ls, 2);
            mrow[hf] = mnew;
            lrow[hf] = lrow[hf] * alpha + ls;
            #pragma unroll
            for (int j = 0; j < 4; j++) {
                o[j][2 * hf]     *= alpha;
                o[j][2 * hf + 1] *= alpha;
            }
        }

        // ---- O += P @ V (3-pass split; P from registers) ----
        #pragma unroll
        for (int t = 0; t < 4; t++) {
            uint32_t ph[4], pl[4];
            split_pack(s[2 * t][0],     s[2 * t][1],     ph[0], pl[0]);
            split_pack(s[2 * t][2],     s[2 * t][3],     ph[1], pl[1]);
            split_pack(s[2 * t + 1][0], s[2 * t + 1][1], ph[2], pl[2]);
            split_pack(s[2 * t + 1][2], s[2 * t + 1][3], ph[3], pl[3]);

            uint32_t vh[4][2], vl[4][2];
            const int vrow = t * 16 + (lane & 15);
            #pragma unroll
            for (int j = 0; j < 4; j++) {
                LDSM_X2_T(vh[j], smem_u32(&sVh[vrow][j * 8]));
                LDSM_X2_T(vl[j], smem_u32(&sVl[vrow][j * 8]));
            }
            #pragma unroll
            for (int j = 0; j < 4; j++) {
                MMA16816(o[j], ph, vh[j]);
                MMA16816(o[j], ph, vl[j]);
                MMA16816(o[j], pl, vh[j]);
            }
        }
    }

    // ---- normalize + store ----
    const float inv0 = 1.0f / lrow[0];
    const float inv1 = 1.0f / lrow[1];
    const int row = qbase + wid * 16 + (lane >> 2);
    #pragma unroll
    for (int j = 0; j < 4; j++) {
        int col = j * 8 + (lane & 3) * 2;
        float2 o0 = make_float2(o[j][0] * inv0, o[j][1] * inv0);
        *(float2*)(Ob + (size_t)row * 256 + col) = o0;
        float2 o1 = make_float2(o[j][2] * inv1, o[j][3] * inv1);
        *(float2*)(Ob + (size_t)(row + 8) * 256 + col) = o1;
    }
}

// ---------------------------------------------------------------------------
extern "C" void kernel_launch(void* const* d_in, const int* in_sizes, int n_in,
                              void* d_out, int out_size)
{
    const float* query = (const float*)d_in[0];
    const float* key   = (const float*)d_in[1];
    const float* value = (const float*)d_in[2];
    const float* Wq    = (const float*)d_in[3];
    const float* bq    = (const float*)d_in[4];
    const float* Wk    = (const float*)d_in[5];
    const float* bk    = (const float*)d_in[6];
    const float* Wv    = (const float*)d_in[7];
    const float* bv    = (const float*)d_in[8];
    const float* Wo    = (const float*)d_in[9];
    const float* bo    = (const float*)d_in[10];
    float* out = (float*)d_out;

    float *Q, *K, *V, *AO;
    __nv_bfloat16 *Wh, *Wl;
    cudaGetSymbolAddress((void**)&Q,  g_Q);
    cudaGetSymbolAddress((void**)&K,  g_K);
    cudaGetSymbolAddress((void**)&V,  g_V);
    cudaGetSymbolAddress((void**)&AO, g_AO);
    cudaGetSymbolAddress((void**)&Wh, g_Wh);
    cudaGetSymbolAddress((void**)&Wl, g_Wl);

    convert_w_kernel<<<dim3(256, 4), 256>>>(Wq, Wk, Wv, Wo, Wh, Wl);

    dim3 ggrid(2, 128);
    gemm_mma_kernel<<<ggrid, 256>>>(query, Wh,          Wl,          bq, Q);
    gemm_mma_kernel<<<ggrid, 256>>>(key,   Wh + 65536,  Wl + 65536,  bk, K);
    gemm_mma_kernel<<<ggrid, 256>>>(value, Wh + 131072, Wl + 131072, bv, V);

    attn_mma_kernel<<<dim3(16, 64), 256>>>(Q, K, V, AO);

    gemm_mma_kernel<<<ggrid, 256>>>(AO, Wh + 196608, Wl + 196608, bo, out);
}

// round 8
// speedup vs baseline: 3.3219x; 1.1685x over previous
#include <cuda_runtime.h>
#include <cuda_bf16.h>
#include <cstdint>

// Problem constants: B=8, N=2048, D=256, HEAD=8, ATT=32
#define NROWS 16384   // B*N
#define DMODEL 256

// Scratch (allocation-free rule: device globals)
__device__ __align__(16) float g_AO[NROWS * DMODEL];
__device__ __align__(16) __nv_bfloat16 g_Qh[NROWS * DMODEL];
__device__ __align__(16) __nv_bfloat16 g_Ql[NROWS * DMODEL];
__device__ __align__(16) __nv_bfloat16 g_Kh[NROWS * DMODEL];
__device__ __align__(16) __nv_bfloat16 g_Kl[NROWS * DMODEL];
__device__ __align__(16) __nv_bfloat16 g_Vh[NROWS * DMODEL];
__device__ __align__(16) __nv_bfloat16 g_Vl[NROWS * DMODEL];
__device__ __align__(16) __nv_bfloat16 g_Wh[4 * DMODEL * DMODEL];
__device__ __align__(16) __nv_bfloat16 g_Wl[4 * DMODEL * DMODEL];

// ========================= PTX helpers (compute_100-safe) ==================
__device__ __forceinline__ uint32_t smem_u32(const void* p) {
    uint32_t a;
    asm("{ .reg .u64 t; cvta.to.shared.u64 t, %1; cvt.u32.u64 %0, t; }"
        : "=r"(a) : "l"(p));
    return a;
}

#define LDSM_X4(r, addr) \
    asm volatile("ldmatrix.sync.aligned.m8n8.x4.shared.b16 {%0,%1,%2,%3}, [%4];" \
        : "=r"((r)[0]), "=r"((r)[1]), "=r"((r)[2]), "=r"((r)[3]) : "r"(addr))

#define LDSM_X2(r, addr) \
    asm volatile("ldmatrix.sync.aligned.m8n8.x2.shared.b16 {%0,%1}, [%2];" \
        : "=r"((r)[0]), "=r"((r)[1]) : "r"(addr))

#define LDSM_X2_T(r, addr) \
    asm volatile("ldmatrix.sync.aligned.m8n8.x2.trans.shared.b16 {%0,%1}, [%2];" \
        : "=r"((r)[0]), "=r"((r)[1]) : "r"(addr))

#define MMA16816(d, a, b) \
    asm volatile("mma.sync.aligned.m16n8k16.row.col.f32.bf16.bf16.f32 " \
        "{%0,%1,%2,%3}, {%4,%5,%6,%7}, {%8,%9}, {%0,%1,%2,%3};" \
        : "+f"((d)[0]), "+f"((d)[1]), "+f"((d)[2]), "+f"((d)[3]) \
        : "r"((a)[0]), "r"((a)[1]), "r"((a)[2]), "r"((a)[3]), \
          "r"((b)[0]), "r"((b)[1]))

#define CP_ASYNC16(dst, src) \
    asm volatile("cp.async.cg.shared.global [%0], [%1], 16;" \
        :: "r"(dst), "l"(src) : "memory")
#define CP_COMMIT() asm volatile("cp.async.commit_group;" ::: "memory")
#define CP_WAIT0()  asm volatile("cp.async.wait_group 0;" ::: "memory")
#define CP_WAIT1()  asm volatile("cp.async.wait_group 1;" ::: "memory")

__device__ __forceinline__ void split_pack(float x, float y, uint32_t& hp, uint32_t& lp) {
    __nv_bfloat16 hx = __float2bfloat16(x);
    __nv_bfloat16 hy = __float2bfloat16(y);
    __nv_bfloat16 lx = __float2bfloat16(x - __bfloat162float(hx));
    __nv_bfloat16 ly = __float2bfloat16(y - __bfloat162float(hy));
    hp = ((uint32_t)__bfloat16_as_ushort(hy) << 16) | __bfloat16_as_ushort(hx);
    lp = ((uint32_t)__bfloat16_as_ushort(ly) << 16) | __bfloat16_as_ushort(lx);
}

// ============================ weight split =================================
__global__ void convert_w_kernel(const float* __restrict__ W0, const float* __restrict__ W1,
                                 const float* __restrict__ W2, const float* __restrict__ W3,
                                 __nv_bfloat16* __restrict__ hi, __nv_bfloat16* __restrict__ lo)
{
    int i = blockIdx.x * 256 + threadIdx.x;
    int m = blockIdx.y;
    const float* src = (m == 0) ? W0 : (m == 1) ? W1 : (m == 2) ? W2 : W3;
    float x = src[i];
    __nv_bfloat16 h = __float2bfloat16(x);
    float r = x - __bfloat162float(h);
    hi[m * 65536 + i] = h;
    lo[m * 65536 + i] = __float2bfloat16(r);
}

// ==================== pipelined mma.sync bf16-split GEMM ===================
// Dynamic smem layout (byte offsets, row stride 40 bf16 = 80 B):
//   sAh @ 0, sAl @ 10240, W buf b: Wh @ 20480+b*20480, Wl @ +10240.  Total 61440.
#define GSM_AH   0
#define GSM_AL   10240
#define GSM_WB(b) (20480 + (b) * 20480)
#define GSM_TOTAL 61440

// Mainloop shared by both GEMM kernels. acc[4][4][4] per thread.
#define GEMM_MAINLOOP(APTR, WHI, WLO)                                              \
    float2 pa[8];                                                                  \
    /* prologue: cp.async W chunk0 -> buf0; load A chunk0 regs */                  \
    _Pragma("unroll")                                                              \
    for (int g = 0; g < 2; g++) {                                                  \
        int s = tid + g * 256, r = s >> 2, c8 = (s & 3) * 8;                       \
        CP_ASYNC16(sb + GSM_WB(0) + (r * 40 + c8) * 2,                             \
                   (WHI) + (size_t)(n0 + r) * 256 + c8);                           \
        CP_ASYNC16(sb + GSM_WB(0) + 10240 + (r * 40 + c8) * 2,                     \
                   (WLO) + (size_t)(n0 + r) * 256 + c8);                           \
    }                                                                              \
    CP_COMMIT();                                                                   \
    _Pragma("unroll")                                                              \
    for (int it = 0; it < 8; it++) {                                               \
        int idx = tid + it * 256, r = idx >> 4, c2 = (idx & 15) * 2;               \
        pa[it] = *(const float2*)((APTR) + (size_t)(m0 + r) * 256 + c2);           \
    }                                                                              \
    for (int chunk = 0; chunk < 8; chunk++) {                                      \
        const int kk = chunk * 32;                                                 \
        const uint32_t wb = sb + GSM_WB(chunk & 1);                                \
        __syncthreads();                                                           \
        _Pragma("unroll")                                                          \
        for (int it = 0; it < 8; it++) {                                           \
            int idx = tid + it * 256, r = idx >> 4, c2 = (idx & 15) * 2;           \
            uint32_t hp, lp;                                                       \
            split_pack(pa[it].x, pa[it].y, hp, lp);                                \
            *(uint32_t*)(smem + GSM_AH + (r * 40 + c2) * 2) = hp;                  \
            *(uint32_t*)(smem + GSM_AL + (r * 40 + c2) * 2) = lp;                  \
        }                                                                          \
        if (chunk < 7) {                                                           \
            const uint32_t wn2 = sb + GSM_WB((chunk + 1) & 1);                     \
            _Pragma("unroll")                                                      \
            for (int g = 0; g < 2; g++) {                                          \
                int s = tid + g * 256, r = s >> 2, c8 = (s & 3) * 8;               \
                CP_ASYNC16(wn2 + (r * 40 + c8) * 2,                                \
                           (WHI) + (size_t)(n0 + r) * 256 + kk + 32 + c8);         \
                CP_ASYNC16(wn2 + 10240 + (r * 40 + c8) * 2,                        \
                           (WLO) + (size_t)(n0 + r) * 256 + kk + 32 + c8);         \
            }                                                                      \
            CP_COMMIT();                                                           \
            _Pragma("unroll")                                                      \
            for (int it = 0; it < 8; it++) {                                       \
                int idx = tid + it * 256, r = idx >> 4, c2 = (idx & 15) * 2;       \
                pa[it] = *(const float2*)((APTR) + (size_t)(m0 + r) * 256 + kk + 32 + c2); \
            }                                                                      \
            CP_WAIT1();                                                            \
        } else {                                                                   \
            CP_WAIT0();                                                            \
        }                                                                          \
        __syncthreads();                                                           \
        _Pragma("unroll")                                                          \
        for (int ks = 0; ks < 32; ks += 16) {                                      \
            uint32_t ah[4][4], al[4][4], wh[4][2], wl[4][2];                       \
            const int arow = lane & 15;                                            \
            const int acol = ks + ((lane >> 4) << 3);                              \
            _Pragma("unroll")                                                      \
            for (int i = 0; i < 4; i++) {                                          \
                LDSM_X4(ah[i], sb + GSM_AH + ((wm + i * 16 + arow) * 40 + acol) * 2); \
                LDSM_X4(al[i], sb + GSM_AL + ((wm + i * 16 + arow) * 40 + acol) * 2); \
            }                                                                      \
            const int brow = lane & 7;                                             \
            const int bcol = ks + (((lane >> 3) & 1) << 3);                        \
            _Pragma("unroll")                                                      \
            for (int j = 0; j < 4; j++) {                                          \
                LDSM_X2(wh[j], wb + ((wn + j * 8 + brow) * 40 + bcol) * 2);        \
                LDSM_X2(wl[j], wb + 10240 + ((wn + j * 8 + brow) * 40 + bcol) * 2);\
            }                                                                      \
            _Pragma("unroll")                                                      \
            for (int i = 0; i < 4; i++)                                            \
                _Pragma("unroll")                                                  \
                for (int j = 0; j < 4; j++) {                                      \
                    MMA16816(acc[i][j], ah[i], wh[j]);                             \
                    MMA16816(acc[i][j], ah[i], wl[j]);                             \
                    MMA16816(acc[i][j], al[i], wh[j]);                             \
                }                                                                  \
        }                                                                          \
    }

// --- fused QKV projection: writes bf16 hi/lo outputs (Q pre-scaled) ---
__global__ __launch_bounds__(256)
void gemm_qkv_kernel(const float* __restrict__ query, const float* __restrict__ key,
                     const float* __restrict__ value,
                     const __nv_bfloat16* __restrict__ Wh_all,
                     const __nv_bfloat16* __restrict__ Wl_all,
                     const float* __restrict__ bq, const float* __restrict__ bk,
                     const float* __restrict__ bv,
                     __nv_bfloat16* __restrict__ Qh, __nv_bfloat16* __restrict__ Ql,
                     __nv_bfloat16* __restrict__ Kh, __nv_bfloat16* __restrict__ Kl,
                     __nv_bfloat16* __restrict__ Vh, __nv_bfloat16* __restrict__ Vl)
{
    extern __shared__ char smem[];
    const uint32_t sb = smem_u32(smem);
    const int tid  = threadIdx.x;
    const int wid  = tid >> 5;
    const int lane = tid & 31;
    const int m0 = blockIdx.y * 128;
    const int n0 = blockIdx.x * 128;
    const int wm = (wid >> 2) * 64;
    const int wn = (wid & 3) * 32;
    const int z = blockIdx.z;

    const float* A   = (z == 0) ? query : (z == 1) ? key : value;
    const float* bia = (z == 0) ? bq    : (z == 1) ? bk  : bv;
    __nv_bfloat16* Oh = (z == 0) ? Qh : (z == 1) ? Kh : Vh;
    __nv_bfloat16* Ol = (z == 0) ? Ql : (z == 1) ? Kl : Vl;
    const __nv_bfloat16* Whi = Wh_all + (size_t)z * 65536;
    const __nv_bfloat16* Wlo = Wl_all + (size_t)z * 65536;
    const float oscale = (z == 0) ? 0.17677669529663687f : 1.0f;

    float acc[4][4][4] = {};
    GEMM_MAINLOOP(A, Whi, Wlo)

    const int r0 = lane >> 2;
    const int cp = (lane & 3) * 2;
    #pragma unroll
    for (int i = 0; i < 4; i++)
        #pragma unroll
        for (int j = 0; j < 4; j++) {
            int col = n0 + wn + j * 8 + cp;
            float2 bb = *(const float2*)(bia + col);
            int row = m0 + wm + i * 16 + r0;
            uint32_t hp, lp;
            split_pack((acc[i][j][0] + bb.x) * oscale,
                       (acc[i][j][1] + bb.y) * oscale, hp, lp);
            *(uint32_t*)(Oh + (size_t)row * 256 + col) = hp;
            *(uint32_t*)(Ol + (size_t)row * 256 + col) = lp;
            split_pack((acc[i][j][2] + bb.x) * oscale,
                       (acc[i][j][3] + bb.y) * oscale, hp, lp);
            *(uint32_t*)(Oh + (size_t)(row + 8) * 256 + col) = hp;
            *(uint32_t*)(Ol + (size_t)(row + 8) * 256 + col) = lp;
        }
}

// --- output projection: fp32 epilogue ---
__global__ __launch_bounds__(256)
void gemm_out_kernel(const float* __restrict__ A,
                     const __nv_bfloat16* __restrict__ Whi,
                     const __nv_bfloat16* __restrict__ Wlo,
                     const float* __restrict__ bias,
                     float* __restrict__ C)
{
    extern __shared__ char smem[];
    const uint32_t sb = smem_u32(smem);
    const int tid  = threadIdx.x;
    const int wid  = tid >> 5;
    const int lane = tid & 31;
    const int m0 = blockIdx.y * 128;
    const int n0 = blockIdx.x * 128;
    const int wm = (wid >> 2) * 64;
    const int wn = (wid & 3) * 32;

    float acc[4][4][4] = {};
    GEMM_MAINLOOP(A, Whi, Wlo)

    const int r0 = lane >> 2;
    const int cp = (lane & 3) * 2;
    #pragma unroll
    for (int i = 0; i < 4; i++)
        #pragma unroll
        for (int j = 0; j < 4; j++) {
            int col = n0 + wn + j * 8 + cp;
            float2 bb = *(const float2*)(bias + col);
            int row = m0 + wm + i * 16 + r0;
            float2 o0 = make_float2(acc[i][j][0] + bb.x, acc[i][j][1] + bb.y);
            *(float2*)(C + (size_t)row * 256 + col) = o0;
            float2 o1 = make_float2(acc[i][j][2] + bb.x, acc[i][j][3] + bb.y);
            *(float2*)(C + (size_t)(row + 8) * 256 + col) = o1;
        }
}

// ====================== mma.sync flash attention ===========================
// Inputs are pre-split bf16 hi/lo (Q pre-scaled). Staging = cp.async only,
// K/V double-buffered. 128 q-rows/block, 8 warps, KV tile 64.
// Dynamic smem: Qh @ 0, Ql @ 10240; KV buf b @ 20480+b*20480:
//   {Kh +0, Kl +5120, Vh +10240, Vl +15360}. Total 61440.
#define ASM_QH 0
#define ASM_QL 10240
#define ASM_KV(b) (20480 + (b) * 20480)
#define ASM_TOTAL 61440

__global__ __launch_bounds__(256)
void attn_mma_kernel(const __nv_bfloat16* __restrict__ Qh_g,
                     const __nv_bfloat16* __restrict__ Ql_g,
                     const __nv_bfloat16* __restrict__ Kh_g,
                     const __nv_bfloat16* __restrict__ Kl_g,
                     const __nv_bfloat16* __restrict__ Vh_g,
                     const __nv_bfloat16* __restrict__ Vl_g,
                     float* __restrict__ Og)
{
    extern __shared__ char smem[];
    const uint32_t sb = smem_u32(smem);
    const int tid  = threadIdx.x;
    const int wid  = tid >> 5;
    const int lane = tid & 31;
    const int tq = (int)gridDim.x - 1 - (int)blockIdx.x;   // long blocks first
    const int hb = blockIdx.y;
    const int h  = hb & 7;
    const int bb = hb >> 3;
    const size_t base = (size_t)bb * 2048 * 256 + (size_t)h * 32;
    const int qbase = tq * 128;
    float* Ob = Og + base;

    const int ntiles = 2 * tq + 2;

    // prologue: cp.async Q (both halves) + KV tile0 -> buf0, one group
    #pragma unroll
    for (int g = 0; g < 2; g++) {
        int s = tid + g * 256, r = s >> 2, c8 = (s & 3) * 8;
        size_t src = base + (size_t)(qbase + r) * 256 + c8;
        CP_ASYNC16(sb + ASM_QH + (r * 40 + c8) * 2, Qh_g + src);
        CP_ASYNC16(sb + ASM_QL + (r * 40 + c8) * 2, Ql_g + src);
    }
    {
        int r = tid >> 2, c8 = (tid & 3) * 8;
        size_t src = base + (size_t)r * 256 + c8;
        CP_ASYNC16(sb + ASM_KV(0) +     0 + (r * 40 + c8) * 2, Kh_g + src);
        CP_ASYNC16(sb + ASM_KV(0) +  5120 + (r * 40 + c8) * 2, Kl_g + src);
        CP_ASYNC16(sb + ASM_KV(0) + 10240 + (r * 40 + c8) * 2, Vh_g + src);
        CP_ASYNC16(sb + ASM_KV(0) + 15360 + (r * 40 + c8) * 2, Vl_g + src);
    }
    CP_COMMIT();

    uint32_t qh[2][4], ql[2][4];
    float o[4][4] = {};
    float mrow[2] = {-1e30f, -1e30f};
    float lrow[2] = {0.0f, 0.0f};

    for (int jt = 0; jt < ntiles; jt++) {
        __syncthreads();   // all warps done reading buf[(jt+1)&1] (tile jt-1)
        if (jt + 1 < ntiles) {
            const uint32_t kv = sb + ASM_KV((jt + 1) & 1);
            int r = tid >> 2, c8 = (tid & 3) * 8;
            size_t src = base + (size_t)((jt + 1) * 64 + r) * 256 + c8;
            CP_ASYNC16(kv +     0 + (r * 40 + c8) * 2, Kh_g + src);
            CP_ASYNC16(kv +  5120 + (r * 40 + c8) * 2, Kl_g + src);
            CP_ASYNC16(kv + 10240 + (r * 40 + c8) * 2, Vh_g + src);
            CP_ASYNC16(kv + 15360 + (r * 40 + c8) * 2, Vl_g + src);
            CP_COMMIT();
            CP_WAIT1();    // tile jt (and Q on jt==0) landed
        } else {
            CP_WAIT0();
        }
        __syncthreads();

        if (jt == 0) {     // load resident Q fragments once
            const int arow = lane & 15;
            const int aco  = ((lane >> 4) << 3);
            #pragma unroll
            for (int ks = 0; ks < 2; ks++) {
                LDSM_X4(qh[ks], sb + ASM_QH + ((wid * 16 + arow) * 40 + ks * 16 + aco) * 2);
                LDSM_X4(ql[ks], sb + ASM_QL + ((wid * 16 + arow) * 40 + ks * 16 + aco) * 2);
            }
        }

        // skip warps fully masked by causality
        if (jt * 64 > qbase + wid * 16 + 15) continue;

        const uint32_t kv = sb + ASM_KV(jt & 1);

        // ---- S = Q @ K^T (3-pass split) ----
        float s[8][4] = {};
        #pragma unroll
        for (int ks = 0; ks < 2; ks++) {
            uint32_t kh[8][2], kl[8][2];
            const int brow = lane & 7;
            const int bcol = ks * 16 + (((lane >> 3) & 1) << 3);
            #pragma unroll
            for (int j = 0; j < 8; j++) {
                LDSM_X2(kh[j], kv +        ((j * 8 + brow) * 40 + bcol) * 2);
                LDSM_X2(kl[j], kv + 5120 + ((j * 8 + brow) * 40 + bcol) * 2);
            }
            #pragma unroll
            for (int j = 0; j < 8; j++) {
                MMA16816(s[j], qh[ks], kh[j]);
                MMA16816(s[j], qh[ks], kl[j]);
                MMA16816(s[j], ql[ks], kh[j]);
            }
        }

        // ---- causal mask (diagonal region only) ----
        if (jt >= 2 * tq) {
            const int row0 = qbase + wid * 16 + (lane >> 2);
            #pragma unroll
            for (int j = 0; j < 8; j++) {
                int col = jt * 64 + j * 8 + (lane & 3) * 2;
                if (col     > row0)     s[j][0] = -1e30f;
                if (col + 1 > row0)     s[j][1] = -1e30f;
                if (col     > row0 + 8) s[j][2] = -1e30f;
                if (col + 1 > row0 + 8) s[j][3] = -1e30f;
            }
        }

        // ---- online softmax ----
        #pragma unroll
        for (int hf = 0; hf < 2; hf++) {
            float mt = -1e30f;
            #pragma unroll
            for (int j = 0; j < 8; j++)
                mt = fmaxf(mt, fmaxf(s[j][2 * hf], s[j][2 * hf + 1]));
            mt = fmaxf(mt, __shfl_xor_sync(0xffffffffu, mt, 1));
            mt = fmaxf(mt, __shfl_xor_sync(0xffffffffu, mt, 2));
            float mnew  = fmaxf(mrow[hf], mt);
            float alpha = __expf(mrow[hf] - mnew);
            float ls = 0.0f;
            #pragma unroll
            for (int j = 0; j < 8; j++) {
                s[j][2 * hf]     = __expf(s[j][2 * hf]     - mnew);
                s[j][2 * hf + 1] = __expf(s[j][2 * hf + 1] - mnew);
                ls += s[j][2 * hf] + s[j][2 * hf + 1];
            }
            ls += __shfl_xor_sync(0xffffffffu, ls, 1);
            ls += __shfl_xor_sync(0xffffffffu, ls, 2);
            mrow[hf] = mnew;
            lrow[hf] = lrow[hf] * alpha + ls;
            #pragma unroll
            for (int j = 0; j < 4; j++) {
                o[j][2 * hf]     *= alpha;
                o[j][2 * hf + 1] *= alpha;
            }
        }

        // ---- O += P @ V (3-pass split; P from registers) ----
        #pragma unroll
        for (int t = 0; t < 4; t++) {
            uint32_t ph[4], pl[4];
            split_pack(s[2 * t][0],     s[2 * t][1],     ph[0], pl[0]);
            split_pack(s[2 * t][2],     s[2 * t][3],     ph[1], pl[1]);
            split_pack(s[2 * t + 1][0], s[2 * t + 1][1], ph[2], pl[2]);
            split_pack(s[2 * t + 1][2], s[2 * t + 1][3], ph[3], pl[3]);

            uint32_t vh[4][2], vl[4][2];
            const int vrow = t * 16 + (lane & 15);
            #pragma unroll
            for (int j = 0; j < 4; j++) {
                LDSM_X2_T(vh[j], kv + 10240 + (vrow * 40 + j * 8) * 2);
                LDSM_X2_T(vl[j], kv + 15360 + (vrow * 40 + j * 8) * 2);
            }
            #pragma unroll
            for (int j = 0; j < 4; j++) {
                MMA16816(o[j], ph, vh[j]);
                MMA16816(o[j], ph, vl[j]);
                MMA16816(o[j], pl, vh[j]);
            }
        }
    }

    // ---- normalize + store ----
    const float inv0 = 1.0f / lrow[0];
    const float inv1 = 1.0f / lrow[1];
    const int row = qbase + wid * 16 + (lane >> 2);
    #pragma unroll
    for (int j = 0; j < 4; j++) {
        int col = j * 8 + (lane & 3) * 2;
        float2 o0 = make_float2(o[j][0] * inv0, o[j][1] * inv0);
        *(float2*)(Ob + (size_t)row * 256 + col) = o0;
        float2 o1 = make_float2(o[j][2] * inv1, o[j][3] * inv1);
        *(float2*)(Ob + (size_t)(row + 8) * 256 + col) = o1;
    }
}

// ---------------------------------------------------------------------------
extern "C" void kernel_launch(void* const* d_in, const int* in_sizes, int n_in,
                              void* d_out, int out_size)
{
    const float* query = (const float*)d_in[0];
    const float* key   = (const float*)d_in[1];
    const float* value = (const float*)d_in[2];
    const float* Wq    = (const float*)d_in[3];
    const float* bq    = (const float*)d_in[4];
    const float* Wk    = (const float*)d_in[5];
    const float* bk    = (const float*)d_in[6];
    const float* Wv    = (const float*)d_in[7];
    const float* bv    = (const float*)d_in[8];
    const float* Wo    = (const float*)d_in[9];
    const float* bo    = (const float*)d_in[10];
    float* out = (float*)d_out;

    float* AO;
    __nv_bfloat16 *Qh, *Ql, *Kh, *Kl, *Vh, *Vl, *Wh, *Wl;
    cudaGetSymbolAddress((void**)&AO, g_AO);
    cudaGetSymbolAddress((void**)&Qh, g_Qh);
    cudaGetSymbolAddress((void**)&Ql, g_Ql);
    cudaGetSymbolAddress((void**)&Kh, g_Kh);
    cudaGetSymbolAddress((void**)&Kl, g_Kl);
    cudaGetSymbolAddress((void**)&Vh, g_Vh);
    cudaGetSymbolAddress((void**)&Vl, g_Vl);
    cudaGetSymbolAddress((void**)&Wh, g_Wh);
    cudaGetSymbolAddress((void**)&Wl, g_Wl);

    cudaFuncSetAttribute(gemm_qkv_kernel,
                         cudaFuncAttributeMaxDynamicSharedMemorySize, GSM_TOTAL);
    cudaFuncSetAttribute(gemm_out_kernel,
                         cudaFuncAttributeMaxDynamicSharedMemorySize, GSM_TOTAL);
    cudaFuncSetAttribute(attn_mma_kernel,
                         cudaFuncAttributeMaxDynamicSharedMemorySize, ASM_TOTAL);

    convert_w_kernel<<<dim3(256, 4), 256>>>(Wq, Wk, Wv, Wo, Wh, Wl);

    gemm_qkv_kernel<<<dim3(2, 128, 3), 256, GSM_TOTAL>>>(
        query, key, value, Wh, Wl, bq, bk, bv, Qh, Ql, Kh, Kl, Vh, Vl);

    attn_mma_kernel<<<dim3(16, 64), 256, ASM_TOTAL>>>(Qh, Ql, Kh, Kl, Vh, Vl, AO);

    gemm_out_kernel<<<dim3(2, 128), 256, GSM_TOTAL>>>(
        AO, Wh + 3 * 65536, Wl + 3 * 65536, bo, out);
}

// round 9
// speedup vs baseline: 3.3538x; 1.0096x over previous
#include <cuda_runtime.h>
#include <cuda_bf16.h>
#include <cstdint>

// Problem constants: B=8, N=2048, D=256, HEAD=8, ATT=32
#define NROWS 16384   // B*N
#define DMODEL 256

// Scratch (allocation-free rule: device globals)
__device__ __align__(16) float g_AO[NROWS * DMODEL];
__device__ __align__(16) __nv_bfloat16 g_Qh[NROWS * DMODEL];
__device__ __align__(16) __nv_bfloat16 g_Ql[NROWS * DMODEL];
__device__ __align__(16) __nv_bfloat16 g_Kh[NROWS * DMODEL];
__device__ __align__(16) __nv_bfloat16 g_Kl[NROWS * DMODEL];
__device__ __align__(16) __nv_bfloat16 g_Vh[NROWS * DMODEL];
__device__ __align__(16) __nv_bfloat16 g_Vl[NROWS * DMODEL];
__device__ __align__(16) __nv_bfloat16 g_Wh[4 * DMODEL * DMODEL];
__device__ __align__(16) __nv_bfloat16 g_Wl[4 * DMODEL * DMODEL];

// ========================= PTX helpers (compute_100-safe) ==================
__device__ __forceinline__ uint32_t smem_u32(const void* p) {
    uint32_t a;
    asm("{ .reg .u64 t; cvta.to.shared.u64 t, %1; cvt.u32.u64 %0, t; }"
        : "=r"(a) : "l"(p));
    return a;
}

#define LDSM_X4(r, addr) \
    asm volatile("ldmatrix.sync.aligned.m8n8.x4.shared.b16 {%0,%1,%2,%3}, [%4];" \
        : "=r"((r)[0]), "=r"((r)[1]), "=r"((r)[2]), "=r"((r)[3]) : "r"(addr))

#define LDSM_X4_T(r, addr) \
    asm volatile("ldmatrix.sync.aligned.m8n8.x4.trans.shared.b16 {%0,%1,%2,%3}, [%4];" \
        : "=r"((r)[0]), "=r"((r)[1]), "=r"((r)[2]), "=r"((r)[3]) : "r"(addr))

#define MMA16816(d, a, b) \
    asm volatile("mma.sync.aligned.m16n8k16.row.col.f32.bf16.bf16.f32 " \
        "{%0,%1,%2,%3}, {%4,%5,%6,%7}, {%8,%9}, {%0,%1,%2,%3};" \
        : "+f"((d)[0]), "+f"((d)[1]), "+f"((d)[2]), "+f"((d)[3]) \
        : "r"((a)[0]), "r"((a)[1]), "r"((a)[2]), "r"((a)[3]), \
          "r"((b)[0]), "r"((b)[1]))

#define CP_ASYNC16(dst, src) \
    asm volatile("cp.async.cg.shared.global [%0], [%1], 16;" \
        :: "r"(dst), "l"(src) : "memory")
#define CP_COMMIT() asm volatile("cp.async.commit_group;" ::: "memory")
#define CP_WAIT0()  asm volatile("cp.async.wait_group 0;" ::: "memory")
#define CP_WAIT1()  asm volatile("cp.async.wait_group 1;" ::: "memory")

__device__ __forceinline__ void split_pack(float x, float y, uint32_t& hp, uint32_t& lp) {
    __nv_bfloat16 hx = __float2bfloat16(x);
    __nv_bfloat16 hy = __float2bfloat16(y);
    __nv_bfloat16 lx = __float2bfloat16(x - __bfloat162float(hx));
    __nv_bfloat16 ly = __float2bfloat16(y - __bfloat162float(hy));
    hp = ((uint32_t)__bfloat16_as_ushort(hy) << 16) | __bfloat16_as_ushort(hx);
    lp = ((uint32_t)__bfloat16_as_ushort(ly) << 16) | __bfloat16_as_ushort(lx);
}

// ============================ weight split =================================
__global__ void convert_w_kernel(const float* __restrict__ W0, const float* __restrict__ W1,
                                 const float* __restrict__ W2, const float* __restrict__ W3,
                                 __nv_bfloat16* __restrict__ hi, __nv_bfloat16* __restrict__ lo)
{
    int i = blockIdx.x * 256 + threadIdx.x;
    int m = blockIdx.y;
    const float* src = (m == 0) ? W0 : (m == 1) ? W1 : (m == 2) ? W2 : W3;
    float x = src[i];
    __nv_bfloat16 h = __float2bfloat16(x);
    float r = x - __bfloat162float(h);
    hi[m * 65536 + i] = h;
    lo[m * 65536 + i] = __float2bfloat16(r);
}

// ==================== pipelined mma.sync bf16-split GEMM ===================
// Dynamic smem (row stride 40 bf16 = 80 B):
//   sAh @ 0, sAl @ 10240, W buf b: Wh @ 20480+b*20480, Wl @ +10240.  Total 61440.
#define GSM_AH   0
#define GSM_AL   10240
#define GSM_WB(b) (20480 + (b) * 20480)
#define GSM_TOTAL 61440

// Mainloop shared by both GEMM kernels. acc[4][4][4] per thread.
// Combined hi/lo W fragment: one ldmatrix.x4 — lanes 0-15 address Wh rows,
// lanes 16-31 address Wl rows (regs {0,1}=Wh frag, {2,3}=Wl frag).
#define GEMM_MAINLOOP(APTR, WHI, WLO)                                              \
    float2 pa[8];                                                                  \
    _Pragma("unroll")                                                              \
    for (int g = 0; g < 2; g++) {                                                  \
        int s = tid + g * 256, r = s >> 2, c8 = (s & 3) * 8;                       \
        CP_ASYNC16(sb + GSM_WB(0) + (r * 40 + c8) * 2,                             \
                   (WHI) + (size_t)(n0 + r) * 256 + c8);                           \
        CP_ASYNC16(sb + GSM_WB(0) + 10240 + (r * 40 + c8) * 2,                     \
                   (WLO) + (size_t)(n0 + r) * 256 + c8);                           \
    }                                                                              \
    CP_COMMIT();                                                                   \
    _Pragma("unroll")                                                              \
    for (int it = 0; it < 8; it++) {                                               \
        int idx = tid + it * 256, r = idx >> 4, c2 = (idx & 15) * 2;               \
        pa[it] = *(const float2*)((APTR) + (size_t)(m0 + r) * 256 + c2);           \
    }                                                                              \
    const uint32_t wfoff = (((lane >> 4) & 1) ? 10240u : 0u)                       \
        + ((wn + (lane & 7)) * 40 + (((lane >> 3) & 1) << 3)) * 2;                 \
    for (int chunk = 0; chunk < 8; chunk++) {                                      \
        const int kk = chunk * 32;                                                 \
        const uint32_t wb = sb + GSM_WB(chunk & 1);                                \
        __syncthreads();                                                           \
        _Pragma("unroll")                                                          \
        for (int it = 0; it < 8; it++) {                                           \
            int idx = tid + it * 256, r = idx >> 4, c2 = (idx & 15) * 2;           \
            uint32_t hp, lp;                                                       \
            split_pack(pa[it].x, pa[it].y, hp, lp);                                \
            *(uint32_t*)(smem + GSM_AH + (r * 40 + c2) * 2) = hp;                  \
            *(uint32_t*)(smem + GSM_AL + (r * 40 + c2) * 2) = lp;                  \
        }                                                                          \
        if (chunk < 7) {                                                           \
            const uint32_t wn2 = sb + GSM_WB((chunk + 1) & 1);                     \
            _Pragma("unroll")                                                      \
            for (int g = 0; g < 2; g++) {                                          \
                int s = tid + g * 256, r = s >> 2, c8 = (s & 3) * 8;               \
                CP_ASYNC16(wn2 + (r * 40 + c8) * 2,                                \
                           (WHI) + (size_t)(n0 + r) * 256 + kk + 32 + c8);         \
                CP_ASYNC16(wn2 + 10240 + (r * 40 + c8) * 2,                        \
                           (WLO) + (size_t)(n0 + r) * 256 + kk + 32 + c8);         \
            }                                                                      \
            CP_COMMIT();                                                           \
            _Pragma("unroll")                                                      \
            for (int it = 0; it < 8; it++) {                                       \
                int idx = tid + it * 256, r = idx >> 4, c2 = (idx & 15) * 2;       \
                pa[it] = *(const float2*)((APTR) + (size_t)(m0 + r) * 256 + kk + 32 + c2); \
            }                                                                      \
            CP_WAIT1();                                                            \
        } else {                                                                   \
            CP_WAIT0();                                                            \
        }                                                                          \
        __syncthreads();                                                           \
        _Pragma("unroll")                                                          \
        for (int ks = 0; ks < 32; ks += 16) {                                      \
            uint32_t ah[4][4], al[4][4];                                           \
            const int arow = lane & 15;                                            \
            const int acol = ks + ((lane >> 4) << 3);                              \
            _Pragma("unroll")                                                      \
            for (int i = 0; i < 4; i++) {                                          \
                LDSM_X4(ah[i], sb + GSM_AH + ((wm + i * 16 + arow) * 40 + acol) * 2); \
                LDSM_X4(al[i], sb + GSM_AL + ((wm + i * 16 + arow) * 40 + acol) * 2); \
            }                                                                      \
            _Pragma("unroll")                                                      \
            for (int j = 0; j < 4; j++) {                                          \
                uint32_t w4[4];                                                    \
                LDSM_X4(w4, wb + wfoff + (j * 8 * 40 + ks) * 2);                   \
                _Pragma("unroll")                                                  \
                for (int i = 0; i < 4; i++) {                                      \
                    MMA16816(acc[i][j], ah[i], (&w4[0]));                          \
                    MMA16816(acc[i][j], ah[i], (&w4[2]));                          \
                    MMA16816(acc[i][j], al[i], (&w4[0]));                          \
                }                                                                  \
            }                                                                      \
        }                                                                          \
    }

// --- fused QKV projection: writes bf16 hi/lo outputs (Q pre-scaled) ---
__global__ __launch_bounds__(256, 2)
void gemm_qkv_kernel(const float* __restrict__ query, const float* __restrict__ key,
                     const float* __restrict__ value,
                     const __nv_bfloat16* __restrict__ Wh_all,
                     const __nv_bfloat16* __restrict__ Wl_all,
                     const float* __restrict__ bq, const float* __restrict__ bk,
                     const float* __restrict__ bv,
                     __nv_bfloat16* __restrict__ Qh, __nv_bfloat16* __restrict__ Ql,
                     __nv_bfloat16* __restrict__ Kh, __nv_bfloat16* __restrict__ Kl,
                     __nv_bfloat16* __restrict__ Vh, __nv_bfloat16* __restrict__ Vl)
{
    extern __shared__ char smem[];
    const uint32_t sb = smem_u32(smem);
    const int tid  = threadIdx.x;
    const int wid  = tid >> 5;
    const int lane = tid & 31;
    const int m0 = blockIdx.y * 128;
    const int n0 = blockIdx.x * 128;
    const int wm = (wid >> 2) * 64;
    const int wn = (wid & 3) * 32;
    const int z = blockIdx.z;

    const float* A   = (z == 0) ? query : (z == 1) ? key : value;
    const float* bia = (z == 0) ? bq    : (z == 1) ? bk  : bv;
    __nv_bfloat16* Oh = (z == 0) ? Qh : (z == 1) ? Kh : Vh;
    __nv_bfloat16* Ol = (z == 0) ? Ql : (z == 1) ? Kl : Vl;
    const __nv_bfloat16* Whi = Wh_all + (size_t)z * 65536;
    const __nv_bfloat16* Wlo = Wl_all + (size_t)z * 65536;
    const float oscale = (z == 0) ? 0.17677669529663687f : 1.0f;

    float acc[4][4][4] = {};
    GEMM_MAINLOOP(A, Whi, Wlo)

    const int r0 = lane >> 2;
    const int cp = (lane & 3) * 2;
    #pragma unroll
    for (int i = 0; i < 4; i++)
        #pragma unroll
        for (int j = 0; j < 4; j++) {
            int col = n0 + wn + j * 8 + cp;
            float2 bb = *(const float2*)(bia + col);
            int row = m0 + wm + i * 16 + r0;
            uint32_t hp, lp;
            split_pack((acc[i][j][0] + bb.x) * oscale,
                       (acc[i][j][1] + bb.y) * oscale, hp, lp);
            *(uint32_t*)(Oh + (size_t)row * 256 + col) = hp;
            *(uint32_t*)(Ol + (size_t)row * 256 + col) = lp;
            split_pack((acc[i][j][2] + bb.x) * oscale,
                       (acc[i][j][3] + bb.y) * oscale, hp, lp);
            *(uint32_t*)(Oh + (size_t)(row + 8) * 256 + col) = hp;
            *(uint32_t*)(Ol + (size_t)(row + 8) * 256 + col) = lp;
        }
}

// --- output projection: fp32 epilogue ---
__global__ __launch_bounds__(256, 2)
void gemm_out_kernel(const float* __restrict__ A,
                     const __nv_bfloat16* __restrict__ Whi,
                     const __nv_bfloat16* __restrict__ Wlo,
                     const float* __restrict__ bias,
                     float* __restrict__ C)
{
    extern __shared__ char smem[];
    const uint32_t sb = smem_u32(smem);
    const int tid  = threadIdx.x;
    const int wid  = tid >> 5;
    const int lane = tid & 31;
    const int m0 = blockIdx.y * 128;
    const int n0 = blockIdx.x * 128;
    const int wm = (wid >> 2) * 64;
    const int wn = (wid & 3) * 32;

    float acc[4][4][4] = {};
    GEMM_MAINLOOP(A, Whi, Wlo)

    const int r0 = lane >> 2;
    const int cp = (lane & 3) * 2;
    #pragma unroll
    for (int i = 0; i < 4; i++)
        #pragma unroll
        for (int j = 0; j < 4; j++) {
            int col = n0 + wn + j * 8 + cp;
            float2 bb = *(const float2*)(bias + col);
            int row = m0 + wm + i * 16 + r0;
            float2 o0 = make_float2(acc[i][j][0] + bb.x, acc[i][j][1] + bb.y);
            *(float2*)(C + (size_t)row * 256 + col) = o0;
            float2 o1 = make_float2(acc[i][j][2] + bb.x, acc[i][j][3] + bb.y);
            *(float2*)(C + (size_t)(row + 8) * 256 + col) = o1;
        }
}

// ====================== mma.sync flash attention ===========================
// Inputs pre-split bf16 hi/lo (Q pre-scaled). cp.async double-buffered KV.
// 128 q-rows/block, 8 warps, KV tile 64. Combined hi/lo ldmatrix.x4 for K & V.
// Dynamic smem: Qh @ 0, Ql @ 10240; KV buf b @ 20480+b*20480:
//   {Kh +0, Kl +5120, Vh +10240, Vl +15360}. Total 61440.
#define ASM_QH 0
#define ASM_QL 10240
#define ASM_KV(b) (20480 + (b) * 20480)
#define ASM_TOTAL 61440

__global__ __launch_bounds__(256, 2)
void attn_mma_kernel(const __nv_bfloat16* __restrict__ Qh_g,
                     const __nv_bfloat16* __restrict__ Ql_g,
                     const __nv_bfloat16* __restrict__ Kh_g,
                     const __nv_bfloat16* __restrict__ Kl_g,
                     const __nv_bfloat16* __restrict__ Vh_g,
                     const __nv_bfloat16* __restrict__ Vl_g,
                     float* __restrict__ Og)
{
    extern __shared__ char smem[];
    const uint32_t sb = smem_u32(smem);
    const int tid  = threadIdx.x;
    const int wid  = tid >> 5;
    const int lane = tid & 31;
    const int tq = (int)gridDim.x - 1 - (int)blockIdx.x;   // long blocks first
    const int hb = blockIdx.y;
    const int h  = hb & 7;
    const int bb = hb >> 3;
    const size_t base = (size_t)bb * 2048 * 256 + (size_t)h * 32;
    const int qbase = tq * 128;
    float* Ob = Og + base;

    const int ntiles = 2 * tq + 2;

    // prologue: cp.async Q (both halves) + KV tile0 -> buf0, one group
    #pragma unroll
    for (int g = 0; g < 2; g++) {
        int s = tid + g * 256, r = s >> 2, c8 = (s & 3) * 8;
        size_t src = base + (size_t)(qbase + r) * 256 + c8;
        CP_ASYNC16(sb + ASM_QH + (r * 40 + c8) * 2, Qh_g + src);
        CP_ASYNC16(sb + ASM_QL + (r * 40 + c8) * 2, Ql_g + src);
    }
    {
        int r = tid >> 2, c8 = (tid & 3) * 8;
        size_t src = base + (size_t)r * 256 + c8;
        CP_ASYNC16(sb + ASM_KV(0) +     0 + (r * 40 + c8) * 2, Kh_g + src);
        CP_ASYNC16(sb + ASM_KV(0) +  5120 + (r * 40 + c8) * 2, Kl_g + src);
        CP_ASYNC16(sb + ASM_KV(0) + 10240 + (r * 40 + c8) * 2, Vh_g + src);
        CP_ASYNC16(sb + ASM_KV(0) + 15360 + (r * 40 + c8) * 2, Vl_g + src);
    }
    CP_COMMIT();

    uint32_t qh[2][4], ql[2][4];
    float o[4][4] = {};
    float mrow[2] = {-1e30f, -1e30f};
    float lrow[2] = {0.0f, 0.0f};

    // per-lane combined-fragment offsets (hi: lanes 0-15, lo: lanes 16-31)
    const uint32_t kfoff = (((lane >> 4) & 1) ? 5120u : 0u)
        + ((lane & 7) * 40) * 2 + (((lane >> 3) & 1) << 4);
    const uint32_t vfoff = 10240u + (((lane >> 4) & 1) ? 5120u : 0u)
        + ((lane & 15) * 40) * 2;

    for (int jt = 0; jt < ntiles; jt++) {
        __syncthreads();   // all warps done reading buf[(jt+1)&1] (tile jt-1)
        if (jt + 1 < ntiles) {
            const uint32_t kv = sb + ASM_KV((jt + 1) & 1);
            int r = tid >> 2, c8 = (tid & 3) * 8;
            size_t src = base + (size_t)((jt + 1) * 64 + r) * 256 + c8;
            CP_ASYNC16(kv +     0 + (r * 40 + c8) * 2, Kh_g + src);
            CP_ASYNC16(kv +  5120 + (r * 40 + c8) * 2, Kl_g + src);
            CP_ASYNC16(kv + 10240 + (r * 40 + c8) * 2, Vh_g + src);
            CP_ASYNC16(kv + 15360 + (r * 40 + c8) * 2, Vl_g + src);
            CP_COMMIT();
            CP_WAIT1();    // tile jt (and Q on jt==0) landed
        } else {
            CP_WAIT0();
        }
        __syncthreads();

        if (jt == 0) {     // load resident Q fragments once
            const int arow = lane & 15;
            const int aco  = ((lane >> 4) << 3);
            #pragma unroll
            for (int ks = 0; ks < 2; ks++) {
                LDSM_X4(qh[ks], sb + ASM_QH + ((wid * 16 + arow) * 40 + ks * 16 + aco) * 2);
                LDSM_X4(ql[ks], sb + ASM_QL + ((wid * 16 + arow) * 40 + ks * 16 + aco) * 2);
            }
        }

        // skip warps fully masked by causality
        if (jt * 64 > qbase + wid * 16 + 15) continue;

        const uint32_t kv = sb + ASM_KV(jt & 1);

        // ---- S = Q @ K^T (3-pass split; combined hi/lo K fragments) ----
        float s[8][4] = {};
        #pragma unroll
        for (int ks = 0; ks < 2; ks++) {
            #pragma unroll
            for (int j = 0; j < 8; j++) {
                uint32_t k4[4];
                LDSM_X4(k4, kv + kfoff + (j * 8 * 40 + ks * 16) * 2);
                MMA16816(s[j], qh[ks], (&k4[0]));
                MMA16816(s[j], qh[ks], (&k4[2]));
                MMA16816(s[j], ql[ks], (&k4[0]));
            }
        }

        // ---- causal mask (diagonal region only) ----
        if (jt >= 2 * tq) {
            const int row0 = qbase + wid * 16 + (lane >> 2);
            #pragma unroll
            for (int j = 0; j < 8; j++) {
                int col = jt * 64 + j * 8 + (lane & 3) * 2;
                if (col     > row0)     s[j][0] = -1e30f;
                if (col + 1 > row0)     s[j][1] = -1e30f;
                if (col     > row0 + 8) s[j][2] = -1e30f;
                if (col + 1 > row0 + 8) s[j][3] = -1e30f;
            }
        }

        // ---- online softmax ----
        #pragma unroll
        for (int hf = 0; hf < 2; hf++) {
            float mt = -1e30f;
            #pragma unroll
            for (int j = 0; j < 8; j++)
                mt = fmaxf(mt, fmaxf(s[j][2 * hf], s[j][2 * hf + 1]));
            mt = fmaxf(mt, __shfl_xor_sync(0xffffffffu, mt, 1));
            mt = fmaxf(mt, __shfl_xor_sync(0xffffffffu, mt, 2));
            float mnew  = fmaxf(mrow[hf], mt);
            float alpha = __expf(mrow[hf] - mnew);
            float ls = 0.0f;
            #pragma unroll
            for (int j = 0; j < 8; j++) {
                s[j][2 * hf]     = __expf(s[j][2 * hf]     - mnew);
                s[j][2 * hf + 1] = __expf(s[j][2 * hf + 1] - mnew);
                ls += s[j][2 * hf] + s[j][2 * hf + 1];
            }
            ls += __shfl_xor_sync(0xffffffffu, ls, 1);
            ls += __shfl_xor_sync(0xffffffffu, ls, 2);
            mrow[hf] = mnew;
            lrow[hf] = lrow[hf] * alpha + ls;
            #pragma unroll
            for (int j = 0; j < 4; j++) {
                o[j][2 * hf]     *= alpha;
                o[j][2 * hf + 1] *= alpha;
            }
        }

        // ---- O += P @ V (3-pass split; P from regs, combined hi/lo V) ----
        #pragma unroll
        for (int t = 0; t < 4; t++) {
            uint32_t ph[4], pl[4];
            split_pack(s[2 * t][0],     s[2 * t][1],     ph[0], pl[0]);
            split_pack(s[2 * t][2],     s[2 * t][3],     ph[1], pl[1]);
            split_pack(s[2 * t + 1][0], s[2 * t + 1][1], ph[2], pl[2]);
            split_pack(s[2 * t + 1][2], s[2 * t + 1][3], ph[3], pl[3]);

            #pragma unroll
            for (int j = 0; j < 4; j++) {
                uint32_t v4[4];
                LDSM_X4_T(v4, kv + vfoff + (t * 16 * 40 + j * 8) * 2);
                MMA16816(o[j], ph, (&v4[0]));
                MMA16816(o[j], ph, (&v4[2]));
                MMA16816(o[j], pl, (&v4[0]));
            }
        }
    }

    // ---- normalize + store ----
    const float inv0 = 1.0f / lrow[0];
    const float inv1 = 1.0f / lrow[1];
    const int row = qbase + wid * 16 + (lane >> 2);
    #pragma unroll
    for (int j = 0; j < 4; j++) {
        int col = j * 8 + (lane & 3) * 2;
        float2 o0 = make_float2(o[j][0] * inv0, o[j][1] * inv0);
        *(float2*)(Ob + (size_t)row * 256 + col) = o0;
        float2 o1 = make_float2(o[j][2] * inv1, o[j][3] * inv1);
        *(float2*)(Ob + (size_t)(row + 8) * 256 + col) = o1;
    }
}

// ---------------------------------------------------------------------------
extern "C" void kernel_launch(void* const* d_in, const int* in_sizes, int n_in,
                              void* d_out, int out_size)
{
    const float* query = (const float*)d_in[0];
    const float* key   = (const float*)d_in[1];
    const float* value = (const float*)d_in[2];
    const float* Wq    = (const float*)d_in[3];
    const float* bq    = (const float*)d_in[4];
    const float* Wk    = (const float*)d_in[5];
    const float* bk    = (const float*)d_in[6];
    const float* Wv    = (const float*)d_in[7];
    const float* bv    = (const float*)d_in[8];
    const float* Wo    = (const float*)d_in[9];
    const float* bo    = (const float*)d_in[10];
    float* out = (float*)d_out;

    float* AO;
    __nv_bfloat16 *Qh, *Ql, *Kh, *Kl, *Vh, *Vl, *Wh, *Wl;
    cudaGetSymbolAddress((void**)&AO, g_AO);
    cudaGetSymbolAddress((void**)&Qh, g_Qh);
    cudaGetSymbolAddress((void**)&Ql, g_Ql);
    cudaGetSymbolAddress((void**)&Kh, g_Kh);
    cudaGetSymbolAddress((void**)&Kl, g_Kl);
    cudaGetSymbolAddress((void**)&Vh, g_Vh);
    cudaGetSymbolAddress((void**)&Vl, g_Vl);
    cudaGetSymbolAddress((void**)&Wh, g_Wh);
    cudaGetSymbolAddress((void**)&Wl, g_Wl);

    cudaFuncSetAttribute(gemm_qkv_kernel,
                         cudaFuncAttributeMaxDynamicSharedMemorySize, GSM_TOTAL);
    cudaFuncSetAttribute(gemm_out_kernel,
                         cudaFuncAttributeMaxDynamicSharedMemorySize, GSM_TOTAL);
    cudaFuncSetAttribute(attn_mma_kernel,
                         cudaFuncAttributeMaxDynamicSharedMemorySize, ASM_TOTAL);

    convert_w_kernel<<<dim3(256, 4), 256>>>(Wq, Wk, Wv, Wo, Wh, Wl);

    gemm_qkv_kernel<<<dim3(2, 128, 3), 256, GSM_TOTAL>>>(
        query, key, value, Wh, Wl, bq, bk, bv, Qh, Ql, Kh, Kl, Vh, Vl);

    attn_mma_kernel<<<dim3(16, 64), 256, ASM_TOTAL>>>(Qh, Ql, Kh, Kl, Vh, Vl, AO);

    gemm_out_kernel<<<dim3(2, 128), 256, GSM_TOTAL>>>(
        AO, Wh + 3 * 65536, Wl + 3 * 65536, bo, out);
}

// round 10
// speedup vs baseline: 4.9546x; 1.4773x over previous
#include <cuda_runtime.h>
#include <cuda_fp16.h>
#include <cstdint>

// Problem constants: B=8, N=2048, D=256, HEAD=8, ATT=32
#define NROWS 16384   // B*N
#define DMODEL 256

// Scratch (allocation-free rule: device globals)
__device__ __align__(16) float  g_AO[NROWS * DMODEL];
__device__ __align__(16) __half g_Qh[NROWS * DMODEL];   // fp16, pre-scaled by 1/sqrt(32)
__device__ __align__(16) __half g_Kh[NROWS * DMODEL];   // fp16
__device__ __align__(16) __half g_Vh[NROWS * DMODEL];   // fp16 hi
__device__ __align__(16) __half g_Vl[NROWS * DMODEL];   // fp16 lo (residual)
__device__ __align__(16) __half g_Wh[4 * DMODEL * DMODEL];
__device__ __align__(16) __half g_Wl[4 * DMODEL * DMODEL];

// ========================= PTX helpers (compute_100-safe) ==================
__device__ __forceinline__ uint32_t smem_u32(const void* p) {
    uint32_t a;
    asm("{ .reg .u64 t; cvta.to.shared.u64 t, %1; cvt.u32.u64 %0, t; }"
        : "=r"(a) : "l"(p));
    return a;
}

#define LDSM_X4(r, addr) \
    asm volatile("ldmatrix.sync.aligned.m8n8.x4.shared.b16 {%0,%1,%2,%3}, [%4];" \
        : "=r"((r)[0]), "=r"((r)[1]), "=r"((r)[2]), "=r"((r)[3]) : "r"(addr))

#define LDSM_X4_T(r, addr) \
    asm volatile("ldmatrix.sync.aligned.m8n8.x4.trans.shared.b16 {%0,%1,%2,%3}, [%4];" \
        : "=r"((r)[0]), "=r"((r)[1]), "=r"((r)[2]), "=r"((r)[3]) : "r"(addr))

#define MMA16816(d, a, b) \
    asm volatile("mma.sync.aligned.m16n8k16.row.col.f32.f16.f16.f32 " \
        "{%0,%1,%2,%3}, {%4,%5,%6,%7}, {%8,%9}, {%0,%1,%2,%3};" \
        : "+f"((d)[0]), "+f"((d)[1]), "+f"((d)[2]), "+f"((d)[3]) \
        : "r"((a)[0]), "r"((a)[1]), "r"((a)[2]), "r"((a)[3]), \
          "r"((b)[0]), "r"((b)[1]))

#define CP_ASYNC16(dst, src) \
    asm volatile("cp.async.cg.shared.global [%0], [%1], 16;" \
        :: "r"(dst), "l"(src) : "memory")
#define CP_COMMIT() asm volatile("cp.async.commit_group;" ::: "memory")
#define CP_WAIT0()  asm volatile("cp.async.wait_group 0;" ::: "memory")
#define CP_WAIT1()  asm volatile("cp.async.wait_group 1;" ::: "memory")

__device__ __forceinline__ uint32_t pack_h(float x, float y) {
    __half2 h = __floats2half2_rn(x, y);
    return *reinterpret_cast<uint32_t*>(&h);
}
__device__ __forceinline__ void split_pack(float x, float y, uint32_t& hp, uint32_t& lp) {
    __half hx = __float2half_rn(x);
    __half hy = __float2half_rn(y);
    __half lx = __float2half_rn(x - __half2float(hx));
    __half ly = __float2half_rn(y - __half2float(hy));
    hp = ((uint32_t)__half_as_ushort(hy) << 16) | __half_as_ushort(hx);
    lp = ((uint32_t)__half_as_ushort(ly) << 16) | __half_as_ushort(lx);
}

// ============================ weight split =================================
__global__ void convert_w_kernel(const float* __restrict__ W0, const float* __restrict__ W1,
                                 const float* __restrict__ W2, const float* __restrict__ W3,
                                 __half* __restrict__ hi, __half* __restrict__ lo)
{
    int i = blockIdx.x * 256 + threadIdx.x;
    int m = blockIdx.y;
    const float* src = (m == 0) ? W0 : (m == 1) ? W1 : (m == 2) ? W2 : W3;
    float x = src[i];
    __half h = __float2half_rn(x);
    float r = x - __half2float(h);
    hi[m * 65536 + i] = h;
    lo[m * 65536 + i] = __float2half_rn(r);
}

// ==================== pipelined mma.sync fp16-split GEMM ===================
// Dynamic smem (row stride 40 halfs = 80 B):
//   sAh @ 0, sAl @ 10240, W buf b: Wh @ 20480+b*20480, Wl @ +10240.  Total 61440.
#define GSM_AH   0
#define GSM_AL   10240
#define GSM_WB(b) (20480 + (b) * 20480)
#define GSM_TOTAL 61440

// 3-pass fp16 split mainloop (internal error ~1e-6). acc[4][4][4] per thread.
#define GEMM_MAINLOOP(APTR, WHI, WLO)                                              \
    float2 pa[8];                                                                  \
    _Pragma("unroll")                                                              \
    for (int g = 0; g < 2; g++) {                                                  \
        int s = tid + g * 256, r = s >> 2, c8 = (s & 3) * 8;                       \
        CP_ASYNC16(sb + GSM_WB(0) + (r * 40 + c8) * 2,                             \
                   (WHI) + (size_t)(n0 + r) * 256 + c8);                           \
        CP_ASYNC16(sb + GSM_WB(0) + 10240 + (r * 40 + c8) * 2,                     \
                   (WLO) + (size_t)(n0 + r) * 256 + c8);                           \
    }                                                                              \
    CP_COMMIT();                                                                   \
    _Pragma("unroll")                                                              \
    for (int it = 0; it < 8; it++) {                                               \
        int idx = tid + it * 256, r = idx >> 4, c2 = (idx & 15) * 2;               \
        pa[it] = *(const float2*)((APTR) + (size_t)(m0 + r) * 256 + c2);           \
    }                                                                              \
    const uint32_t wfoff = (((lane >> 4) & 1) ? 10240u : 0u)                       \
        + ((wn + (lane & 7)) * 40 + (((lane >> 3) & 1) << 3)) * 2;                 \
    for (int chunk = 0; chunk < 8; chunk++) {                                      \
        const int kk = chunk * 32;                                                 \
        const uint32_t wb = sb + GSM_WB(chunk & 1);                                \
        __syncthreads();                                                           \
        _Pragma("unroll")                                                          \
        for (int it = 0; it < 8; it++) {                                           \
            int idx = tid + it * 256, r = idx >> 4, c2 = (idx & 15) * 2;           \
            uint32_t hp, lp;                                                       \
            split_pack(pa[it].x, pa[it].y, hp, lp);                                \
            *(uint32_t*)(smem + GSM_AH + (r * 40 + c2) * 2) = hp;                  \
            *(uint32_t*)(smem + GSM_AL + (r * 40 + c2) * 2) = lp;                  \
        }                                                                          \
        if (chunk < 7) {                                                           \
            const uint32_t wn2 = sb + GSM_WB((chunk + 1) & 1);                     \
            _Pragma("unroll")                                                      \
            for (int g = 0; g < 2; g++) {                                          \
                int s = tid + g * 256, r = s >> 2, c8 = (s & 3) * 8;               \
                CP_ASYNC16(wn2 + (r * 40 + c8) * 2,                                \
                           (WHI) + (size_t)(n0 + r) * 256 + kk + 32 + c8);         \
                CP_ASYNC16(wn2 + 10240 + (r * 40 + c8) * 2,                        \
                           (WLO) + (size_t)(n0 + r) * 256 + kk + 32 + c8);         \
            }                                                                      \
            CP_COMMIT();                                                           \
            _Pragma("unroll")                                                      \
            for (int it = 0; it < 8; it++) {                                       \
                int idx = tid + it * 256, r = idx >> 4, c2 = (idx & 15) * 2;       \
                pa[it] = *(const float2*)((APTR) + (size_t)(m0 + r) * 256 + kk + 32 + c2); \
            }                                                                      \
            CP_WAIT1();                                                            \
        } else {                                                                   \
            CP_WAIT0();                                                            \
        }                                                                          \
        __syncthreads();                                                           \
        _Pragma("unroll")                                                          \
        for (int ks = 0; ks < 32; ks += 16) {                                      \
            uint32_t ah[4][4], al[4][4];                                           \
            const int arow = lane & 15;                                            \
            const int acol = ks + ((lane >> 4) << 3);                              \
            _Pragma("unroll")                                                      \
            for (int i = 0; i < 4; i++) {                                          \
                LDSM_X4(ah[i], sb + GSM_AH + ((wm + i * 16 + arow) * 40 + acol) * 2); \
                LDSM_X4(al[i], sb + GSM_AL + ((wm + i * 16 + arow) * 40 + acol) * 2); \
            }                                                                      \
            _Pragma("unroll")                                                      \
            for (int j = 0; j < 4; j++) {                                          \
                uint32_t w4[4];                                                    \
                LDSM_X4(w4, wb + wfoff + (j * 8 * 40 + ks) * 2);                   \
                _Pragma("unroll")                                                  \
                for (int i = 0; i < 4; i++) {                                      \
                    MMA16816(acc[i][j], ah[i], (&w4[0]));                          \
                    MMA16816(acc[i][j], ah[i], (&w4[2]));                          \
                    MMA16816(acc[i][j], al[i], (&w4[0]));                          \
                }                                                                  \
            }                                                                      \
        }                                                                          \
    }

// --- fused QKV projection: Q,K write single fp16 (Q pre-scaled); V writes hi+lo ---
__global__ __launch_bounds__(256, 2)
void gemm_qkv_kernel(const float* __restrict__ query, const float* __restrict__ key,
                     const float* __restrict__ value,
                     const __half* __restrict__ Wh_all,
                     const __half* __restrict__ Wl_all,
                     const float* __restrict__ bq, const float* __restrict__ bk,
                     const float* __restrict__ bv,
                     __half* __restrict__ Qh, __half* __restrict__ Kh,
                     __half* __restrict__ Vh, __half* __restrict__ Vl)
{
    extern __shared__ char smem[];
    const uint32_t sb = smem_u32(smem);
    const int tid  = threadIdx.x;
    const int wid  = tid >> 5;
    const int lane = tid & 31;
    const int m0 = blockIdx.y * 128;
    const int n0 = blockIdx.x * 128;
    const int wm = (wid >> 2) * 64;
    const int wn = (wid & 3) * 32;
    const int z = blockIdx.z;

    const float* A   = (z == 0) ? query : (z == 1) ? key : value;
    const float* bia = (z == 0) ? bq    : (z == 1) ? bk  : bv;
    const __half* Whi = Wh_all + (size_t)z * 65536;
    const __half* Wlo = Wl_all + (size_t)z * 65536;
    __half* Oh = (z == 0) ? Qh : (z == 1) ? Kh : Vh;
    const float oscale = (z == 0) ? 0.17677669529663687f : 1.0f;

    float acc[4][4][4] = {};
    GEMM_MAINLOOP(A, Whi, Wlo)

    const int r0 = lane >> 2;
    const int cp = (lane & 3) * 2;
    #pragma unroll
    for (int i = 0; i < 4; i++)
        #pragma unroll
        for (int j = 0; j < 4; j++) {
            int col = n0 + wn + j * 8 + cp;
            float2 bb = *(const float2*)(bia + col);
            int row = m0 + wm + i * 16 + r0;
            float x0 = (acc[i][j][0] + bb.x) * oscale;
            float y0 = (acc[i][j][1] + bb.y) * oscale;
            float x1 = (acc[i][j][2] + bb.x) * oscale;
            float y1 = (acc[i][j][3] + bb.y) * oscale;
            if (z == 2) {
                uint32_t hp, lp;
                split_pack(x0, y0, hp, lp);
                *(uint32_t*)(Vh + (size_t)row * 256 + col) = hp;
                *(uint32_t*)(Vl + (size_t)row * 256 + col) = lp;
                split_pack(x1, y1, hp, lp);
                *(uint32_t*)(Vh + (size_t)(row + 8) * 256 + col) = hp;
                *(uint32_t*)(Vl + (size_t)(row + 8) * 256 + col) = lp;
            } else {
                *(uint32_t*)(Oh + (size_t)row * 256 + col)       = pack_h(x0, y0);
                *(uint32_t*)(Oh + (size_t)(row + 8) * 256 + col) = pack_h(x1, y1);
            }
        }
}

// --- output projection: fp32 epilogue ---
__global__ __launch_bounds__(256, 2)
void gemm_out_kernel(const float* __restrict__ A,
                     const __half* __restrict__ Whi,
                     const __half* __restrict__ Wlo,
                     const float* __restrict__ bias,
                     float* __restrict__ C)
{
    extern __shared__ char smem[];
    const uint32_t sb = smem_u32(smem);
    const int tid  = threadIdx.x;
    const int wid  = tid >> 5;
    const int lane = tid & 31;
    const int m0 = blockIdx.y * 128;
    const int n0 = blockIdx.x * 128;
    const int wm = (wid >> 2) * 64;
    const int wn = (wid & 3) * 32;

    float acc[4][4][4] = {};
    GEMM_MAINLOOP(A, Whi, Wlo)

    const int r0 = lane >> 2;
    const int cp = (lane & 3) * 2;
    #pragma unroll
    for (int i = 0; i < 4; i++)
        #pragma unroll
        for (int j = 0; j < 4; j++) {
            int col = n0 + wn + j * 8 + cp;
            float2 bb = *(const float2*)(bias + col);
            int row = m0 + wm + i * 16 + r0;
            float2 o0 = make_float2(acc[i][j][0] + bb.x, acc[i][j][1] + bb.y);
            *(float2*)(C + (size_t)row * 256 + col) = o0;
            float2 o1 = make_float2(acc[i][j][2] + bb.x, acc[i][j][3] + bb.y);
            *(float2*)(C + (size_t)(row + 8) * 256 + col) = o1;
        }
}

// ====================== mma.sync flash attention (fp16) ====================
// Q,K single fp16 (S = 1 MMA pass); P packed fp16; V fp16 hi+lo (PV = 2 passes).
// 128 q-rows/block, 8 warps, KV tile 64, cp.async double-buffered KV.
// Dynamic smem: Qh @ 0 (10240); KV buf b @ 10240+b*15360:
//   {Kh +0, Vh +5120, Vl +10240}. Total 40960.
#define ASM_QH 0
#define ASM_KV(b) (10240 + (b) * 15360)
#define ASM_TOTAL 40960

__global__ __launch_bounds__(256, 2)
void attn_mma_kernel(const __half* __restrict__ Qh_g,
                     const __half* __restrict__ Kh_g,
                     const __half* __restrict__ Vh_g,
                     const __half* __restrict__ Vl_g,
                     float* __restrict__ Og)
{
    extern __shared__ char smem[];
    const uint32_t sb = smem_u32(smem);
    const int tid  = threadIdx.x;
    const int wid  = tid >> 5;
    const int lane = tid & 31;
    const int tq = (int)gridDim.x - 1 - (int)blockIdx.x;   // long blocks first
    const int hb = blockIdx.y;
    const int h  = hb & 7;
    const int bb = hb >> 3;
    const size_t base = (size_t)bb * 2048 * 256 + (size_t)h * 32;
    const int qbase = tq * 128;
    float* Ob = Og + base;

    const int ntiles = 2 * tq + 2;

    // prologue: cp.async Q + KV tile0 -> buf0, one group
    #pragma unroll
    for (int g = 0; g < 2; g++) {
        int s = tid + g * 256, r = s >> 2, c8 = (s & 3) * 8;
        CP_ASYNC16(sb + ASM_QH + (r * 40 + c8) * 2,
                   Qh_g + base + (size_t)(qbase + r) * 256 + c8);
    }
    {
        int r = tid >> 2, c8 = (tid & 3) * 8;
        size_t src = base + (size_t)r * 256 + c8;
        CP_ASYNC16(sb + ASM_KV(0) +     0 + (r * 40 + c8) * 2, Kh_g + src);
        CP_ASYNC16(sb + ASM_KV(0) +  5120 + (r * 40 + c8) * 2, Vh_g + src);
        CP_ASYNC16(sb + ASM_KV(0) + 10240 + (r * 40 + c8) * 2, Vl_g + src);
    }
    CP_COMMIT();

    uint32_t qh[2][4];
    float o[4][4] = {};
    float mrow[2] = {-1e30f, -1e30f};
    float lrow[2] = {0.0f, 0.0f};

    // K fragment addressing: one x4 loads b-frags for a PAIR of n8 tiles.
    // lanes 0-7: rows jp*16+0..7 @k+0 | 8-15: same rows @k+8
    // lanes 16-23: rows jp*16+8..15 @k+0 | 24-31: same @k+8
    const uint32_t kfoff = (((((lane >> 4) & 1) << 3) + (lane & 7)) * 40
                           + (((lane >> 3) & 1) << 3)) * 2;
    // V fragment addressing (trans): lanes 0-15 -> Vh rows, 16-31 -> Vl rows
    const uint32_t vfoff = 5120u + (((lane >> 4) & 1) ? 5120u : 0u)
                           + ((lane & 15) * 40) * 2;

    for (int jt = 0; jt < ntiles; jt++) {
        __syncthreads();   // all warps done reading buf[(jt+1)&1] (tile jt-1)
        if (jt + 1 < ntiles) {
            const uint32_t kv = sb + ASM_KV((jt + 1) & 1);
            int r = tid >> 2, c8 = (tid & 3) * 8;
            size_t src = base + (size_t)((jt + 1) * 64 + r) * 256 + c8;
            CP_ASYNC16(kv +     0 + (r * 40 + c8) * 2, Kh_g + src);
            CP_ASYNC16(kv +  5120 + (r * 40 + c8) * 2, Vh_g + src);
            CP_ASYNC16(kv + 10240 + (r * 40 + c8) * 2, Vl_g + src);
            CP_COMMIT();
            CP_WAIT1();    // tile jt (and Q on jt==0) landed
        } else {
            CP_WAIT0();
        }
        __syncthreads();

        if (jt == 0) {     // resident Q fragments
            const int arow = lane & 15;
            const int aco  = ((lane >> 4) << 3);
            #pragma unroll
            for (int ks = 0; ks < 2; ks++)
                LDSM_X4(qh[ks], sb + ASM_QH + ((wid * 16 + arow) * 40 + ks * 16 + aco) * 2);
        }

        // skip warps fully masked by causality
        if (jt * 64 > qbase + wid * 16 + 15) continue;

        const uint32_t kv = sb + ASM_KV(jt & 1);

        // ---- S = Q @ K^T (single fp16 pass) ----
        float s[8][4] = {};
        #pragma unroll
        for (int ks = 0; ks < 2; ks++) {
            #pragma unroll
            for (int jp = 0; jp < 4; jp++) {
                uint32_t k4[4];
                LDSM_X4(k4, kv + kfoff + (jp * 16 * 40 + ks * 16) * 2);
                MMA16816(s[2 * jp],     qh[ks], (&k4[0]));
                MMA16816(s[2 * jp + 1], qh[ks], (&k4[2]));
            }
        }

        // ---- causal mask (diagonal region only) ----
        if (jt >= 2 * tq) {
            const int row0 = qbase + wid * 16 + (lane >> 2);
            #pragma unroll
            for (int j = 0; j < 8; j++) {
                int col = jt * 64 + j * 8 + (lane & 3) * 2;
                if (col     > row0)     s[j][0] = -1e30f;
                if (col + 1 > row0)     s[j][1] = -1e30f;
                if (col     > row0 + 8) s[j][2] = -1e30f;
                if (col + 1 > row0 + 8) s[j][3] = -1e30f;
            }
        }

        // ---- online softmax ----
        #pragma unroll
        for (int hf = 0; hf < 2; hf++) {
            float mt = -1e30f;
            #pragma unroll
            for (int j = 0; j < 8; j++)
                mt = fmaxf(mt, fmaxf(s[j][2 * hf], s[j][2 * hf + 1]));
            mt = fmaxf(mt, __shfl_xor_sync(0xffffffffu, mt, 1));
            mt = fmaxf(mt, __shfl_xor_sync(0xffffffffu, mt, 2));
            float mnew  = fmaxf(mrow[hf], mt);
            float alpha = __expf(mrow[hf] - mnew);
            float ls = 0.0f;
            #pragma unroll
            for (int j = 0; j < 8; j++) {
                s[j][2 * hf]     = __expf(s[j][2 * hf]     - mnew);
                s[j][2 * hf + 1] = __expf(s[j][2 * hf + 1] - mnew);
                ls += s[j][2 * hf] + s[j][2 * hf + 1];
            }
            ls += __shfl_xor_sync(0xffffffffu, ls, 1);
            ls += __shfl_xor_sync(0xffffffffu, ls, 2);
            mrow[hf] = mnew;
            lrow[hf] = lrow[hf] * alpha + ls;
            #pragma unroll
            for (int j = 0; j < 4; j++) {
                o[j][2 * hf]     *= alpha;
                o[j][2 * hf + 1] *= alpha;
            }
        }

        // ---- O += P @ V (P fp16; V hi+lo => 2 passes) ----
        #pragma unroll
        for (int t = 0; t < 4; t++) {
            uint32_t ph[4];
            ph[0] = pack_h(s[2 * t][0],     s[2 * t][1]);
            ph[1] = pack_h(s[2 * t][2],     s[2 * t][3]);
            ph[2] = pack_h(s[2 * t + 1][0], s[2 * t + 1][1]);
            ph[3] = pack_h(s[2 * t + 1][2], s[2 * t + 1][3]);

            #pragma unroll
            for (int j = 0; j < 4; j++) {
                uint32_t v4[4];
                LDSM_X4_T(v4, kv + vfoff + (t * 16 * 40 + j * 8) * 2);
                MMA16816(o[j], ph, (&v4[0]));
                MMA16816(o[j], ph, (&v4[2]));
            }
        }
    }

    // ---- normalize + store ----
    const float inv0 = 1.0f / lrow[0];
    const float inv1 = 1.0f / lrow[1];
    const int row = qbase + wid * 16 + (lane >> 2);
    #pragma unroll
    for (int j = 0; j < 4; j++) {
        int col = j * 8 + (lane & 3) * 2;
        float2 o0 = make_float2(o[j][0] * inv0, o[j][1] * inv0);
        *(float2*)(Ob + (size_t)row * 256 + col) = o0;
        float2 o1 = make_float2(o[j][2] * inv1, o[j][3] * inv1);
        *(float2*)(Ob + (size_t)(row + 8) * 256 + col) = o1;
    }
}

// ---------------------------------------------------------------------------
extern "C" void kernel_launch(void* const* d_in, const int* in_sizes, int n_in,
                              void* d_out, int out_size)
{
    const float* query = (const float*)d_in[0];
    const float* key   = (const float*)d_in[1];
    const float* value = (const float*)d_in[2];
    const float* Wq    = (const float*)d_in[3];
    const float* bq    = (const float*)d_in[4];
    const float* Wk    = (const float*)d_in[5];
    const float* bk    = (const float*)d_in[6];
    const float* Wv    = (const float*)d_in[7];
    const float* bv    = (const float*)d_in[8];
    const float* Wo    = (const float*)d_in[9];
    const float* bo    = (const float*)d_in[10];
    float* out = (float*)d_out;

    float* AO;
    __half *Qh, *Kh, *Vh, *Vl, *Wh, *Wl;
    cudaGetSymbolAddress((void**)&AO, g_AO);
    cudaGetSymbolAddress((void**)&Qh, g_Qh);
    cudaGetSymbolAddress((void**)&Kh, g_Kh);
    cudaGetSymbolAddress((void**)&Vh, g_Vh);
    cudaGetSymbolAddress((void**)&Vl, g_Vl);
    cudaGetSymbolAddress((void**)&Wh, g_Wh);
    cudaGetSymbolAddress((void**)&Wl, g_Wl);

    cudaFuncSetAttribute(gemm_qkv_kernel,
                         cudaFuncAttributeMaxDynamicSharedMemorySize, GSM_TOTAL);
    cudaFuncSetAttribute(gemm_out_kernel,
                         cudaFuncAttributeMaxDynamicSharedMemorySize, GSM_TOTAL);
    cudaFuncSetAttribute(attn_mma_kernel,
                         cudaFuncAttributeMaxDynamicSharedMemorySize, ASM_TOTAL);

    convert_w_kernel<<<dim3(256, 4), 256>>>(Wq, Wk, Wv, Wo, Wh, Wl);

    gemm_qkv_kernel<<<dim3(2, 128, 3), 256, GSM_TOTAL>>>(
        query, key, value, Wh, Wl, bq, bk, bv, Qh, Kh, Vh, Vl);

    attn_mma_kernel<<<dim3(16, 64), 256, ASM_TOTAL>>>(Qh, Kh, Vh, Vl, AO);

    gemm_out_kernel<<<dim3(2, 128), 256, GSM_TOTAL>>>(
        AO, Wh + 3 * 65536, Wl + 3 * 65536, bo, out);
}

// round 11
// speedup vs baseline: 6.4418x; 1.3002x over previous
#include <cuda_runtime.h>
#include <cuda_fp16.h>
#include <cstdint>

// Problem constants: B=8, N=2048, D=256, HEAD=8, ATT=32
#define NROWS 16384   // B*N
#define DMODEL 256

// Scratch (allocation-free rule: device globals)
__device__ __align__(16) float  g_AO[NROWS * DMODEL];
__device__ __align__(16) __half g_Qh[NROWS * DMODEL];   // fp16, pre-scaled by 1/sqrt(32)
__device__ __align__(16) __half g_Kh[NROWS * DMODEL];   // fp16
__device__ __align__(16) __half g_Vh[NROWS * DMODEL];   // fp16
__device__ __align__(16) __half g_Wh[4 * DMODEL * DMODEL];
__device__ __align__(16) __half g_Wl[4 * DMODEL * DMODEL];

// ========================= PTX helpers (compute_100-safe) ==================
__device__ __forceinline__ uint32_t smem_u32(const void* p) {
    uint32_t a;
    asm("{ .reg .u64 t; cvta.to.shared.u64 t, %1; cvt.u32.u64 %0, t; }"
        : "=r"(a) : "l"(p));
    return a;
}

#define LDSM_X4(r, addr) \
    asm volatile("ldmatrix.sync.aligned.m8n8.x4.shared.b16 {%0,%1,%2,%3}, [%4];" \
        : "=r"((r)[0]), "=r"((r)[1]), "=r"((r)[2]), "=r"((r)[3]) : "r"(addr))

#define LDSM_X4_T(r, addr) \
    asm volatile("ldmatrix.sync.aligned.m8n8.x4.trans.shared.b16 {%0,%1,%2,%3}, [%4];" \
        : "=r"((r)[0]), "=r"((r)[1]), "=r"((r)[2]), "=r"((r)[3]) : "r"(addr))

#define MMA16816(d, a, b) \
    asm volatile("mma.sync.aligned.m16n8k16.row.col.f32.f16.f16.f32 " \
        "{%0,%1,%2,%3}, {%4,%5,%6,%7}, {%8,%9}, {%0,%1,%2,%3};" \
        : "+f"((d)[0]), "+f"((d)[1]), "+f"((d)[2]), "+f"((d)[3]) \
        : "r"((a)[0]), "r"((a)[1]), "r"((a)[2]), "r"((a)[3]), \
          "r"((b)[0]), "r"((b)[1]))

#define CP_ASYNC16(dst, src) \
    asm volatile("cp.async.cg.shared.global [%0], [%1], 16;" \
        :: "r"(dst), "l"(src) : "memory")
#define CP_COMMIT() asm volatile("cp.async.commit_group;" ::: "memory")
#define CP_WAIT0()  asm volatile("cp.async.wait_group 0;" ::: "memory")
#define CP_WAIT1()  asm volatile("cp.async.wait_group 1;" ::: "memory")

__device__ __forceinline__ uint32_t pack_h(float x, float y) {
    __half2 h = __floats2half2_rn(x, y);
    return *reinterpret_cast<uint32_t*>(&h);
}

// ============================ weight split =================================
__global__ void convert_w_kernel(const float* __restrict__ W0, const float* __restrict__ W1,
                                 const float* __restrict__ W2, const float* __restrict__ W3,
                                 __half* __restrict__ hi, __half* __restrict__ lo)
{
    int i = blockIdx.x * 256 + threadIdx.x;
    int m = blockIdx.y;
    const float* src = (m == 0) ? W0 : (m == 1) ? W1 : (m == 2) ? W2 : W3;
    float x = src[i];
    __half h = __float2half_rn(x);
    float r = x - __half2float(h);
    hi[m * 65536 + i] = h;
    lo[m * 65536 + i] = __float2half_rn(r);
}

// ==================== pipelined mma.sync fp16 GEMM (2-pass) ================
// C ~= Ah*(Wh + Wl) + bias.  Dynamic smem (row stride 40 halfs = 80 B):
//   sAh @ 0 (10240), W buf b: Wh @ 10240+b*20480, Wl @ +10240.  Total 51200.
#define GSM_AH   0
#define GSM_WB(b) (10240 + (b) * 20480)
#define GSM_TOTAL 51200

#define GEMM_MAINLOOP(APTR, WHI, WLO)                                              \
    float2 pa[8];                                                                  \
    _Pragma("unroll")                                                              \
    for (int g = 0; g < 2; g++) {                                                  \
        int s = tid + g * 256, r = s >> 2, c8 = (s & 3) * 8;                       \
        CP_ASYNC16(sb + GSM_WB(0) + (r * 40 + c8) * 2,                             \
                   (WHI) + (size_t)(n0 + r) * 256 + c8);                           \
        CP_ASYNC16(sb + GSM_WB(0) + 10240 + (r * 40 + c8) * 2,                     \
                   (WLO) + (size_t)(n0 + r) * 256 + c8);                           \
    }                                                                              \
    CP_COMMIT();                                                                   \
    _Pragma("unroll")                                                              \
    for (int it = 0; it < 8; it++) {                                               \
        int idx = tid + it * 256, r = idx >> 4, c2 = (idx & 15) * 2;               \
        pa[it] = *(const float2*)((APTR) + (size_t)(m0 + r) * 256 + c2);           \
    }                                                                              \
    const uint32_t wfoff = (((lane >> 4) & 1) ? 10240u : 0u)                       \
        + ((wn + (lane & 7)) * 40 + (((lane >> 3) & 1) << 3)) * 2;                 \
    for (int chunk = 0; chunk < 8; chunk++) {                                      \
        const int kk = chunk * 32;                                                 \
        const uint32_t wb = sb + GSM_WB(chunk & 1);                                \
        __syncthreads();                                                           \
        _Pragma("unroll")                                                          \
        for (int it = 0; it < 8; it++) {                                           \
            int idx = tid + it * 256, r = idx >> 4, c2 = (idx & 15) * 2;           \
            *(uint32_t*)(smem + GSM_AH + (r * 40 + c2) * 2) =                      \
                pack_h(pa[it].x, pa[it].y);                                        \
        }                                                                          \
        if (chunk < 7) {                                                           \
            const uint32_t wn2 = sb + GSM_WB((chunk + 1) & 1);                     \
            _Pragma("unroll")                                                      \
            for (int g = 0; g < 2; g++) {                                          \
                int s = tid + g * 256, r = s >> 2, c8 = (s & 3) * 8;               \
                CP_ASYNC16(wn2 + (r * 40 + c8) * 2,                                \
                           (WHI) + (size_t)(n0 + r) * 256 + kk + 32 + c8);         \
                CP_ASYNC16(wn2 + 10240 + (r * 40 + c8) * 2,                        \
                           (WLO) + (size_t)(n0 + r) * 256 + kk + 32 + c8);         \
            }                                                                      \
            CP_COMMIT();                                                           \
            _Pragma("unroll")                                                      \
            for (int it = 0; it < 8; it++) {                                       \
                int idx = tid + it * 256, r = idx >> 4, c2 = (idx & 15) * 2;       \
                pa[it] = *(const float2*)((APTR) + (size_t)(m0 + r) * 256 + kk + 32 + c2); \
            }                                                                      \
            CP_WAIT1();                                                            \
        } else {                                                                   \
            CP_WAIT0();                                                            \
        }                                                                          \
        __syncthreads();                                                           \
        _Pragma("unroll")                                                          \
        for (int ks = 0; ks < 32; ks += 16) {                                      \
            uint32_t ah[4][4];                                                     \
            const int arow = lane & 15;                                            \
            const int acol = ks + ((lane >> 4) << 3);                              \
            _Pragma("unroll")                                                      \
            for (int i = 0; i < 4; i++)                                            \
                LDSM_X4(ah[i], sb + GSM_AH + ((wm + i * 16 + arow) * 40 + acol) * 2); \
            _Pragma("unroll")                                                      \
            for (int j = 0; j < 4; j++) {                                          \
                uint32_t w4[4];                                                    \
                LDSM_X4(w4, wb + wfoff + (j * 8 * 40 + ks) * 2);                   \
                _Pragma("unroll")                                                  \
                for (int i = 0; i < 4; i++) {                                      \
                    MMA16816(acc[i][j], ah[i], (&w4[0]));                          \
                    MMA16816(acc[i][j], ah[i], (&w4[2]));                          \
                }                                                                  \
            }                                                                      \
        }                                                                          \
    }

// --- fused QKV projection: all outputs single fp16 (Q pre-scaled) ---
__global__ __launch_bounds__(256, 2)
void gemm_qkv_kernel(const float* __restrict__ query, const float* __restrict__ key,
                     const float* __restrict__ value,
                     const __half* __restrict__ Wh_all,
                     const __half* __restrict__ Wl_all,
                     const float* __restrict__ bq, const float* __restrict__ bk,
                     const float* __restrict__ bv,
                     __half* __restrict__ Qh, __half* __restrict__ Kh,
                     __half* __restrict__ Vh)
{
    extern __shared__ char smem[];
    const uint32_t sb = smem_u32(smem);
    const int tid  = threadIdx.x;
    const int wid  = tid >> 5;
    const int lane = tid & 31;
    const int m0 = blockIdx.y * 128;
    const int n0 = blockIdx.x * 128;
    const int wm = (wid >> 2) * 64;
    const int wn = (wid & 3) * 32;
    const int z = blockIdx.z;

    const float* A   = (z == 0) ? query : (z == 1) ? key : value;
    const float* bia = (z == 0) ? bq    : (z == 1) ? bk  : bv;
    const __half* Whi = Wh_all + (size_t)z * 65536;
    const __half* Wlo = Wl_all + (size_t)z * 65536;
    __half* Oh = (z == 0) ? Qh : (z == 1) ? Kh : Vh;
    const float oscale = (z == 0) ? 0.17677669529663687f : 1.0f;

    float acc[4][4][4] = {};
    GEMM_MAINLOOP(A, Whi, Wlo)

    const int r0 = lane >> 2;
    const int cp = (lane & 3) * 2;
    #pragma unroll
    for (int i = 0; i < 4; i++)
        #pragma unroll
        for (int j = 0; j < 4; j++) {
            int col = n0 + wn + j * 8 + cp;
            float2 bb = *(const float2*)(bia + col);
            int row = m0 + wm + i * 16 + r0;
            *(uint32_t*)(Oh + (size_t)row * 256 + col) =
                pack_h((acc[i][j][0] + bb.x) * oscale, (acc[i][j][1] + bb.y) * oscale);
            *(uint32_t*)(Oh + (size_t)(row + 8) * 256 + col) =
                pack_h((acc[i][j][2] + bb.x) * oscale, (acc[i][j][3] + bb.y) * oscale);
        }
}

// --- output projection: fp32 epilogue ---
__global__ __launch_bounds__(256, 2)
void gemm_out_kernel(const float* __restrict__ A,
                     const __half* __restrict__ Whi,
                     const __half* __restrict__ Wlo,
                     const float* __restrict__ bias,
                     float* __restrict__ C)
{
    extern __shared__ char smem[];
    const uint32_t sb = smem_u32(smem);
    const int tid  = threadIdx.x;
    const int wid  = tid >> 5;
    const int lane = tid & 31;
    const int m0 = blockIdx.y * 128;
    const int n0 = blockIdx.x * 128;
    const int wm = (wid >> 2) * 64;
    const int wn = (wid & 3) * 32;

    float acc[4][4][4] = {};
    GEMM_MAINLOOP(A, Whi, Wlo)

    const int r0 = lane >> 2;
    const int cp = (lane & 3) * 2;
    #pragma unroll
    for (int i = 0; i < 4; i++)
        #pragma unroll
        for (int j = 0; j < 4; j++) {
            int col = n0 + wn + j * 8 + cp;
            float2 bb = *(const float2*)(bias + col);
            int row = m0 + wm + i * 16 + r0;
            float2 o0 = make_float2(acc[i][j][0] + bb.x, acc[i][j][1] + bb.y);
            *(float2*)(C + (size_t)row * 256 + col) = o0;
            float2 o1 = make_float2(acc[i][j][2] + bb.x, acc[i][j][3] + bb.y);
            *(float2*)(C + (size_t)(row + 8) * 256 + col) = o1;
        }
}

// ====================== mma.sync flash attention (fp16) ====================
// Q,K,V single fp16. S = 1 pass; PV = 1 pass (P packed fp16).
// 128 q-rows/block, 8 warps, KV tile 64, cp.async double-buffered KV.
// Dynamic smem: Qh @ 0 (10240); KV buf b @ 10240+b*10240: {Kh +0, Vh +5120}.
// Total 30720.
#define ASM_QH 0
#define ASM_KV(b) (10240 + (b) * 10240)
#define ASM_TOTAL 30720

__global__ __launch_bounds__(256, 2)
void attn_mma_kernel(const __half* __restrict__ Qh_g,
                     const __half* __restrict__ Kh_g,
                     const __half* __restrict__ Vh_g,
                     float* __restrict__ Og)
{
    extern __shared__ char smem[];
    const uint32_t sb = smem_u32(smem);
    const int tid  = threadIdx.x;
    const int wid  = tid >> 5;
    const int lane = tid & 31;
    const int tq = (int)gridDim.x - 1 - (int)blockIdx.x;   // long blocks first
    const int hb = blockIdx.y;
    const int h  = hb & 7;
    const int bb = hb >> 3;
    const size_t base = (size_t)bb * 2048 * 256 + (size_t)h * 32;
    const int qbase = tq * 128;
    float* Ob = Og + base;

    const int ntiles = 2 * tq + 2;

    // prologue: cp.async Q + KV tile0 -> buf0, one group
    #pragma unroll
    for (int g = 0; g < 2; g++) {
        int s = tid + g * 256, r = s >> 2, c8 = (s & 3) * 8;
        CP_ASYNC16(sb + ASM_QH + (r * 40 + c8) * 2,
                   Qh_g + base + (size_t)(qbase + r) * 256 + c8);
    }
    {
        int r = tid >> 2, c8 = (tid & 3) * 8;
        size_t src = base + (size_t)r * 256 + c8;
        CP_ASYNC16(sb + ASM_KV(0) +    0 + (r * 40 + c8) * 2, Kh_g + src);
        CP_ASYNC16(sb + ASM_KV(0) + 5120 + (r * 40 + c8) * 2, Vh_g + src);
    }
    CP_COMMIT();

    uint32_t qh[2][4];
    float o[4][4] = {};
    float mrow[2] = {-1e30f, -1e30f};
    float lrow[2] = {0.0f, 0.0f};

    // K fragments: one x4 loads b-frags for a PAIR of n8 tiles (R9 layout).
    const uint32_t kfoff = (((((lane >> 4) & 1) << 3) + (lane & 7)) * 40
                           + (((lane >> 3) & 1) << 3)) * 2;
    // V fragments (trans): one x4 loads b-frags for a PAIR of d8 tiles.
    // lanes 0-15 -> rows t*16+(lane&15) col jp*16; lanes 16-31 -> same rows col +8.
    const uint32_t vfoff = 5120u + ((lane & 15) * 40 + (((lane >> 4) & 1) << 3)) * 2;

    for (int jt = 0; jt < ntiles; jt++) {
        __syncthreads();   // all warps done reading buf[(jt+1)&1] (tile jt-1)
        if (jt + 1 < ntiles) {
            const uint32_t kv = sb + ASM_KV((jt + 1) & 1);
            int r = tid >> 2, c8 = (tid & 3) * 8;
            size_t src = base + (size_t)((jt + 1) * 64 + r) * 256 + c8;
            CP_ASYNC16(kv +    0 + (r * 40 + c8) * 2, Kh_g + src);
            CP_ASYNC16(kv + 5120 + (r * 40 + c8) * 2, Vh_g + src);
            CP_COMMIT();
            CP_WAIT1();    // tile jt (and Q on jt==0) landed
        } else {
            CP_WAIT0();
        }
        __syncthreads();

        if (jt == 0) {     // resident Q fragments
            const int arow = lane & 15;
            const int aco  = ((lane >> 4) << 3);
            #pragma unroll
            for (int ks = 0; ks < 2; ks++)
                LDSM_X4(qh[ks], sb + ASM_QH + ((wid * 16 + arow) * 40 + ks * 16 + aco) * 2);
        }

        // skip warps fully masked by causality
        if (jt * 64 > qbase + wid * 16 + 15) continue;

        const uint32_t kv = sb + ASM_KV(jt & 1);

        // ---- S = Q @ K^T (single fp16 pass) ----
        float s[8][4] = {};
        #pragma unroll
        for (int ks = 0; ks < 2; ks++) {
            #pragma unroll
            for (int jp = 0; jp < 4; jp++) {
                uint32_t k4[4];
                LDSM_X4(k4, kv + kfoff + (jp * 16 * 40 + ks * 16) * 2);
                MMA16816(s[2 * jp],     qh[ks], (&k4[0]));
                MMA16816(s[2 * jp + 1], qh[ks], (&k4[2]));
            }
        }

        // ---- causal mask (diagonal region only) ----
        if (jt >= 2 * tq) {
            const int row0 = qbase + wid * 16 + (lane >> 2);
            #pragma unroll
            for (int j = 0; j < 8; j++) {
                int col = jt * 64 + j * 8 + (lane & 3) * 2;
                if (col     > row0)     s[j][0] = -1e30f;
                if (col + 1 > row0)     s[j][1] = -1e30f;
                if (col     > row0 + 8) s[j][2] = -1e30f;
                if (col + 1 > row0 + 8) s[j][3] = -1e30f;
            }
        }

        // ---- online softmax ----
        #pragma unroll
        for (int hf = 0; hf < 2; hf++) {
            float mt = -1e30f;
            #pragma unroll
            for (int j = 0; j < 8; j++)
                mt = fmaxf(mt, fmaxf(s[j][2 * hf], s[j][2 * hf + 1]));
            mt = fmaxf(mt, __shfl_xor_sync(0xffffffffu, mt, 1));
            mt = fmaxf(mt, __shfl_xor_sync(0xffffffffu, mt, 2));
            float mnew  = fmaxf(mrow[hf], mt);
            float alpha = __expf(mrow[hf] - mnew);
            float ls = 0.0f;
            #pragma unroll
            for (int j = 0; j < 8; j++) {
                s[j][2 * hf]     = __expf(s[j][2 * hf]     - mnew);
                s[j][2 * hf + 1] = __expf(s[j][2 * hf + 1] - mnew);
                ls += s[j][2 * hf] + s[j][2 * hf + 1];
            }
            ls += __shfl_xor_sync(0xffffffffu, ls, 1);
            ls += __shfl_xor_sync(0xffffffffu, ls, 2);
            mrow[hf] = mnew;
            lrow[hf] = lrow[hf] * alpha + ls;
            #pragma unroll
            for (int j = 0; j < 4; j++) {
                o[j][2 * hf]     *= alpha;
                o[j][2 * hf + 1] *= alpha;
            }
        }

        // ---- O += P @ V (single pass; P packed fp16 from regs) ----
        #pragma unroll
        for (int t = 0; t < 4; t++) {
            uint32_t ph[4];
            ph[0] = pack_h(s[2 * t][0],     s[2 * t][1]);
            ph[1] = pack_h(s[2 * t][2],     s[2 * t][3]);
            ph[2] = pack_h(s[2 * t + 1][0], s[2 * t + 1][1]);
            ph[3] = pack_h(s[2 * t + 1][2], s[2 * t + 1][3]);

            #pragma unroll
            for (int jp = 0; jp < 2; jp++) {
                uint32_t v4[4];
                LDSM_X4_T(v4, kv + vfoff + (t * 16 * 40 + jp * 16) * 2);
                MMA16816(o[2 * jp],     ph, (&v4[0]));
                MMA16816(o[2 * jp + 1], ph, (&v4[2]));
            }
        }
    }

    // ---- normalize + store ----
    const float inv0 = 1.0f / lrow[0];
    const float inv1 = 1.0f / lrow[1];
    const int row = qbase + wid * 16 + (lane >> 2);
    #pragma unroll
    for (int j = 0; j < 4; j++) {
        int col = j * 8 + (lane & 3) * 2;
        float2 o0 = make_float2(o[j][0] * inv0, o[j][1] * inv0);
        *(float2*)(Ob + (size_t)row * 256 + col) = o0;
        float2 o1 = make_float2(o[j][2] * inv1, o[j][3] * inv1);
        *(float2*)(Ob + (size_t)(row + 8) * 256 + col) = o1;
    }
}

// ---------------------------------------------------------------------------
extern "C" void kernel_launch(void* const* d_in, const int* in_sizes, int n_in,
                              void* d_out, int out_size)
{
    const float* query = (const float*)d_in[0];
    const float* key   = (const float*)d_in[1];
    const float* value = (const float*)d_in[2];
    const float* Wq    = (const float*)d_in[3];
    const float* bq    = (const float*)d_in[4];
    const float* Wk    = (const float*)d_in[5];
    const float* bk    = (const float*)d_in[6];
    const float* Wv    = (const float*)d_in[7];
    const float* bv    = (const float*)d_in[8];
    const float* Wo    = (const float*)d_in[9];
    const float* bo    = (const float*)d_in[10];
    float* out = (float*)d_out;

    float* AO;
    __half *Qh, *Kh, *Vh, *Wh, *Wl;
    cudaGetSymbolAddress((void**)&AO, g_AO);
    cudaGetSymbolAddress((void**)&Qh, g_Qh);
    cudaGetSymbolAddress((void**)&Kh, g_Kh);
    cudaGetSymbolAddress((void**)&Vh, g_Vh);
    cudaGetSymbolAddress((void**)&Wh, g_Wh);
    cudaGetSymbolAddress((void**)&Wl, g_Wl);

    cudaFuncSetAttribute(gemm_qkv_kernel,
                         cudaFuncAttributeMaxDynamicSharedMemorySize, GSM_TOTAL);
    cudaFuncSetAttribute(gemm_out_kernel,
                         cudaFuncAttributeMaxDynamicSharedMemorySize, GSM_TOTAL);
    cudaFuncSetAttribute(attn_mma_kernel,
                         cudaFuncAttributeMaxDynamicSharedMemorySize, ASM_TOTAL);

    convert_w_kernel<<<dim3(256, 4), 256>>>(Wq, Wk, Wv, Wo, Wh, Wl);

    gemm_qkv_kernel<<<dim3(2, 128, 3), 256, GSM_TOTAL>>>(
        query, key, value, Wh, Wl, bq, bk, bv, Qh, Kh, Vh);

    attn_mma_kernel<<<dim3(16, 64), 256, ASM_TOTAL>>>(Qh, Kh, Vh, AO);

    gemm_out_kernel<<<dim3(2, 128), 256, GSM_TOTAL>>>(
        AO, Wh + 3 * 65536, Wl + 3 * 65536, bo, out);
}

// round 12
// speedup vs baseline: 7.4632x; 1.1586x over previous
#include <cuda_runtime.h>
#include <cuda_fp16.h>
#include <cstdint>

// Problem constants: B=8, N=2048, D=256, HEAD=8, ATT=32
#define NROWS 16384   // B*N
#define DMODEL 256

// Scratch (allocation-free rule: device globals)
__device__ __align__(16) float  g_AO[NROWS * DMODEL];
__device__ __align__(16) __half g_Qh[NROWS * DMODEL];   // fp16, pre-scaled by 1/sqrt(32)
__device__ __align__(16) __half g_Kh[NROWS * DMODEL];   // fp16
__device__ __align__(16) __half g_Vh[NROWS * DMODEL];   // fp16
__device__ __align__(16) __half g_Wh[4 * DMODEL * DMODEL];

// ========================= PTX helpers (compute_100-safe) ==================
__device__ __forceinline__ uint32_t smem_u32(const void* p) {
    uint32_t a;
    asm("{ .reg .u64 t; cvta.to.shared.u64 t, %1; cvt.u32.u64 %0, t; }"
        : "=r"(a) : "l"(p));
    return a;
}

#define LDSM_X4(r, addr) \
    asm volatile("ldmatrix.sync.aligned.m8n8.x4.shared.b16 {%0,%1,%2,%3}, [%4];" \
        : "=r"((r)[0]), "=r"((r)[1]), "=r"((r)[2]), "=r"((r)[3]) : "r"(addr))

#define LDSM_X4_T(r, addr) \
    asm volatile("ldmatrix.sync.aligned.m8n8.x4.trans.shared.b16 {%0,%1,%2,%3}, [%4];" \
        : "=r"((r)[0]), "=r"((r)[1]), "=r"((r)[2]), "=r"((r)[3]) : "r"(addr))

#define MMA16816(d, a, b) \
    asm volatile("mma.sync.aligned.m16n8k16.row.col.f32.f16.f16.f32 " \
        "{%0,%1,%2,%3}, {%4,%5,%6,%7}, {%8,%9}, {%0,%1,%2,%3};" \
        : "+f"((d)[0]), "+f"((d)[1]), "+f"((d)[2]), "+f"((d)[3]) \
        : "r"((a)[0]), "r"((a)[1]), "r"((a)[2]), "r"((a)[3]), \
          "r"((b)[0]), "r"((b)[1]))

#define CP_ASYNC16(dst, src) \
    asm volatile("cp.async.cg.shared.global [%0], [%1], 16;" \
        :: "r"(dst), "l"(src) : "memory")
#define CP_COMMIT() asm volatile("cp.async.commit_group;" ::: "memory")
#define CP_WAIT0()  asm volatile("cp.async.wait_group 0;" ::: "memory")
#define CP_WAIT1()  asm volatile("cp.async.wait_group 1;" ::: "memory")

__device__ __forceinline__ uint32_t pack_h(float x, float y) {
    __half2 h = __floats2half2_rn(x, y);
    return *reinterpret_cast<uint32_t*>(&h);
}

// ============================ weight convert ===============================
__global__ void convert_w_kernel(const float* __restrict__ W0, const float* __restrict__ W1,
                                 const float* __restrict__ W2, const float* __restrict__ W3,
                                 __half* __restrict__ hi)
{
    int i = blockIdx.x * 256 + threadIdx.x;
    int m = blockIdx.y;
    const float* src = (m == 0) ? W0 : (m == 1) ? W1 : (m == 2) ? W2 : W3;
    hi[m * 65536 + i] = __float2half_rn(src[i]);
}

// ==================== pipelined mma.sync fp16 GEMM (1-pass) ================
// C ~= Ah*Wh + bias.  Dynamic smem (row stride 40 halfs = 80 B):
//   sAh @ 0 (10240), W buf b @ 10240+b*10240.  Total 30720.
#define GSM_AH   0
#define GSM_WB(b) (10240 + (b) * 10240)
#define GSM_TOTAL 30720

#define GEMM_MAINLOOP(APTR, WHI)                                                   \
    float2 pa[8];                                                                  \
    _Pragma("unroll")                                                              \
    for (int g = 0; g < 2; g++) {                                                  \
        int s = tid + g * 256, r = s >> 2, c8 = (s & 3) * 8;                       \
        CP_ASYNC16(sb + GSM_WB(0) + (r * 40 + c8) * 2,                             \
                   (WHI) + (size_t)(n0 + r) * 256 + c8);                           \
    }                                                                              \
    CP_COMMIT();                                                                   \
    _Pragma("unroll")                                                              \
    for (int it = 0; it < 8; it++) {                                               \
        int idx = tid + it * 256, r = idx >> 4, c2 = (idx & 15) * 2;               \
        pa[it] = *(const float2*)((APTR) + (size_t)(m0 + r) * 256 + c2);           \
    }                                                                              \
    /* paired-n8 W fragment addressing (one x4 feeds 2 n8 tiles) */                \
    const uint32_t wfoff = ((wn + (((lane >> 4) & 1) << 3) + (lane & 7)) * 40      \
                           + (((lane >> 3) & 1) << 3)) * 2;                        \
    for (int chunk = 0; chunk < 8; chunk++) {                                      \
        const int kk = chunk * 32;                                                 \
        const uint32_t wb = sb + GSM_WB(chunk & 1);                                \
        __syncthreads();                                                           \
        _Pragma("unroll")                                                          \
        for (int it = 0; it < 8; it++) {                                           \
            int idx = tid + it * 256, r = idx >> 4, c2 = (idx & 15) * 2;           \
            *(uint32_t*)(smem + GSM_AH + (r * 40 + c2) * 2) =                      \
                pack_h(pa[it].x, pa[it].y);                                        \
        }                                                                          \
        if (chunk < 7) {                                                           \
            const uint32_t wn2 = sb + GSM_WB((chunk + 1) & 1);                     \
            _Pragma("unroll")                                                      \
            for (int g = 0; g < 2; g++) {                                          \
                int s = tid + g * 256, r = s >> 2, c8 = (s & 3) * 8;               \
                CP_ASYNC16(wn2 + (r * 40 + c8) * 2,                                \
                           (WHI) + (size_t)(n0 + r) * 256 + kk + 32 + c8);         \
            }                                                                      \
            CP_COMMIT();                                                           \
            _Pragma("unroll")                                                      \
            for (int it = 0; it < 8; it++) {                                       \
                int idx = tid + it * 256, r = idx >> 4, c2 = (idx & 15) * 2;       \
                pa[it] = *(const float2*)((APTR) + (size_t)(m0 + r) * 256 + kk + 32 + c2); \
            }                                                                      \
            CP_WAIT1();                                                            \
        } else {                                                                   \
            CP_WAIT0();                                                            \
        }                                                                          \
        __syncthreads();                                                           \
        _Pragma("unroll")                                                          \
        for (int ks = 0; ks < 32; ks += 16) {                                      \
            uint32_t ah[4][4];                                                     \
            const int arow = lane & 15;                                            \
            const int acol = ks + ((lane >> 4) << 3);                              \
            _Pragma("unroll")                                                      \
            for (int i = 0; i < 4; i++)                                            \
                LDSM_X4(ah[i], sb + GSM_AH + ((wm + i * 16 + arow) * 40 + acol) * 2); \
            _Pragma("unroll")                                                      \
            for (int jp = 0; jp < 2; jp++) {                                       \
                uint32_t w4[4];                                                    \
                LDSM_X4(w4, wb + wfoff + (jp * 16 * 40 + ks) * 2);                 \
                _Pragma("unroll")                                                  \
                for (int i = 0; i < 4; i++) {                                      \
                    MMA16816(acc[i][2 * jp],     ah[i], (&w4[0]));                 \
                    MMA16816(acc[i][2 * jp + 1], ah[i], (&w4[2]));                 \
                }                                                                  \
            }                                                                      \
        }                                                                          \
    }

// --- fused QKV projection: all outputs single fp16 (Q pre-scaled) ---
__global__ __launch_bounds__(256, 2)
void gemm_qkv_kernel(const float* __restrict__ query, const float* __restrict__ key,
                     const float* __restrict__ value,
                     const __half* __restrict__ Wh_all,
                     const float* __restrict__ bq, const float* __restrict__ bk,
                     const float* __restrict__ bv,
                     __half* __restrict__ Qh, __half* __restrict__ Kh,
                     __half* __restrict__ Vh)
{
    extern __shared__ char smem[];
    const uint32_t sb = smem_u32(smem);
    const int tid  = threadIdx.x;
    const int wid  = tid >> 5;
    const int lane = tid & 31;
    const int m0 = blockIdx.y * 128;
    const int n0 = blockIdx.x * 128;
    const int wm = (wid >> 2) * 64;
    const int wn = (wid & 3) * 32;
    const int z = blockIdx.z;

    const float* A   = (z == 0) ? query : (z == 1) ? key : value;
    const float* bia = (z == 0) ? bq    : (z == 1) ? bk  : bv;
    const __half* Whi = Wh_all + (size_t)z * 65536;
    __half* Oh = (z == 0) ? Qh : (z == 1) ? Kh : Vh;
    const float oscale = (z == 0) ? 0.17677669529663687f : 1.0f;

    float acc[4][4][4] = {};
    GEMM_MAINLOOP(A, Whi)

    const int r0 = lane >> 2;
    const int cp = (lane & 3) * 2;
    #pragma unroll
    for (int i = 0; i < 4; i++)
        #pragma unroll
        for (int j = 0; j < 4; j++) {
            int col = n0 + wn + j * 8 + cp;
            float2 bb = *(const float2*)(bia + col);
            int row = m0 + wm + i * 16 + r0;
            *(uint32_t*)(Oh + (size_t)row * 256 + col) =
                pack_h((acc[i][j][0] + bb.x) * oscale, (acc[i][j][1] + bb.y) * oscale);
            *(uint32_t*)(Oh + (size_t)(row + 8) * 256 + col) =
                pack_h((acc[i][j][2] + bb.x) * oscale, (acc[i][j][3] + bb.y) * oscale);
        }
}

// --- output projection: fp32 epilogue ---
__global__ __launch_bounds__(256, 2)
void gemm_out_kernel(const float* __restrict__ A,
                     const __half* __restrict__ Whi,
                     const float* __restrict__ bias,
                     float* __restrict__ C)
{
    extern __shared__ char smem[];
    const uint32_t sb = smem_u32(smem);
    const int tid  = threadIdx.x;
    const int wid  = tid >> 5;
    const int lane = tid & 31;
    const int m0 = blockIdx.y * 128;
    const int n0 = blockIdx.x * 128;
    const int wm = (wid >> 2) * 64;
    const int wn = (wid & 3) * 32;

    float acc[4][4][4] = {};
    GEMM_MAINLOOP(A, Whi)

    const int r0 = lane >> 2;
    const int cp = (lane & 3) * 2;
    #pragma unroll
    for (int i = 0; i < 4; i++)
        #pragma unroll
        for (int j = 0; j < 4; j++) {
            int col = n0 + wn + j * 8 + cp;
            float2 bb = *(const float2*)(bias + col);
            int row = m0 + wm + i * 16 + r0;
            float2 o0 = make_float2(acc[i][j][0] + bb.x, acc[i][j][1] + bb.y);
            *(float2*)(C + (size_t)row * 256 + col) = o0;
            float2 o1 = make_float2(acc[i][j][2] + bb.x, acc[i][j][3] + bb.y);
            *(float2*)(C + (size_t)(row + 8) * 256 + col) = o1;
        }
}

// ====================== mma.sync flash attention (fp16) ====================
// Q,K,V single fp16. S = 1 pass; PV = 1 pass (P packed fp16).
// 128 q-rows/block, 8 warps, KV tile 64, cp.async double-buffered KV.
// Dynamic smem: Qh @ 0 (10240); KV buf b @ 10240+b*10240: {Kh +0, Vh +5120}.
// Total 30720.
#define ASM_QH 0
#define ASM_KV(b) (10240 + (b) * 10240)
#define ASM_TOTAL 30720

__global__ __launch_bounds__(256, 2)
void attn_mma_kernel(const __half* __restrict__ Qh_g,
                     const __half* __restrict__ Kh_g,
                     const __half* __restrict__ Vh_g,
                     float* __restrict__ Og)
{
    extern __shared__ char smem[];
    const uint32_t sb = smem_u32(smem);
    const int tid  = threadIdx.x;
    const int wid  = tid >> 5;
    const int lane = tid & 31;
    const int tq = (int)gridDim.x - 1 - (int)blockIdx.x;   // long blocks first
    const int hb = blockIdx.y;
    const int h  = hb & 7;
    const int bb = hb >> 3;
    const size_t base = (size_t)bb * 2048 * 256 + (size_t)h * 32;
    const int qbase = tq * 128;
    float* Ob = Og + base;

    const int ntiles = 2 * tq + 2;

    // prologue: cp.async Q + KV tile0 -> buf0, one group
    #pragma unroll
    for (int g = 0; g < 2; g++) {
        int s = tid + g * 256, r = s >> 2, c8 = (s & 3) * 8;
        CP_ASYNC16(sb + ASM_QH + (r * 40 + c8) * 2,
                   Qh_g + base + (size_t)(qbase + r) * 256 + c8);
    }
    {
        int r = tid >> 2, c8 = (tid & 3) * 8;
        size_t src = base + (size_t)r * 256 + c8;
        CP_ASYNC16(sb + ASM_KV(0) +    0 + (r * 40 + c8) * 2, Kh_g + src);
        CP_ASYNC16(sb + ASM_KV(0) + 5120 + (r * 40 + c8) * 2, Vh_g + src);
    }
    CP_COMMIT();

    uint32_t qh[2][4];
    float o[4][4] = {};
    float mrow[2] = {-1e30f, -1e30f};
    float lrow[2] = {0.0f, 0.0f};

    // K fragments: one x4 loads b-frags for a PAIR of n8 tiles.
    const uint32_t kfoff = (((((lane >> 4) & 1) << 3) + (lane & 7)) * 40
                           + (((lane >> 3) & 1) << 3)) * 2;
    // V fragments (trans): one x4 loads b-frags for a PAIR of d8 tiles.
    const uint32_t vfoff = 5120u + ((lane & 15) * 40 + (((lane >> 4) & 1) << 3)) * 2;

    for (int jt = 0; jt < ntiles; jt++) {
        __syncthreads();   // all warps done reading buf[(jt+1)&1] (tile jt-1)
        if (jt + 1 < ntiles) {
            const uint32_t kv = sb + ASM_KV((jt + 1) & 1);
            int r = tid >> 2, c8 = (tid & 3) * 8;
            size_t src = base + (size_t)((jt + 1) * 64 + r) * 256 + c8;
            CP_ASYNC16(kv +    0 + (r * 40 + c8) * 2, Kh_g + src);
            CP_ASYNC16(kv + 5120 + (r * 40 + c8) * 2, Vh_g + src);
            CP_COMMIT();
            CP_WAIT1();    // tile jt (and Q on jt==0) landed
        } else {
            CP_WAIT0();
        }
        __syncthreads();

        if (jt == 0) {     // resident Q fragments
            const int arow = lane & 15;
            const int aco  = ((lane >> 4) << 3);
            #pragma unroll
            for (int ks = 0; ks < 2; ks++)
                LDSM_X4(qh[ks], sb + ASM_QH + ((wid * 16 + arow) * 40 + ks * 16 + aco) * 2);
        }

        // skip warps fully masked by causality
        if (jt * 64 > qbase + wid * 16 + 15) continue;

        const uint32_t kv = sb + ASM_KV(jt & 1);

        // ---- S = Q @ K^T (single fp16 pass) ----
        float s[8][4] = {};
        #pragma unroll
        for (int ks = 0; ks < 2; ks++) {
            #pragma unroll
            for (int jp = 0; jp < 4; jp++) {
                uint32_t k4[4];
                LDSM_X4(k4, kv + kfoff + (jp * 16 * 40 + ks * 16) * 2);
                MMA16816(s[2 * jp],     qh[ks], (&k4[0]));
                MMA16816(s[2 * jp + 1], qh[ks], (&k4[2]));
            }
        }

        // ---- causal mask (diagonal region only) ----
        if (jt >= 2 * tq) {
            const int row0 = qbase + wid * 16 + (lane >> 2);
            #pragma unroll
            for (int j = 0; j < 8; j++) {
                int col = jt * 64 + j * 8 + (lane & 3) * 2;
                if (col     > row0)     s[j][0] = -1e30f;
                if (col + 1 > row0)     s[j][1] = -1e30f;
                if (col     > row0 + 8) s[j][2] = -1e30f;
                if (col + 1 > row0 + 8) s[j][3] = -1e30f;
            }
        }

        // ---- online softmax ----
        #pragma unroll
        for (int hf = 0; hf < 2; hf++) {
            float mt = -1e30f;
            #pragma unroll
            for (int j = 0; j < 8; j++)
                mt = fmaxf(mt, fmaxf(s[j][2 * hf], s[j][2 * hf + 1]));
            mt = fmaxf(mt, __shfl_xor_sync(0xffffffffu, mt, 1));
            mt = fmaxf(mt, __shfl_xor_sync(0xffffffffu, mt, 2));
            float mnew  = fmaxf(mrow[hf], mt);
            float alpha = __expf(mrow[hf] - mnew);
            float ls = 0.0f;
            #pragma unroll
            for (int j = 0; j < 8; j++) {
                s[j][2 * hf]     = __expf(s[j][2 * hf]     - mnew);
                s[j][2 * hf + 1] = __expf(s[j][2 * hf + 1] - mnew);
                ls += s[j][2 * hf] + s[j][2 * hf + 1];
            }
            ls += __shfl_xor_sync(0xffffffffu, ls, 1);
            ls += __shfl_xor_sync(0xffffffffu, ls, 2);
            mrow[hf] = mnew;
            lrow[hf] = lrow[hf] * alpha + ls;
            #pragma unroll
            for (int j = 0; j < 4; j++) {
                o[j][2 * hf]     *= alpha;
                o[j][2 * hf + 1] *= alpha;
            }
        }

        // ---- O += P @ V (single pass; P packed fp16 from regs) ----
        #pragma unroll
        for (int t = 0; t < 4; t++) {
            uint32_t ph[4];
            ph[0] = pack_h(s[2 * t][0],     s[2 * t][1]);
            ph[1] = pack_h(s[2 * t][2],     s[2 * t][3]);
            ph[2] = pack_h(s[2 * t + 1][0], s[2 * t + 1][1]);
            ph[3] = pack_h(s[2 * t + 1][2], s[2 * t + 1][3]);

            #pragma unroll
            for (int jp = 0; jp < 2; jp++) {
                uint32_t v4[4];
                LDSM_X4_T(v4, kv + vfoff + (t * 16 * 40 + jp * 16) * 2);
                MMA16816(o[2 * jp],     ph, (&v4[0]));
                MMA16816(o[2 * jp + 1], ph, (&v4[2]));
            }
        }
    }

    // ---- normalize + store ----
    const float inv0 = 1.0f / lrow[0];
    const float inv1 = 1.0f / lrow[1];
    const int row = qbase + wid * 16 + (lane >> 2);
    #pragma unroll
    for (int j = 0; j < 4; j++) {
        int col = j * 8 + (lane & 3) * 2;
        float2 o0 = make_float2(o[j][0] * inv0, o[j][1] * inv0);
        *(float2*)(Ob + (size_t)row * 256 + col) = o0;
        float2 o1 = make_float2(o[j][2] * inv1, o[j][3] * inv1);
        *(float2*)(Ob + (size_t)(row + 8) * 256 + col) = o1;
    }
}

// ---------------------------------------------------------------------------
extern "C" void kernel_launch(void* const* d_in, const int* in_sizes, int n_in,
                              void* d_out, int out_size)
{
    const float* query = (const float*)d_in[0];
    const float* key   = (const float*)d_in[1];
    const float* value = (const float*)d_in[2];
    const float* Wq    = (const float*)d_in[3];
    const float* bq    = (const float*)d_in[4];
    const float* Wk    = (const float*)d_in[5];
    const float* bk    = (const float*)d_in[6];
    const float* Wv    = (const float*)d_in[7];
    const float* bv    = (const float*)d_in[8];
    const float* Wo    = (const float*)d_in[9];
    const float* bo    = (const float*)d_in[10];
    float* out = (float*)d_out;

    float* AO;
    __half *Qh, *Kh, *Vh, *Wh;
    cudaGetSymbolAddress((void**)&AO, g_AO);
    cudaGetSymbolAddress((void**)&Qh, g_Qh);
    cudaGetSymbolAddress((void**)&Kh, g_Kh);
    cudaGetSymbolAddress((void**)&Vh, g_Vh);
    cudaGetSymbolAddress((void**)&Wh, g_Wh);

    cudaFuncSetAttribute(gemm_qkv_kernel,
                         cudaFuncAttributeMaxDynamicSharedMemorySize, GSM_TOTAL);
    cudaFuncSetAttribute(gemm_out_kernel,
                         cudaFuncAttributeMaxDynamicSharedMemorySize, GSM_TOTAL);
    cudaFuncSetAttribute(attn_mma_kernel,
                         cudaFuncAttributeMaxDynamicSharedMemorySize, ASM_TOTAL);

    convert_w_kernel<<<dim3(256, 4), 256>>>(Wq, Wk, Wv, Wo, Wh);

    gemm_qkv_kernel<<<dim3(2, 128, 3), 256, GSM_TOTAL>>>(
        query, key, value, Wh, bq, bk, bv, Qh, Kh, Vh);

    attn_mma_kernel<<<dim3(16, 64), 256, ASM_TOTAL>>>(Qh, Kh, Vh, AO);

    gemm_out_kernel<<<dim3(2, 128), 256, GSM_TOTAL>>>(
        AO, Wh + 3 * 65536, bo, out);
}

// round 13
// speedup vs baseline: 7.6158x; 1.0204x over previous
#include <cuda_runtime.h>
#include <cuda_fp16.h>
#include <cstdint>

// Problem constants: B=8, N=2048, D=256, HEAD=8, ATT=32
#define NROWS 16384   // B*N
#define DMODEL 256

// Scratch (allocation-free rule: device globals)
__device__ __align__(16) __half g_AOh[NROWS * DMODEL];  // attention out, fp16
__device__ __align__(16) __half g_Qh[NROWS * DMODEL];   // fp16, pre-scaled log2e/sqrt(32)
__device__ __align__(16) __half g_Kh[NROWS * DMODEL];   // fp16
__device__ __align__(16) __half g_Vh[NROWS * DMODEL];   // fp16
__device__ __align__(16) __half g_Wh[4 * DMODEL * DMODEL];

// ========================= PTX helpers (compute_100-safe) ==================
__device__ __forceinline__ uint32_t smem_u32(const void* p) {
    uint32_t a;
    asm("{ .reg .u64 t; cvta.to.shared.u64 t, %1; cvt.u32.u64 %0, t; }"
        : "=r"(a) : "l"(p));
    return a;
}

#define LDSM_X4(r, addr) \
    asm volatile("ldmatrix.sync.aligned.m8n8.x4.shared.b16 {%0,%1,%2,%3}, [%4];" \
        : "=r"((r)[0]), "=r"((r)[1]), "=r"((r)[2]), "=r"((r)[3]) : "r"(addr))

#define LDSM_X4_T(r, addr) \
    asm volatile("ldmatrix.sync.aligned.m8n8.x4.trans.shared.b16 {%0,%1,%2,%3}, [%4];" \
        : "=r"((r)[0]), "=r"((r)[1]), "=r"((r)[2]), "=r"((r)[3]) : "r"(addr))

#define MMA16816(d, a, b) \
    asm volatile("mma.sync.aligned.m16n8k16.row.col.f32.f16.f16.f32 " \
        "{%0,%1,%2,%3}, {%4,%5,%6,%7}, {%8,%9}, {%0,%1,%2,%3};" \
        : "+f"((d)[0]), "+f"((d)[1]), "+f"((d)[2]), "+f"((d)[3]) \
        : "r"((a)[0]), "r"((a)[1]), "r"((a)[2]), "r"((a)[3]), \
          "r"((b)[0]), "r"((b)[1]))

#define CP_ASYNC16(dst, src) \
    asm volatile("cp.async.cg.shared.global [%0], [%1], 16;" \
        :: "r"(dst), "l"(src) : "memory")
#define CP_COMMIT() asm volatile("cp.async.commit_group;" ::: "memory")
#define CP_WAIT0()  asm volatile("cp.async.wait_group 0;" ::: "memory")
#define CP_WAIT1()  asm volatile("cp.async.wait_group 1;" ::: "memory")

__device__ __forceinline__ uint32_t pack_h(float x, float y) {
    __half2 h = __floats2half2_rn(x, y);
    return *reinterpret_cast<uint32_t*>(&h);
}
__device__ __forceinline__ float ex2f(float x) {
    float y;
    asm("ex2.approx.f32 %0, %1;" : "=f"(y) : "f"(x));
    return y;
}

// ============================ weight convert ===============================
__global__ void convert_w_kernel(const float* __restrict__ W0, const float* __restrict__ W1,
                                 const float* __restrict__ W2, const float* __restrict__ W3,
                                 __half* __restrict__ hi)
{
    int i = blockIdx.x * 256 + threadIdx.x;
    int m = blockIdx.y;
    const float* src = (m == 0) ? W0 : (m == 1) ? W1 : (m == 2) ? W2 : W3;
    hi[m * 65536 + i] = __float2half_rn(src[i]);
}

// ==================== pipelined mma.sync fp16 GEMM (QKV) ===================
// C ~= Ah*Wh + bias, A fp32 converted in-loop (wide LDG.128/STS.128 staging).
// Dynamic smem (row stride 40 halfs = 80 B):
//   sAh @ 0 (10240), W buf b @ 10240+b*10240.  Total 30720.
#define GSM_AH   0
#define GSM_WB(b) (10240 + (b) * 10240)
#define GSM_TOTAL 30720

#define GEMM_MAINLOOP(APTR, WHI)                                                   \
    float4 pa[4];                                                                  \
    const int ar  = tid >> 1;                                                      \
    const int acb = (tid & 1) * 16;                                                \
    _Pragma("unroll")                                                              \
    for (int g = 0; g < 2; g++) {                                                  \
        int s = tid + g * 256, r = s >> 2, c8 = (s & 3) * 8;                       \
        CP_ASYNC16(sb + GSM_WB(0) + (r * 40 + c8) * 2,                             \
                   (WHI) + (size_t)(n0 + r) * 256 + c8);                           \
    }                                                                              \
    CP_COMMIT();                                                                   \
    _Pragma("unroll")                                                              \
    for (int it = 0; it < 4; it++)                                                 \
        pa[it] = *(const float4*)((APTR) + (size_t)(m0 + ar) * 256 + acb + it * 4);\
    const uint32_t wfoff = ((wn + (((lane >> 4) & 1) << 3) + (lane & 7)) * 40      \
                           + (((lane >> 3) & 1) << 3)) * 2;                        \
    for (int chunk = 0; chunk < 8; chunk++) {                                      \
        const int kk = chunk * 32;                                                 \
        const uint32_t wb = sb + GSM_WB(chunk & 1);                                \
        __syncthreads();                                                           \
        {                                                                          \
            uint32_t p[8];                                                         \
            _Pragma("unroll")                                                      \
            for (int q = 0; q < 4; q++) {                                          \
                p[2 * q]     = pack_h(pa[q].x, pa[q].y);                           \
                p[2 * q + 1] = pack_h(pa[q].z, pa[q].w);                           \
            }                                                                      \
            *(uint4*)(smem + GSM_AH + (ar * 40 + acb) * 2) =                       \
                make_uint4(p[0], p[1], p[2], p[3]);                                \
            *(uint4*)(smem + GSM_AH + (ar * 40 + acb) * 2 + 16) =                  \
                make_uint4(p[4], p[5], p[6], p[7]);                                \
        }                                                                          \
        if (chunk < 7) {                                                           \
            const uint32_t wn2 = sb + GSM_WB((chunk + 1) & 1);                     \
            _Pragma("unroll")                                                      \
            for (int g = 0; g < 2; g++) {                                          \
                int s = tid + g * 256, r = s >> 2, c8 = (s & 3) * 8;               \
                CP_ASYNC16(wn2 + (r * 40 + c8) * 2,                                \
                           (WHI) + (size_t)(n0 + r) * 256 + kk + 32 + c8);         \
            }                                                                      \
            CP_COMMIT();                                                           \
            _Pragma("unroll")                                                      \
            for (int it = 0; it < 4; it++)                                         \
                pa[it] = *(const float4*)((APTR) + (size_t)(m0 + ar) * 256         \
                                          + kk + 32 + acb + it * 4);               \
            CP_WAIT1();                                                            \
        } else {                                                                   \
            CP_WAIT0();                                                            \
        }                                                                          \
        __syncthreads();                                                           \
        _Pragma("unroll")                                                          \
        for (int ks = 0; ks < 32; ks += 16) {                                      \
            uint32_t ah[4][4];                                                     \
            const int arow = lane & 15;                                            \
            const int acol = ks + ((lane >> 4) << 3);                              \
            _Pragma("unroll")                                                      \
            for (int i = 0; i < 4; i++)                                            \
                LDSM_X4(ah[i], sb + GSM_AH + ((wm + i * 16 + arow) * 40 + acol) * 2); \
            _Pragma("unroll")                                                      \
            for (int jp = 0; jp < 2; jp++) {                                       \
                uint32_t w4[4];                                                    \
                LDSM_X4(w4, wb + wfoff + (jp * 16 * 40 + ks) * 2);                 \
                _Pragma("unroll")                                                  \
                for (int i = 0; i < 4; i++) {                                      \
                    MMA16816(acc[i][2 * jp],     ah[i], (&w4[0]));                 \
                    MMA16816(acc[i][2 * jp + 1], ah[i], (&w4[2]));                 \
                }                                                                  \
            }                                                                      \
        }                                                                          \
    }

// --- fused QKV projection: outputs fp16 (Q pre-scaled by log2e/sqrt(32)) ---
__global__ __launch_bounds__(256, 2)
void gemm_qkv_kernel(const float* __restrict__ query, const float* __restrict__ key,
                     const float* __restrict__ value,
                     const __half* __restrict__ Wh_all,
                     const float* __restrict__ bq, const float* __restrict__ bk,
                     const float* __restrict__ bv,
                     __half* __restrict__ Qh, __half* __restrict__ Kh,
                     __half* __restrict__ Vh)
{
    extern __shared__ char smem[];
    const uint32_t sb = smem_u32(smem);
    const int tid  = threadIdx.x;
    const int wid  = tid >> 5;
    const int lane = tid & 31;
    const int m0 = blockIdx.y * 128;
    const int n0 = blockIdx.x * 128;
    const int wm = (wid >> 2) * 64;
    const int wn = (wid & 3) * 32;
    const int z = blockIdx.z;

    const float* A   = (z == 0) ? query : (z == 1) ? key : value;
    const float* bia = (z == 0) ? bq    : (z == 1) ? bk  : bv;
    const __half* Whi = Wh_all + (size_t)z * 65536;
    __half* Oh = (z == 0) ? Qh : (z == 1) ? Kh : Vh;
    // Q scale = log2(e)/sqrt(32): softmax done in base-2 units
    const float oscale = (z == 0) ? 0.2550348652153015f : 1.0f;

    float acc[4][4][4] = {};
    GEMM_MAINLOOP(A, Whi)

    const int r0 = lane >> 2;
    const int cp = (lane & 3) * 2;
    #pragma unroll
    for (int i = 0; i < 4; i++)
        #pragma unroll
        for (int j = 0; j < 4; j++) {
            int col = n0 + wn + j * 8 + cp;
            float2 bb = *(const float2*)(bia + col);
            int row = m0 + wm + i * 16 + r0;
            *(uint32_t*)(Oh + (size_t)row * 256 + col) =
                pack_h((acc[i][j][0] + bb.x) * oscale, (acc[i][j][1] + bb.y) * oscale);
            *(uint32_t*)(Oh + (size_t)(row + 8) * 256 + col) =
                pack_h((acc[i][j][2] + bb.x) * oscale, (acc[i][j][3] + bb.y) * oscale);
        }
}

// --- output projection: A is fp16 (attention output), pure cp.async staging ---
// Dynamic smem: buf b @ b*20480: {A 10240, W @ +10240}. Total 40960.
#define OSM_AB(b) ((b) * 20480)
#define OSM_WB(b) ((b) * 20480 + 10240)
#define OSM_TOTAL 40960

__global__ __launch_bounds__(256, 2)
void gemm_out_kernel(const __half* __restrict__ A,
                     const __half* __restrict__ Whi,
                     const float* __restrict__ bias,
                     float* __restrict__ C)
{
    extern __shared__ char smem[];
    const uint32_t sb = smem_u32(smem);
    const int tid  = threadIdx.x;
    const int wid  = tid >> 5;
    const int lane = tid & 31;
    const int m0 = blockIdx.y * 128;
    const int n0 = blockIdx.x * 128;
    const int wm = (wid >> 2) * 64;
    const int wn = (wid & 3) * 32;

    float acc[4][4][4] = {};

    // prologue: A+W chunk0 -> buf0
    #pragma unroll
    for (int g = 0; g < 2; g++) {
        int s = tid + g * 256, r = s >> 2, c8 = (s & 3) * 8;
        CP_ASYNC16(sb + OSM_AB(0) + (r * 40 + c8) * 2, A   + (size_t)(m0 + r) * 256 + c8);
        CP_ASYNC16(sb + OSM_WB(0) + (r * 40 + c8) * 2, Whi + (size_t)(n0 + r) * 256 + c8);
    }
    CP_COMMIT();

    const uint32_t wfoff = ((wn + (((lane >> 4) & 1) << 3) + (lane & 7)) * 40
                           + (((lane >> 3) & 1) << 3)) * 2;

    for (int chunk = 0; chunk < 8; chunk++) {
        const int kk = chunk * 32;
        __syncthreads();   // prev iter's reads of buf[(chunk+1)&1] done
        if (chunk < 7) {
            const uint32_t ab = sb + OSM_AB((chunk + 1) & 1);
            const uint32_t wb2 = sb + OSM_WB((chunk + 1) & 1);
            #pragma unroll
            for (int g = 0; g < 2; g++) {
                int s = tid + g * 256, r = s >> 2, c8 = (s & 3) * 8;
                CP_ASYNC16(ab  + (r * 40 + c8) * 2, A   + (size_t)(m0 + r) * 256 + kk + 32 + c8);
                CP_ASYNC16(wb2 + (r * 40 + c8) * 2, Whi + (size_t)(n0 + r) * 256 + kk + 32 + c8);
            }
            CP_COMMIT();
            CP_WAIT1();
        } else {
            CP_WAIT0();
        }
        __syncthreads();

        const uint32_t ab = sb + OSM_AB(chunk & 1);
        const uint32_t wb = sb + OSM_WB(chunk & 1);
        #pragma unroll
        for (int ks = 0; ks < 32; ks += 16) {
            uint32_t ah[4][4];
            const int arow = lane & 15;
            const int acol = ks + ((lane >> 4) << 3);
            #pragma unroll
            for (int i = 0; i < 4; i++)
                LDSM_X4(ah[i], ab + ((wm + i * 16 + arow) * 40 + acol) * 2);
            #pragma unroll
            for (int jp = 0; jp < 2; jp++) {
                uint32_t w4[4];
                LDSM_X4(w4, wb + wfoff + (jp * 16 * 40 + ks) * 2);
                #pragma unroll
                for (int i = 0; i < 4; i++) {
                    MMA16816(acc[i][2 * jp],     ah[i], (&w4[0]));
                    MMA16816(acc[i][2 * jp + 1], ah[i], (&w4[2]));
                }
            }
        }
    }

    const int r0 = lane >> 2;
    const int cp = (lane & 3) * 2;
    #pragma unroll
    for (int i = 0; i < 4; i++)
        #pragma unroll
        for (int j = 0; j < 4; j++) {
            int col = n0 + wn + j * 8 + cp;
            float2 bb = *(const float2*)(bias + col);
            int row = m0 + wm + i * 16 + r0;
            float2 o0 = make_float2(acc[i][j][0] + bb.x, acc[i][j][1] + bb.y);
            *(float2*)(C + (size_t)row * 256 + col) = o0;
            float2 o1 = make_float2(acc[i][j][2] + bb.x, acc[i][j][3] + bb.y);
            *(float2*)(C + (size_t)(row + 8) * 256 + col) = o1;
        }
}

// ====================== mma.sync flash attention (fp16) ====================
// Q,K,V single fp16; logits in log2 units (scale folded into Q); softmax via
// ex2.approx with tree reductions; output written fp16.
// Dynamic smem: Qh @ 0 (10240); KV buf b @ 10240+b*10240: {Kh +0, Vh +5120}.
#define ASM_QH 0
#define ASM_KV(b) (10240 + (b) * 10240)
#define ASM_TOTAL 30720

__global__ __launch_bounds__(256, 2)
void attn_mma_kernel(const __half* __restrict__ Qh_g,
                     const __half* __restrict__ Kh_g,
                     const __half* __restrict__ Vh_g,
                     __half* __restrict__ Og)
{
    extern __shared__ char smem[];
    const uint32_t sb = smem_u32(smem);
    const int tid  = threadIdx.x;
    const int wid  = tid >> 5;
    const int lane = tid & 31;
    const int tq = (int)gridDim.x - 1 - (int)blockIdx.x;   // long blocks first
    const int hb = blockIdx.y;
    const int h  = hb & 7;
    const int bb = hb >> 3;
    const size_t base = (size_t)bb * 2048 * 256 + (size_t)h * 32;
    const int qbase = tq * 128;
    __half* Ob = Og + base;

    const int ntiles = 2 * tq + 2;

    // prologue: cp.async Q + KV tile0 -> buf0, one group
    #pragma unroll
    for (int g = 0; g < 2; g++) {
        int s = tid + g * 256, r = s >> 2, c8 = (s & 3) * 8;
        CP_ASYNC16(sb + ASM_QH + (r * 40 + c8) * 2,
                   Qh_g + base + (size_t)(qbase + r) * 256 + c8);
    }
    {
        int r = tid >> 2, c8 = (tid & 3) * 8;
        size_t src = base + (size_t)r * 256 + c8;
        CP_ASYNC16(sb + ASM_KV(0) +    0 + (r * 40 + c8) * 2, Kh_g + src);
        CP_ASYNC16(sb + ASM_KV(0) + 5120 + (r * 40 + c8) * 2, Vh_g + src);
    }
    CP_COMMIT();

    uint32_t qh[2][4];
    float o[4][4] = {};
    float mrow[2] = {-1e30f, -1e30f};   // log2 units
    float lrow[2] = {0.0f, 0.0f};

    // K fragments: one x4 loads b-frags for a PAIR of n8 tiles.
    const uint32_t kfoff = (((((lane >> 4) & 1) << 3) + (lane & 7)) * 40
                           + (((lane >> 3) & 1) << 3)) * 2;
    // V fragments (trans): one x4 loads b-frags for a PAIR of d8 tiles.
    const uint32_t vfoff = 5120u + ((lane & 15) * 40 + (((lane >> 4) & 1) << 3)) * 2;

    for (int jt = 0; jt < ntiles; jt++) {
        __syncthreads();   // all warps done reading buf[(jt+1)&1] (tile jt-1)
        if (jt + 1 < ntiles) {
            const uint32_t kv = sb + ASM_KV((jt + 1) & 1);
            int r = tid >> 2, c8 = (tid & 3) * 8;
            size_t src = base + (size_t)((jt + 1) * 64 + r) * 256 + c8;
            CP_ASYNC16(kv +    0 + (r * 40 + c8) * 2, Kh_g + src);
            CP_ASYNC16(kv + 5120 + (r * 40 + c8) * 2, Vh_g + src);
            CP_COMMIT();
            CP_WAIT1();    // tile jt (and Q on jt==0) landed
        } else {
            CP_WAIT0();
        }
        __syncthreads();

        if (jt == 0) {     // resident Q fragments
            const int arow = lane & 15;
            const int aco  = ((lane >> 4) << 3);
            #pragma unroll
            for (int ks = 0; ks < 2; ks++)
                LDSM_X4(qh[ks], sb + ASM_QH + ((wid * 16 + arow) * 40 + ks * 16 + aco) * 2);
        }

        // skip warps fully masked by causality
        if (jt * 64 > qbase + wid * 16 + 15) continue;

        const uint32_t kv = sb + ASM_KV(jt & 1);

        // ---- S = Q @ K^T (single fp16 pass; logits in log2 units) ----
        float s[8][4] = {};
        #pragma unroll
        for (int ks = 0; ks < 2; ks++) {
            #pragma unroll
            for (int jp = 0; jp < 4; jp++) {
                uint32_t k4[4];
                LDSM_X4(k4, kv + kfoff + (jp * 16 * 40 + ks * 16) * 2);
                MMA16816(s[2 * jp],     qh[ks], (&k4[0]));
                MMA16816(s[2 * jp + 1], qh[ks], (&k4[2]));
            }
        }

        // ---- causal mask (diagonal region only) ----
        if (jt >= 2 * tq) {
            const int row0 = qbase + wid * 16 + (lane >> 2);
            #pragma unroll
            for (int j = 0; j < 8; j++) {
                int col = jt * 64 + j * 8 + (lane & 3) * 2;
                if (col     > row0)     s[j][0] = -1e30f;
                if (col + 1 > row0)     s[j][1] = -1e30f;
                if (col     > row0 + 8) s[j][2] = -1e30f;
                if (col + 1 > row0 + 8) s[j][3] = -1e30f;
            }
        }

        // ---- online softmax (base-2, tree reductions) ----
        #pragma unroll
        for (int hf = 0; hf < 2; hf++) {
            const int a0 = 2 * hf, a1 = 2 * hf + 1;
            float mj[8];
            #pragma unroll
            for (int j = 0; j < 8; j++) mj[j] = fmaxf(s[j][a0], s[j][a1]);
            mj[0] = fmaxf(mj[0], mj[1]); mj[2] = fmaxf(mj[2], mj[3]);
            mj[4] = fmaxf(mj[4], mj[5]); mj[6] = fmaxf(mj[6], mj[7]);
            mj[0] = fmaxf(mj[0], mj[2]); mj[4] = fmaxf(mj[4], mj[6]);
            float mt = fmaxf(mj[0], mj[4]);
            mt = fmaxf(mt, __shfl_xor_sync(0xffffffffu, mt, 1));
            mt = fmaxf(mt, __shfl_xor_sync(0xffffffffu, mt, 2));
            float mnew  = fmaxf(mrow[hf], mt);
            float alpha = ex2f(mrow[hf] - mnew);
            float sa[8];
            #pragma unroll
            for (int j = 0; j < 8; j++) {
                s[j][a0] = ex2f(s[j][a0] - mnew);
                s[j][a1] = ex2f(s[j][a1] - mnew);
                sa[j] = s[j][a0] + s[j][a1];
            }
            sa[0] += sa[1]; sa[2] += sa[3]; sa[4] += sa[5]; sa[6] += sa[7];
            sa[0] += sa[2]; sa[4] += sa[6];
            float ls = sa[0] + sa[4];
            ls += __shfl_xor_sync(0xffffffffu, ls, 1);
            ls += __shfl_xor_sync(0xffffffffu, ls, 2);
            mrow[hf] = mnew;
            lrow[hf] = lrow[hf] * alpha + ls;
            #pragma unroll
            for (int j = 0; j < 4; j++) {
                o[j][a0] *= alpha;
                o[j][a1] *= alpha;
            }
        }

        // ---- O += P @ V (single pass; P packed fp16 from regs) ----
        #pragma unroll
        for (int t = 0; t < 4; t++) {
            uint32_t ph[4];
            ph[0] = pack_h(s[2 * t][0],     s[2 * t][1]);
            ph[1] = pack_h(s[2 * t][2],     s[2 * t][3]);
            ph[2] = pack_h(s[2 * t + 1][0], s[2 * t + 1][1]);
            ph[3] = pack_h(s[2 * t + 1][2], s[2 * t + 1][3]);

            #pragma unroll
            for (int jp = 0; jp < 2; jp++) {
                uint32_t v4[4];
                LDSM_X4_T(v4, kv + vfoff + (t * 16 * 40 + jp * 16) * 2);
                MMA16816(o[2 * jp],     ph, (&v4[0]));
                MMA16816(o[2 * jp + 1], ph, (&v4[2]));
            }
        }
    }

    // ---- normalize + store (fp16) ----
    const float inv0 = 1.0f / lrow[0];
    const float inv1 = 1.0f / lrow[1];
    const int row = qbase + wid * 16 + (lane >> 2);
    #pragma unroll
    for (int j = 0; j < 4; j++) {
        int col = j * 8 + (lane & 3) * 2;
        *(uint32_t*)(Ob + (size_t)row * 256 + col) =
            pack_h(o[j][0] * inv0, o[j][1] * inv0);
        *(uint32_t*)(Ob + (size_t)(row + 8) * 256 + col) =
            pack_h(o[j][2] * inv1, o[j][3] * inv1);
    }
}

// ---------------------------------------------------------------------------
extern "C" void kernel_launch(void* const* d_in, const int* in_sizes, int n_in,
                              void* d_out, int out_size)
{
    const float* query = (const float*)d_in[0];
    const float* key   = (const float*)d_in[1];
    const float* value = (const float*)d_in[2];
    const float* Wq    = (const float*)d_in[3];
    const float* bq    = (const float*)d_in[4];
    const float* Wk    = (const float*)d_in[5];
    const float* bk    = (const float*)d_in[6];
    const float* Wv    = (const float*)d_in[7];
    const float* bv    = (const float*)d_in[8];
    const float* Wo    = (const float*)d_in[9];
    const float* bo    = (const float*)d_in[10];
    float* out = (float*)d_out;

    __half *AOh, *Qh, *Kh, *Vh, *Wh;
    cudaGetSymbolAddress((void**)&AOh, g_AOh);
    cudaGetSymbolAddress((void**)&Qh,  g_Qh);
    cudaGetSymbolAddress((void**)&Kh,  g_Kh);
    cudaGetSymbolAddress((void**)&Vh,  g_Vh);
    cudaGetSymbolAddress((void**)&Wh,  g_Wh);

    cudaFuncSetAttribute(gemm_qkv_kernel,
                         cudaFuncAttributeMaxDynamicSharedMemorySize, GSM_TOTAL);
    cudaFuncSetAttribute(gemm_out_kernel,
                         cudaFuncAttributeMaxDynamicSharedMemorySize, OSM_TOTAL);
    cudaFuncSetAttribute(attn_mma_kernel,
                         cudaFuncAttributeMaxDynamicSharedMemorySize, ASM_TOTAL);

    convert_w_kernel<<<dim3(256, 4), 256>>>(Wq, Wk, Wv, Wo, Wh);

    gemm_qkv_kernel<<<dim3(2, 128, 3), 256, GSM_TOTAL>>>(
        query, key, value, Wh, bq, bk, bv, Qh, Kh, Vh);

    attn_mma_kernel<<<dim3(16, 64), 256, ASM_TOTAL>>>(Qh, Kh, Vh, AOh);

    gemm_out_kernel<<<dim3(2, 128), 256, OSM_TOTAL>>>(
        AOh, Wh + 3 * 65536, bo, out);
}

// round 14
// speedup vs baseline: 7.7170x; 1.0133x over previous
#include <cuda_runtime.h>
#include <cuda_fp16.h>
#include <cstdint>

// Problem constants: B=8, N=2048, D=256, HEAD=8, ATT=32
#define NROWS 16384   // B*N
#define DMODEL 256

// Scratch (allocation-free rule: device globals)
__device__ __align__(16) __half g_AOh[NROWS * DMODEL];  // attention out, fp16
__device__ __align__(16) __half g_Qh[NROWS * DMODEL];   // fp16, pre-scaled log2e/sqrt(32)
__device__ __align__(16) __half g_Kh[NROWS * DMODEL];   // fp16
__device__ __align__(16) __half g_Vh[NROWS * DMODEL];   // fp16
__device__ __align__(16) __half g_Wh[4 * DMODEL * DMODEL];

// ========================= PTX helpers (compute_100-safe) ==================
__device__ __forceinline__ uint32_t smem_u32(const void* p) {
    uint32_t a;
    asm("{ .reg .u64 t; cvta.to.shared.u64 t, %1; cvt.u32.u64 %0, t; }"
        : "=r"(a) : "l"(p));
    return a;
}

#define LDSM_X4(r, addr) \
    asm volatile("ldmatrix.sync.aligned.m8n8.x4.shared.b16 {%0,%1,%2,%3}, [%4];" \
        : "=r"((r)[0]), "=r"((r)[1]), "=r"((r)[2]), "=r"((r)[3]) : "r"(addr))

#define LDSM_X4_T(r, addr) \
    asm volatile("ldmatrix.sync.aligned.m8n8.x4.trans.shared.b16 {%0,%1,%2,%3}, [%4];" \
        : "=r"((r)[0]), "=r"((r)[1]), "=r"((r)[2]), "=r"((r)[3]) : "r"(addr))

#define MMA16816(d, a, b) \
    asm volatile("mma.sync.aligned.m16n8k16.row.col.f32.f16.f16.f32 " \
        "{%0,%1,%2,%3}, {%4,%5,%6,%7}, {%8,%9}, {%0,%1,%2,%3};" \
        : "+f"((d)[0]), "+f"((d)[1]), "+f"((d)[2]), "+f"((d)[3]) \
        : "r"((a)[0]), "r"((a)[1]), "r"((a)[2]), "r"((a)[3]), \
          "r"((b)[0]), "r"((b)[1]))

#define CP_ASYNC16(dst, src) \
    asm volatile("cp.async.cg.shared.global [%0], [%1], 16;" \
        :: "r"(dst), "l"(src) : "memory")
#define CP_COMMIT() asm volatile("cp.async.commit_group;" ::: "memory")
#define CP_WAIT0()  asm volatile("cp.async.wait_group 0;" ::: "memory")
#define CP_WAIT1()  asm volatile("cp.async.wait_group 1;" ::: "memory")

__device__ __forceinline__ uint32_t pack_h(float x, float y) {
    __half2 h = __floats2half2_rn(x, y);
    return *reinterpret_cast<uint32_t*>(&h);
}
__device__ __forceinline__ float ex2f(float x) {
    float y;
    asm("ex2.approx.f32 %0, %1;" : "=f"(y) : "f"(x));
    return y;
}
// packed fp16 2^x: argument pair -> P pair (already MMA-ready)
__device__ __forceinline__ uint32_t ex2_h2(float x, float y) {
    __half2 a = __floats2half2_rn(x, y);
    uint32_t au = *reinterpret_cast<uint32_t*>(&a), pu;
    asm("ex2.approx.f16x2 %0, %1;" : "=r"(pu) : "r"(au));
    return pu;
}
__device__ __forceinline__ __half2 u2h2(uint32_t u) {
    return *reinterpret_cast<__half2*>(&u);
}

// ============================ weight convert ===============================
__global__ void convert_w_kernel(const float* __restrict__ W0, const float* __restrict__ W1,
                                 const float* __restrict__ W2, const float* __restrict__ W3,
                                 __half* __restrict__ hi)
{
    int i = blockIdx.x * 256 + threadIdx.x;
    int m = blockIdx.y;
    const float* src = (m == 0) ? W0 : (m == 1) ? W1 : (m == 2) ? W2 : W3;
    hi[m * 65536 + i] = __float2half_rn(src[i]);
}

// ==================== pipelined mma.sync fp16 GEMM (QKV) ===================
// C ~= Ah*Wh + bias, A fp32 converted in-loop (wide LDG.128/STS.128 staging).
#define GSM_AH   0
#define GSM_WB(b) (10240 + (b) * 10240)
#define GSM_TOTAL 30720

#define GEMM_MAINLOOP(APTR, WHI)                                                   \
    float4 pa[4];                                                                  \
    const int ar  = tid >> 1;                                                      \
    const int acb = (tid & 1) * 16;                                                \
    _Pragma("unroll")                                                              \
    for (int g = 0; g < 2; g++) {                                                  \
        int s = tid + g * 256, r = s >> 2, c8 = (s & 3) * 8;                       \
        CP_ASYNC16(sb + GSM_WB(0) + (r * 40 + c8) * 2,                             \
                   (WHI) + (size_t)(n0 + r) * 256 + c8);                           \
    }                                                                              \
    CP_COMMIT();                                                                   \
    _Pragma("unroll")                                                              \
    for (int it = 0; it < 4; it++)                                                 \
        pa[it] = *(const float4*)((APTR) + (size_t)(m0 + ar) * 256 + acb + it * 4);\
    const uint32_t wfoff = ((wn + (((lane >> 4) & 1) << 3) + (lane & 7)) * 40      \
                           + (((lane >> 3) & 1) << 3)) * 2;                        \
    for (int chunk = 0; chunk < 8; chunk++) {                                      \
        const int kk = chunk * 32;                                                 \
        const uint32_t wb = sb + GSM_WB(chunk & 1);                                \
        __syncthreads();                                                           \
        {                                                                          \
            uint32_t p[8];                                                         \
            _Pragma("unroll")                                                      \
            for (int q = 0; q < 4; q++) {                                          \
                p[2 * q]     = pack_h(pa[q].x, pa[q].y);                           \
                p[2 * q + 1] = pack_h(pa[q].z, pa[q].w);                           \
            }                                                                      \
            *(uint4*)(smem + GSM_AH + (ar * 40 + acb) * 2) =                       \
                make_uint4(p[0], p[1], p[2], p[3]);                                \
            *(uint4*)(smem + GSM_AH + (ar * 40 + acb) * 2 + 16) =                  \
                make_uint4(p[4], p[5], p[6], p[7]);                                \
        }                                                                          \
        if (chunk < 7) {                                                           \
            const uint32_t wn2 = sb + GSM_WB((chunk + 1) & 1);                     \
            _Pragma("unroll")                                                      \
            for (int g = 0; g < 2; g++) {                                          \
                int s = tid + g * 256, r = s >> 2, c8 = (s & 3) * 8;               \
                CP_ASYNC16(wn2 + (r * 40 + c8) * 2,                                \
                           (WHI) + (size_t)(n0 + r) * 256 + kk + 32 + c8);         \
            }                                                                      \
            CP_COMMIT();                                                           \
            _Pragma("unroll")                                                      \
            for (int it = 0; it < 4; it++)                                         \
                pa[it] = *(const float4*)((APTR) + (size_t)(m0 + ar) * 256         \
                                          + kk + 32 + acb + it * 4);               \
            CP_WAIT1();                                                            \
        } else {                                                                   \
            CP_WAIT0();                                                            \
        }                                                                          \
        __syncthreads();                                                           \
        _Pragma("unroll")                                                          \
        for (int ks = 0; ks < 32; ks += 16) {                                      \
            uint32_t ah[4][4];                                                     \
            const int arow = lane & 15;                                            \
            const int acol = ks + ((lane >> 4) << 3);                              \
            _Pragma("unroll")                                                      \
            for (int i = 0; i < 4; i++)                                            \
                LDSM_X4(ah[i], sb + GSM_AH + ((wm + i * 16 + arow) * 40 + acol) * 2); \
            _Pragma("unroll")                                                      \
            for (int jp = 0; jp < 2; jp++) {                                       \
                uint32_t w4[4];                                                    \
                LDSM_X4(w4, wb + wfoff + (jp * 16 * 40 + ks) * 2);                 \
                _Pragma("unroll")                                                  \
                for (int i = 0; i < 4; i++) {                                      \
                    MMA16816(acc[i][2 * jp],     ah[i], (&w4[0]));                 \
                    MMA16816(acc[i][2 * jp + 1], ah[i], (&w4[2]));                 \
                }                                                                  \
            }                                                                      \
        }                                                                          \
    }

// --- fused QKV projection: outputs fp16 (Q pre-scaled by log2e/sqrt(32)) ---
__global__ __launch_bounds__(256, 2)
void gemm_qkv_kernel(const float* __restrict__ query, const float* __restrict__ key,
                     const float* __restrict__ value,
                     const __half* __restrict__ Wh_all,
                     const float* __restrict__ bq, const float* __restrict__ bk,
                     const float* __restrict__ bv,
                     __half* __restrict__ Qh, __half* __restrict__ Kh,
                     __half* __restrict__ Vh)
{
    extern __shared__ char smem[];
    const uint32_t sb = smem_u32(smem);
    const int tid  = threadIdx.x;
    const int wid  = tid >> 5;
    const int lane = tid & 31;
    const int m0 = blockIdx.y * 128;
    const int n0 = blockIdx.x * 128;
    const int wm = (wid >> 2) * 64;
    const int wn = (wid & 3) * 32;
    const int z = blockIdx.z;

    const float* A   = (z == 0) ? query : (z == 1) ? key : value;
    const float* bia = (z == 0) ? bq    : (z == 1) ? bk  : bv;
    const __half* Whi = Wh_all + (size_t)z * 65536;
    __half* Oh = (z == 0) ? Qh : (z == 1) ? Kh : Vh;
    // Q scale = log2(e)/sqrt(32): softmax done in base-2 units
    const float oscale = (z == 0) ? 0.2550348652153015f : 1.0f;

    float acc[4][4][4] = {};
    GEMM_MAINLOOP(A, Whi)

    const int r0 = lane >> 2;
    const int cp = (lane & 3) * 2;
    #pragma unroll
    for (int i = 0; i < 4; i++)
        #pragma unroll
        for (int j = 0; j < 4; j++) {
            int col = n0 + wn + j * 8 + cp;
            float2 bb = *(const float2*)(bia + col);
            int row = m0 + wm + i * 16 + r0;
            *(uint32_t*)(Oh + (size_t)row * 256 + col) =
                pack_h((acc[i][j][0] + bb.x) * oscale, (acc[i][j][1] + bb.y) * oscale);
            *(uint32_t*)(Oh + (size_t)(row + 8) * 256 + col) =
                pack_h((acc[i][j][2] + bb.x) * oscale, (acc[i][j][3] + bb.y) * oscale);
        }
}

// --- output projection: A is fp16 (attention output), pure cp.async staging ---
#define OSM_AB(b) ((b) * 20480)
#define OSM_WB(b) ((b) * 20480 + 10240)
#define OSM_TOTAL 40960

__global__ __launch_bounds__(256, 2)
void gemm_out_kernel(const __half* __restrict__ A,
                     const __half* __restrict__ Whi,
                     const float* __restrict__ bias,
                     float* __restrict__ C)
{
    extern __shared__ char smem[];
    const uint32_t sb = smem_u32(smem);
    const int tid  = threadIdx.x;
    const int wid  = tid >> 5;
    const int lane = tid & 31;
    const int m0 = blockIdx.y * 128;
    const int n0 = blockIdx.x * 128;
    const int wm = (wid >> 2) * 64;
    const int wn = (wid & 3) * 32;

    float acc[4][4][4] = {};

    #pragma unroll
    for (int g = 0; g < 2; g++) {
        int s = tid + g * 256, r = s >> 2, c8 = (s & 3) * 8;
        CP_ASYNC16(sb + OSM_AB(0) + (r * 40 + c8) * 2, A   + (size_t)(m0 + r) * 256 + c8);
        CP_ASYNC16(sb + OSM_WB(0) + (r * 40 + c8) * 2, Whi + (size_t)(n0 + r) * 256 + c8);
    }
    CP_COMMIT();

    const uint32_t wfoff = ((wn + (((lane >> 4) & 1) << 3) + (lane & 7)) * 40
                           + (((lane >> 3) & 1) << 3)) * 2;

    for (int chunk = 0; chunk < 8; chunk++) {
        const int kk = chunk * 32;
        __syncthreads();
        if (chunk < 7) {
            const uint32_t ab = sb + OSM_AB((chunk + 1) & 1);
            const uint32_t wb2 = sb + OSM_WB((chunk + 1) & 1);
            #pragma unroll
            for (int g = 0; g < 2; g++) {
                int s = tid + g * 256, r = s >> 2, c8 = (s & 3) * 8;
                CP_ASYNC16(ab  + (r * 40 + c8) * 2, A   + (size_t)(m0 + r) * 256 + kk + 32 + c8);
                CP_ASYNC16(wb2 + (r * 40 + c8) * 2, Whi + (size_t)(n0 + r) * 256 + kk + 32 + c8);
            }
            CP_COMMIT();
            CP_WAIT1();
        } else {
            CP_WAIT0();
        }
        __syncthreads();

        const uint32_t ab = sb + OSM_AB(chunk & 1);
        const uint32_t wb = sb + OSM_WB(chunk & 1);
        #pragma unroll
        for (int ks = 0; ks < 32; ks += 16) {
            uint32_t ah[4][4];
            const int arow = lane & 15;
            const int acol = ks + ((lane >> 4) << 3);
            #pragma unroll
            for (int i = 0; i < 4; i++)
                LDSM_X4(ah[i], ab + ((wm + i * 16 + arow) * 40 + acol) * 2);
            #pragma unroll
            for (int jp = 0; jp < 2; jp++) {
                uint32_t w4[4];
                LDSM_X4(w4, wb + wfoff + (jp * 16 * 40 + ks) * 2);
                #pragma unroll
                for (int i = 0; i < 4; i++) {
                    MMA16816(acc[i][2 * jp],     ah[i], (&w4[0]));
                    MMA16816(acc[i][2 * jp + 1], ah[i], (&w4[2]));
                }
            }
        }
    }

    const int r0 = lane >> 2;
    const int cp = (lane & 3) * 2;
    #pragma unroll
    for (int i = 0; i < 4; i++)
        #pragma unroll
        for (int j = 0; j < 4; j++) {
            int col = n0 + wn + j * 8 + cp;
            float2 bb = *(const float2*)(bias + col);
            int row = m0 + wm + i * 16 + r0;
            float2 o0 = make_float2(acc[i][j][0] + bb.x, acc[i][j][1] + bb.y);
            *(float2*)(C + (size_t)row * 256 + col) = o0;
            float2 o1 = make_float2(acc[i][j][2] + bb.x, acc[i][j][3] + bb.y);
            *(float2*)(C + (size_t)(row + 8) * 256 + col) = o1;
        }
}

// ====================== mma.sync flash attention (fp16) ====================
// Logits in log2 units (scale folded into Q). P computed by ex2.approx.f16x2:
// one MUFU op yields two packed-fp16 P values, MMA-ready (fuses exp + pack).
// Row sums via hadd2 trees on the same packed P (normalization cancels the
// common-mode fp16 error).
#define ASM_QH 0
#define ASM_KV(b) (10240 + (b) * 10240)
#define ASM_TOTAL 30720

__global__ __launch_bounds__(256, 2)
void attn_mma_kernel(const __half* __restrict__ Qh_g,
                     const __half* __restrict__ Kh_g,
                     const __half* __restrict__ Vh_g,
                     __half* __restrict__ Og)
{
    extern __shared__ char smem[];
    const uint32_t sb = smem_u32(smem);
    const int tid  = threadIdx.x;
    const int wid  = tid >> 5;
    const int lane = tid & 31;
    const int tq = (int)gridDim.x - 1 - (int)blockIdx.x;   // long blocks first
    const int hb = blockIdx.y;
    const int h  = hb & 7;
    const int bb = hb >> 3;
    const size_t base = (size_t)bb * 2048 * 256 + (size_t)h * 32;
    const int qbase = tq * 128;
    __half* Ob = Og + base;

    const int ntiles = 2 * tq + 2;

    #pragma unroll
    for (int g = 0; g < 2; g++) {
        int s = tid + g * 256, r = s >> 2, c8 = (s & 3) * 8;
        CP_ASYNC16(sb + ASM_QH + (r * 40 + c8) * 2,
                   Qh_g + base + (size_t)(qbase + r) * 256 + c8);
    }
    {
        int r = tid >> 2, c8 = (tid & 3) * 8;
        size_t src = base + (size_t)r * 256 + c8;
        CP_ASYNC16(sb + ASM_KV(0) +    0 + (r * 40 + c8) * 2, Kh_g + src);
        CP_ASYNC16(sb + ASM_KV(0) + 5120 + (r * 40 + c8) * 2, Vh_g + src);
    }
    CP_COMMIT();

    uint32_t qh[2][4];
    float o[4][4] = {};
    float mrow[2] = {-1e30f, -1e30f};   // log2 units
    float lrow[2] = {0.0f, 0.0f};

    const uint32_t kfoff = (((((lane >> 4) & 1) << 3) + (lane & 7)) * 40
                           + (((lane >> 3) & 1) << 3)) * 2;
    const uint32_t vfoff = 5120u + ((lane & 15) * 40 + (((lane >> 4) & 1) << 3)) * 2;

    for (int jt = 0; jt < ntiles; jt++) {
        __syncthreads();
        if (jt + 1 < ntiles) {
            const uint32_t kv = sb + ASM_KV((jt + 1) & 1);
            int r = tid >> 2, c8 = (tid & 3) * 8;
            size_t src = base + (size_t)((jt + 1) * 64 + r) * 256 + c8;
            CP_ASYNC16(kv +    0 + (r * 40 + c8) * 2, Kh_g + src);
            CP_ASYNC16(kv + 5120 + (r * 40 + c8) * 2, Vh_g + src);
            CP_COMMIT();
            CP_WAIT1();
        } else {
            CP_WAIT0();
        }
        __syncthreads();

        if (jt == 0) {
            const int arow = lane & 15;
            const int aco  = ((lane >> 4) << 3);
            #pragma unroll
            for (int ks = 0; ks < 2; ks++)
                LDSM_X4(qh[ks], sb + ASM_QH + ((wid * 16 + arow) * 40 + ks * 16 + aco) * 2);
        }

        if (jt * 64 > qbase + wid * 16 + 15) continue;

        const uint32_t kv = sb + ASM_KV(jt & 1);

        // ---- S = Q @ K^T (single fp16 pass; logits in log2 units) ----
        float s[8][4] = {};
        #pragma unroll
        for (int ks = 0; ks < 2; ks++) {
            #pragma unroll
            for (int jp = 0; jp < 4; jp++) {
                uint32_t k4[4];
                LDSM_X4(k4, kv + kfoff + (jp * 16 * 40 + ks * 16) * 2);
                MMA16816(s[2 * jp],     qh[ks], (&k4[0]));
                MMA16816(s[2 * jp + 1], qh[ks], (&k4[2]));
            }
        }

        // ---- causal mask (diagonal region only) ----
        if (jt >= 2 * tq) {
            const int row0 = qbase + wid * 16 + (lane >> 2);
            #pragma unroll
            for (int j = 0; j < 8; j++) {
                int col = jt * 64 + j * 8 + (lane & 3) * 2;
                if (col     > row0)     s[j][0] = -1e30f;
                if (col + 1 > row0)     s[j][1] = -1e30f;
                if (col     > row0 + 8) s[j][2] = -1e30f;
                if (col + 1 > row0 + 8) s[j][3] = -1e30f;
            }
        }

        // ---- online softmax (base-2; P via ex2.approx.f16x2, MMA-ready) ----
        uint32_t p2[2][8];   // [row-half hf][col-pair j] packed fp16 P
        #pragma unroll
        for (int hf = 0; hf < 2; hf++) {
            const int a0 = 2 * hf, a1 = 2 * hf + 1;
            float mj[8];
            #pragma unroll
            for (int j = 0; j < 8; j++) mj[j] = fmaxf(s[j][a0], s[j][a1]);
            mj[0] = fmaxf(mj[0], mj[1]); mj[2] = fmaxf(mj[2], mj[3]);
            mj[4] = fmaxf(mj[4], mj[5]); mj[6] = fmaxf(mj[6], mj[7]);
            mj[0] = fmaxf(mj[0], mj[2]); mj[4] = fmaxf(mj[4], mj[6]);
            float mt = fmaxf(mj[0], mj[4]);
            mt = fmaxf(mt, __shfl_xor_sync(0xffffffffu, mt, 1));
            mt = fmaxf(mt, __shfl_xor_sync(0xffffffffu, mt, 2));
            float mnew  = fmaxf(mrow[hf], mt);
            float alpha = ex2f(mrow[hf] - mnew);
            #pragma unroll
            for (int j = 0; j < 8; j++)
                p2[hf][j] = ex2_h2(s[j][a0] - mnew, s[j][a1] - mnew);
            // row sum via hadd2 tree on packed P
            __half2 t0 = __hadd2(u2h2(p2[hf][0]), u2h2(p2[hf][1]));
            __half2 t1 = __hadd2(u2h2(p2[hf][2]), u2h2(p2[hf][3]));
            __half2 t2 = __hadd2(u2h2(p2[hf][4]), u2h2(p2[hf][5]));
            __half2 t3 = __hadd2(u2h2(p2[hf][6]), u2h2(p2[hf][7]));
            t0 = __hadd2(t0, t1); t2 = __hadd2(t2, t3);
            t0 = __hadd2(t0, t2);
            float ls = __low2float(t0) + __high2float(t0);
            ls += __shfl_xor_sync(0xffffffffu, ls, 1);
            ls += __shfl_xor_sync(0xffffffffu, ls, 2);
            mrow[hf] = mnew;
            lrow[hf] = lrow[hf] * alpha + ls;
            #pragma unroll
            for (int j = 0; j < 4; j++) {
                o[j][a0] *= alpha;
                o[j][a1] *= alpha;
            }
        }

        // ---- O += P @ V (single pass; P already packed by ex2.f16x2) ----
        #pragma unroll
        for (int t = 0; t < 4; t++) {
            uint32_t ph[4];
            ph[0] = p2[0][2 * t];        // row g,   cols 2t
            ph[1] = p2[1][2 * t];        // row g+8, cols 2t
            ph[2] = p2[0][2 * t + 1];    // row g,   cols 2t+1
            ph[3] = p2[1][2 * t + 1];    // row g+8, cols 2t+1

            #pragma unroll
            for (int jp = 0; jp < 2; jp++) {
                uint32_t v4[4];
                LDSM_X4_T(v4, kv + vfoff + (t * 16 * 40 + jp * 16) * 2);
                MMA16816(o[2 * jp],     ph, (&v4[0]));
                MMA16816(o[2 * jp + 1], ph, (&v4[2]));
            }
        }
    }

    // ---- normalize + store (fp16) ----
    const float inv0 = 1.0f / lrow[0];
    const float inv1 = 1.0f / lrow[1];
    const int row = qbase + wid * 16 + (lane >> 2);
    #pragma unroll
    for (int j = 0; j < 4; j++) {
        int col = j * 8 + (lane & 3) * 2;
        *(uint32_t*)(Ob + (size_t)row * 256 + col) =
            pack_h(o[j][0] * inv0, o[j][1] * inv0);
        *(uint32_t*)(Ob + (size_t)(row + 8) * 256 + col) =
            pack_h(o[j][2] * inv1, o[j][3] * inv1);
    }
}

// ---------------------------------------------------------------------------
extern "C" void kernel_launch(void* const* d_in, const int* in_sizes, int n_in,
                              void* d_out, int out_size)
{
    const float* query = (const float*)d_in[0];
    const float* key   = (const float*)d_in[1];
    const float* value = (const float*)d_in[2];
    const float* Wq    = (const float*)d_in[3];
    const float* bq    = (const float*)d_in[4];
    const float* Wk    = (const float*)d_in[5];
    const float* bk    = (const float*)d_in[6];
    const float* Wv    = (const float*)d_in[7];
    const float* bv    = (const float*)d_in[8];
    const float* Wo    = (const float*)d_in[9];
    const float* bo    = (const float*)d_in[10];
    float* out = (float*)d_out;

    __half *AOh, *Qh, *Kh, *Vh, *Wh;
    cudaGetSymbolAddress((void**)&AOh, g_AOh);
    cudaGetSymbolAddress((void**)&Qh,  g_Qh);
    cudaGetSymbolAddress((void**)&Kh,  g_Kh);
    cudaGetSymbolAddress((void**)&Vh,  g_Vh);
    cudaGetSymbolAddress((void**)&Wh,  g_Wh);

    cudaFuncSetAttribute(gemm_qkv_kernel,
                         cudaFuncAttributeMaxDynamicSharedMemorySize, GSM_TOTAL);
    cudaFuncSetAttribute(gemm_out_kernel,
                         cudaFuncAttributeMaxDynamicSharedMemorySize, OSM_TOTAL);
    cudaFuncSetAttribute(attn_mma_kernel,
                         cudaFuncAttributeMaxDynamicSharedMemorySize, ASM_TOTAL);

    convert_w_kernel<<<dim3(256, 4), 256>>>(Wq, Wk, Wv, Wo, Wh);

    gemm_qkv_kernel<<<dim3(2, 128, 3), 256, GSM_TOTAL>>>(
        query, key, value, Wh, bq, bk, bv, Qh, Kh, Vh);

    attn_mma_kernel<<<dim3(16, 64), 256, ASM_TOTAL>>>(Qh, Kh, Vh, AOh);

    gemm_out_kernel<<<dim3(2, 128), 256, OSM_TOTAL>>>(
        AOh, Wh + 3 * 65536, bo, out);
}